// round 5
// baseline (speedup 1.0000x reference)
#include <cuda_runtime.h>
#include <cstdint>
#include <math.h>

#define BATCH 8
#define CH    512
#define CH3   1536
#define HH    64
#define NPIX  4096          // 64*64
#define WR    33            // rfft width 64/2+1
#define FREQ  2112          // 64*33
#define PLANES (BATCH*CH)   // 4096

// ---- static scratch (no allocations allowed) ----
__device__ float2 g_Xc[BATCH*CH*FREQ];    // interleaved {re,im}
__device__ float2 g_Qc[BATCH*CH3*FREQ];   // interleaved {re,im}
__device__ float  g_y[BATCH*CH*NPIX];
__device__ float  g_t[BATCH*CH*NPIX];

#define TWO_PI_OVER_64 0.09817477042468103f

// ---- packed f32x2 helpers ----
typedef unsigned long long ull;

__device__ __forceinline__ ull pk2(float lo, float hi) {
    ull r;
    asm("mov.b64 %0, {%1, %2};" : "=l"(r) : "f"(lo), "f"(hi));
    return r;
}
__device__ __forceinline__ ull dup2(float v) { return pk2(v, v); }
__device__ __forceinline__ float2 upk2(ull v) {
    float2 f;
    asm("mov.b64 {%0, %1}, %2;" : "=f"(f.x), "=f"(f.y) : "l"(v));
    return f;
}
__device__ __forceinline__ void fma2(ull& d, ull a, ull b) {
    asm("fma.rn.f32x2 %0, %1, %2, %0;" : "+l"(d) : "l"(a), "l"(b));
}
__device__ __forceinline__ ull lds_u64(const float2* p) {
    return *reinterpret_cast<const ull*>(p);
}
__device__ __forceinline__ void cp_async16(unsigned int saddr, const void* g, int sz) {
    asm volatile("cp.async.cg.shared.global [%0], [%1], 16, %2;\n"
                 :: "r"(saddr), "l"(g), "r"(sz));
}
__device__ __forceinline__ void cp_commit() { asm volatile("cp.async.commit_group;\n"); }
__device__ __forceinline__ void cp_wait0()  { asm volatile("cp.async.wait_group 0;\n" ::: "memory"); }

// ============================================================
// Forward rfft2 of one 64x64 real plane -> interleaved complex.
// ============================================================
__global__ __launch_bounds__(256) void fft2_fwd_kernel(
    const float* __restrict__ in,
    float2* __restrict__ outc,
    float scale)
{
    __shared__ float  sp[HH][65];
    __shared__ float2 t2[HH][WR];
    __shared__ float2 TAf[64];        // {cos, -sin}
    __shared__ float2 TB2f[64];       // {sin,  cos}
    const int tid = threadIdx.x;
    const float* p = in + (size_t)blockIdx.x * NPIX;

    if (tid < 64) {
        float s, c; sincosf(TWO_PI_OVER_64 * (float)tid, &s, &c);
        TAf[tid]  = make_float2(c, -s);
        TB2f[tid] = make_float2(s,  c);
    }
    for (int i = tid; i < NPIX; i += 256) sp[i >> 6][i & 63] = p[i];
    __syncthreads();

    // Stage A: transform along w. 2 h x 4 kw per thread (kw 0..31).
    {
        const int hg  = tid & 31;
        const int kwg = tid >> 5;
        ull acc0[4] = {0,0,0,0};
        ull acc1[4] = {0,0,0,0};
        int idx[4], stp[4];
        #pragma unroll
        for (int j = 0; j < 4; j++) { idx[j] = 0; stp[j] = 4*kwg + j; }
        #pragma unroll 4
        for (int w = 0; w < 64; w++) {
            ull v0 = dup2(sp[hg][w]);
            ull v1 = dup2(sp[hg + 32][w]);
            #pragma unroll
            for (int j = 0; j < 4; j++) {
                ull T = lds_u64(&TAf[idx[j]]);
                fma2(acc0[j], v0, T);
                fma2(acc1[j], v1, T);
                idx[j] = (idx[j] + stp[j]) & 63;
            }
        }
        #pragma unroll
        for (int j = 0; j < 4; j++) {
            t2[hg][4*kwg + j]      = upk2(acc0[j]);
            t2[hg + 32][4*kwg + j] = upk2(acc1[j]);
        }
        if (tid < 64) {
            float s = 0.f;
            #pragma unroll 8
            for (int w = 0; w < 64; w += 2) s += sp[tid][w] - sp[tid][w + 1];
            t2[tid][32] = make_float2(s, 0.f);
        }
    }
    __syncthreads();

    // Stage B: transform along h. 2 kh x 4 kw per thread.
    {
        const int kwg = tid & 7;
        const int khg = tid >> 3;
        ull acc0[4] = {0,0,0,0};
        ull acc1[4] = {0,0,0,0};
        int idx = 0;
        #pragma unroll 4
        for (int h = 0; h < 64; h++) {
            int idx2 = idx ^ ((h & 1) << 5);
            ull Ta1 = lds_u64(&TAf[idx]);
            ull Ta2 = lds_u64(&TB2f[idx]);
            ull Tb1 = lds_u64(&TAf[idx2]);
            ull Tb2 = lds_u64(&TB2f[idx2]);
            #pragma unroll
            for (int j = 0; j < 4; j++) {
                float2 u = t2[h][4*kwg + j];
                ull ud = dup2(u.x), vd = dup2(u.y);
                fma2(acc0[j], ud, Ta1); fma2(acc0[j], vd, Ta2);
                fma2(acc1[j], ud, Tb1); fma2(acc1[j], vd, Tb2);
            }
            idx = (idx + khg) & 63;
        }
        float2* ob = outc + (size_t)blockIdx.x * FREQ;
        #pragma unroll
        for (int j = 0; j < 4; j++) {
            float2 r0 = upk2(acc0[j]);
            float2 r1 = upk2(acc1[j]);
            int n = 4*kwg + j;
            ob[khg*WR + n]      = make_float2(r0.x * scale, r0.y * scale);
            ob[(khg+32)*WR + n] = make_float2(r1.x * scale, r1.y * scale);
        }
        if (tid < 64) {
            const int kh = tid;
            float yr = 0.f, yi = 0.f;
            int ix = 0;
            #pragma unroll 8
            for (int h = 0; h < 64; h++) {
                float2 T = TAf[ix];
                float tr = t2[h][32].x;
                yr = fmaf(tr, T.x, yr);
                yi = fmaf(tr, T.y, yi);
                ix = (ix + kh) & 63;
            }
            ob[kh*WR + 32] = make_float2(yr * scale, yi * scale);
        }
    }
}

// ============================================================
// Fused middle: conj(q)*k -> irfft2(ortho) -> softmax ->
// rfft2(backward norm) -> outc. Plane never leaves smem.
// ============================================================
__global__ __launch_bounds__(256) void mid_fused_kernel(
    const float2* __restrict__ qc,
    float2* __restrict__ outc)
{
    __shared__ float2 y2[FREQ];       // also reused as plane [64][65] floats
    __shared__ float2 u2[FREQ];
    __shared__ float2 Tcs[64];        // {cos,  sin}
    __shared__ float2 Tns[64];        // {-sin, cos}
    __shared__ float2 Tcn[64];        // {cos, -sin}
    __shared__ float2 Tsc[64];        // {sin,  cos}
    __shared__ float  red[256];
    float* pl = (float*)y2;

    const int tid = threadIdx.x;
    const int plane = blockIdx.x;
    const int b  = plane >> 9;
    const int ch = plane & 511;
    const float2* qp = qc + ((size_t)b * CH3 + ch) * FREQ;
    const float2* kp = qc + ((size_t)b * CH3 + 512 + ch) * FREQ;

    if (tid < 64) {
        float s, c; sincosf(TWO_PI_OVER_64 * (float)tid, &s, &c);
        Tcs[tid] = make_float2(c,  s);
        Tns[tid] = make_float2(-s, c);
        Tcn[tid] = make_float2(c, -s);
        Tsc[tid] = make_float2(s,  c);
    }
    // Phase 1: Y = conj(q)*k
    for (int i = tid; i < FREQ; i += 256) {
        float2 q = qp[i], k = kp[i];
        y2[i] = make_float2(q.x*k.x + q.y*k.y, q.x*k.y - q.y*k.x);
    }
    __syncthreads();

    // Phase 2: inverse along kh: y2 -> u2
    {
        const int kwg = tid & 7;
        const int hg  = tid >> 3;
        ull acc0[4] = {0,0,0,0};
        ull acc1[4] = {0,0,0,0};
        int idx = 0;
        #pragma unroll 4
        for (int kh = 0; kh < 64; kh++) {
            int idx2 = idx ^ ((kh & 1) << 5);
            ull Ta1 = lds_u64(&Tcs[idx]);
            ull Ta2 = lds_u64(&Tns[idx]);
            ull Tb1 = lds_u64(&Tcs[idx2]);
            ull Tb2 = lds_u64(&Tns[idx2]);
            #pragma unroll
            for (int j = 0; j < 4; j++) {
                float2 y = y2[kh*WR + 4*kwg + j];
                ull yr = dup2(y.x), yi = dup2(y.y);
                fma2(acc0[j], yr, Ta1); fma2(acc0[j], yi, Ta2);
                fma2(acc1[j], yr, Tb1); fma2(acc1[j], yi, Tb2);
            }
            idx = (idx + hg) & 63;
        }
        float2 tmp0[4], tmp1[4];
        #pragma unroll
        for (int j = 0; j < 4; j++) { tmp0[j] = upk2(acc0[j]); tmp1[j] = upk2(acc1[j]); }
        float2 ny = make_float2(0.f, 0.f);
        if (tid < 64) {
            const int h = tid;
            int ix = 0;
            #pragma unroll 8
            for (int kh = 0; kh < 64; kh++) {
                float2 T = Tcs[ix];
                float2 y = y2[kh*WR + 32];
                ny.x = fmaf(y.x, T.x, fmaf(-y.y, T.y, ny.x));
                ny.y = fmaf(y.x, T.y, fmaf( y.y, T.x, ny.y));
                ix = (ix + h) & 63;
            }
        }
        #pragma unroll
        for (int j = 0; j < 4; j++) {
            u2[hg*WR + 4*kwg + j]        = tmp0[j];
            u2[(hg + 32)*WR + 4*kwg + j] = tmp1[j];
        }
        if (tid < 64) u2[tid*WR + 32] = ny;
    }
    __syncthreads();

    // Phase 3: inverse along kw (Hermitian) -> real plane pl (stride 65), *1/64
    {
        const int wg = tid & 7;
        const int hg = tid >> 3;
        const float scale = 1.0f / 64.0f;
        float accP[2][4] = {{0,0,0,0},{0,0,0,0}};
        float accM[2][4] = {{0,0,0,0},{0,0,0,0}};
        int idx[4], stp[4];
        #pragma unroll
        for (int j = 0; j < 4; j++) { stp[j] = 4*wg + j; idx[j] = stp[j]; }
        float res[2][8];
        #pragma unroll 2
        for (int kw = 1; kw < 32; kw++) {
            float sgn = (kw & 1) ? -1.f : 1.f;
            float2 ua = u2[hg*WR + kw];
            float2 ub = u2[(hg + 32)*WR + kw];
            #pragma unroll
            for (int j = 0; j < 4; j++) {
                float2 T = Tcs[idx[j]];
                float ta = fmaf(ua.x, T.x, -ua.y * T.y);
                float tb = fmaf(ub.x, T.x, -ub.y * T.y);
                accP[0][j] += ta;  accM[0][j] = fmaf(sgn, ta, accM[0][j]);
                accP[1][j] += tb;  accM[1][j] = fmaf(sgn, tb, accM[1][j]);
                idx[j] = (idx[j] + stp[j]) & 63;
            }
        }
        float dcA = u2[hg*WR].x,        nyA = u2[hg*WR + 32].x;
        float dcB = u2[(hg + 32)*WR].x, nyB = u2[(hg + 32)*WR + 32].x;
        #pragma unroll
        for (int j = 0; j < 4; j++) {
            float ps = (j & 1) ? -1.f : 1.f;
            float baseA = fmaf(ps, nyA, dcA);
            float baseB = fmaf(ps, nyB, dcB);
            res[0][j]     = (2.f*accP[0][j] + baseA) * scale;
            res[0][j + 4] = (2.f*accM[0][j] + baseA) * scale;
            res[1][j]     = (2.f*accP[1][j] + baseB) * scale;
            res[1][j + 4] = (2.f*accM[1][j] + baseB) * scale;
        }
        __syncthreads();
        #pragma unroll
        for (int j = 0; j < 4; j++) {
            int w = 4*wg + j;
            pl[hg*65 + w]             = res[0][j];
            pl[hg*65 + w + 32]        = res[0][j + 4];
            pl[(hg + 32)*65 + w]      = res[1][j];
            pl[(hg + 32)*65 + w + 32] = res[1][j + 4];
        }
    }
    __syncthreads();

    // Phase 4: softmax over the 4096 plane values (stride-65 layout)
    {
        float m = -3.4e38f;
        for (int i = tid; i < NPIX; i += 256) {
            float v = pl[(i >> 6)*65 + (i & 63)];
            m = fmaxf(m, v);
        }
        red[tid] = m; __syncthreads();
        for (int s = 128; s > 0; s >>= 1) { if (tid < s) red[tid] = fmaxf(red[tid], red[tid + s]); __syncthreads(); }
        const float M = red[0];
        __syncthreads();
        float sum = 0.f;
        for (int i = tid; i < NPIX; i += 256) {
            int a = (i >> 6)*65 + (i & 63);
            float e = __expf(pl[a] - M);
            pl[a] = e; sum += e;
        }
        red[tid] = sum; __syncthreads();
        for (int s = 128; s > 0; s >>= 1) { if (tid < s) red[tid] += red[tid + s]; __syncthreads(); }
        const float inv = 1.f / red[0];
        __syncthreads();
        for (int i = tid; i < NPIX; i += 256) {
            int a = (i >> 6)*65 + (i & 63);
            pl[a] *= inv;
        }
    }
    __syncthreads();

    // Phase 5: forward rfft along w: pl -> u2
    {
        const int hg  = tid & 31;
        const int kwg = tid >> 5;
        ull acc0[4] = {0,0,0,0};
        ull acc1[4] = {0,0,0,0};
        int idx[4], stp[4];
        #pragma unroll
        for (int j = 0; j < 4; j++) { idx[j] = 0; stp[j] = 4*kwg + j; }
        #pragma unroll 4
        for (int w = 0; w < 64; w++) {
            ull v0 = dup2(pl[hg*65 + w]);
            ull v1 = dup2(pl[(hg + 32)*65 + w]);
            #pragma unroll
            for (int j = 0; j < 4; j++) {
                ull T = lds_u64(&Tcn[idx[j]]);
                fma2(acc0[j], v0, T);
                fma2(acc1[j], v1, T);
                idx[j] = (idx[j] + stp[j]) & 63;
            }
        }
        float ny = 0.f;
        if (tid < 64) {
            #pragma unroll 8
            for (int w = 0; w < 64; w += 2) ny += pl[tid*65 + w] - pl[tid*65 + w + 1];
        }
        __syncthreads();
        #pragma unroll
        for (int j = 0; j < 4; j++) {
            u2[hg*WR + 4*kwg + j]        = upk2(acc0[j]);
            u2[(hg + 32)*WR + 4*kwg + j] = upk2(acc1[j]);
        }
        if (tid < 64) u2[tid*WR + 32] = make_float2(ny, 0.f);
    }
    __syncthreads();

    // Phase 6: forward fft along h: u2 -> global (scale 1, backward norm)
    {
        const int kwg = tid & 7;
        const int khg = tid >> 3;
        ull acc0[4] = {0,0,0,0};
        ull acc1[4] = {0,0,0,0};
        int idx = 0;
        #pragma unroll 4
        for (int h = 0; h < 64; h++) {
            int idx2 = idx ^ ((h & 1) << 5);
            ull Ta1 = lds_u64(&Tcn[idx]);
            ull Ta2 = lds_u64(&Tsc[idx]);
            ull Tb1 = lds_u64(&Tcn[idx2]);
            ull Tb2 = lds_u64(&Tsc[idx2]);
            #pragma unroll
            for (int j = 0; j < 4; j++) {
                float2 u = u2[h*WR + 4*kwg + j];
                ull ud = dup2(u.x), vd = dup2(u.y);
                fma2(acc0[j], ud, Ta1); fma2(acc0[j], vd, Ta2);
                fma2(acc1[j], ud, Tb1); fma2(acc1[j], vd, Tb2);
            }
            idx = (idx + khg) & 63;
        }
        float2* ob = outc + (size_t)plane * FREQ;
        #pragma unroll
        for (int j = 0; j < 4; j++) {
            int n = 4*kwg + j;
            ob[khg*WR + n]      = upk2(acc0[j]);
            ob[(khg+32)*WR + n] = upk2(acc1[j]);
        }
        if (tid < 64) {
            const int kh = tid;
            float yr = 0.f, yi = 0.f;
            int ix = 0;
            #pragma unroll 8
            for (int h = 0; h < 64; h++) {
                float2 T = Tcn[ix];
                float tr = u2[h*WR + 32].x;
                yr = fmaf(tr, T.x, yr);
                yi = fmaf(tr, T.y, yi);
                ix = (ix + kh) & 63;
            }
            ob[kh*WR + 32] = make_float2(yr, yi);
        }
    }
}

// ============================================================
// Fused: Y = conj(a)*b, irfft2(Y), multiply by gate, write plane.
// ============================================================
__global__ __launch_bounds__(256) void prod_ifft2_gate_kernel(
    const float2* __restrict__ ac, int aCPB, int aOff,
    const float2* __restrict__ bc, int bCPB, int bOff,
    const float* __restrict__ gate,
    float* __restrict__ out, float scale)
{
    __shared__ float2 y2[FREQ];
    __shared__ float2 u2[FREQ];
    __shared__ float2 TI1f[64];       // {cos,  sin}
    __shared__ float2 TI2f[64];       // {-sin, cos}
    const int tid = threadIdx.x;
    const int plane = blockIdx.x;
    const int b  = plane >> 9;
    const int ch = plane & 511;
    const float2* ap = ac + ((size_t)b * aCPB + aOff + ch) * FREQ;
    const float2* bp = bc + ((size_t)b * bCPB + bOff + ch) * FREQ;

    if (tid < 64) {
        float s, c; sincosf(TWO_PI_OVER_64 * (float)tid, &s, &c);
        TI1f[tid] = make_float2(c,  s);
        TI2f[tid] = make_float2(-s, c);
    }
    for (int i = tid; i < FREQ; i += 256) {
        float2 a = ap[i], bb = bp[i];
        y2[i] = make_float2(a.x*bb.x + a.y*bb.y, a.x*bb.y - a.y*bb.x);
    }
    __syncthreads();

    // Stage A: inverse along kh
    {
        const int kwg = tid & 7;
        const int hg  = tid >> 3;
        ull acc0[4] = {0,0,0,0};
        ull acc1[4] = {0,0,0,0};
        int idx = 0;
        #pragma unroll 4
        for (int kh = 0; kh < 64; kh++) {
            int idx2 = idx ^ ((kh & 1) << 5);
            ull Ta1 = lds_u64(&TI1f[idx]);
            ull Ta2 = lds_u64(&TI2f[idx]);
            ull Tb1 = lds_u64(&TI1f[idx2]);
            ull Tb2 = lds_u64(&TI2f[idx2]);
            #pragma unroll
            for (int j = 0; j < 4; j++) {
                float2 y = y2[kh*WR + 4*kwg + j];
                ull yr = dup2(y.x), yi = dup2(y.y);
                fma2(acc0[j], yr, Ta1); fma2(acc0[j], yi, Ta2);
                fma2(acc1[j], yr, Tb1); fma2(acc1[j], yi, Tb2);
            }
            idx = (idx + hg) & 63;
        }
        #pragma unroll
        for (int j = 0; j < 4; j++) {
            u2[hg*WR + 4*kwg + j]        = upk2(acc0[j]);
            u2[(hg + 32)*WR + 4*kwg + j] = upk2(acc1[j]);
        }
        if (tid < 64) {
            const int h = tid;
            float ur = 0.f, ui = 0.f;
            int ix = 0;
            #pragma unroll 8
            for (int kh = 0; kh < 64; kh++) {
                float2 T = TI1f[ix];
                float2 y = y2[kh*WR + 32];
                ur = fmaf(y.x, T.x, fmaf(-y.y, T.y, ur));
                ui = fmaf(y.x, T.y, fmaf( y.y, T.x, ui));
                ix = (ix + h) & 63;
            }
            u2[h*WR + 32] = make_float2(ur, ui);
        }
    }
    __syncthreads();

    // Stage B: inverse along kw (Hermitian), gate-multiply, store
    {
        const int wg = tid & 7;
        const int hg = tid >> 3;
        float accP[2][4] = {{0,0,0,0},{0,0,0,0}};
        float accM[2][4] = {{0,0,0,0},{0,0,0,0}};
        int idx[4], stp[4];
        #pragma unroll
        for (int j = 0; j < 4; j++) { stp[j] = 4*wg + j; idx[j] = stp[j]; }
        #pragma unroll 2
        for (int kw = 1; kw < 32; kw++) {
            float sgn = (kw & 1) ? -1.f : 1.f;
            float2 ua = u2[hg*WR + kw];
            float2 ub = u2[(hg + 32)*WR + kw];
            #pragma unroll
            for (int j = 0; j < 4; j++) {
                float2 T = TI1f[idx[j]];
                float ta = fmaf(ua.x, T.x, -ua.y * T.y);
                float tb = fmaf(ub.x, T.x, -ub.y * T.y);
                accP[0][j] += ta;  accM[0][j] = fmaf(sgn, ta, accM[0][j]);
                accP[1][j] += tb;  accM[1][j] = fmaf(sgn, tb, accM[1][j]);
                idx[j] = (idx[j] + stp[j]) & 63;
            }
        }
        float* op = out + (size_t)plane * NPIX;
        const float* gp = gate + (size_t)plane * NPIX;
        float dcA = u2[hg*WR].x,        nyA = u2[hg*WR + 32].x;
        float dcB = u2[(hg + 32)*WR].x, nyB = u2[(hg + 32)*WR + 32].x;
        #pragma unroll
        for (int j = 0; j < 4; j++) {
            int w = 4*wg + j;
            float ps = (j & 1) ? -1.f : 1.f;
            float baseA = fmaf(ps, nyA, dcA);
            float baseB = fmaf(ps, nyB, dcB);
            op[hg*64 + w]             = (2.f*accP[0][j] + baseA) * scale * gp[hg*64 + w];
            op[hg*64 + w + 32]        = (2.f*accM[0][j] + baseA) * scale * gp[hg*64 + w + 32];
            op[(hg + 32)*64 + w]      = (2.f*accP[1][j] + baseB) * scale * gp[(hg + 32)*64 + w];
            op[(hg + 32)*64 + w + 32] = (2.f*accM[1][j] + baseB) * scale * gp[(hg + 32)*64 + w + 32];
        }
    }
}

// ============================================================
// Packed-f32x2 GEMM, double-buffered (cp.async B, reg-staged A),
// A pre-duplicated in smem (no movs in inner loop).
// C[m,n] = sum_k A[m,k]*B[k,n]; 128x128x16 tiles, 256 thr, 2 CTA/SM.
// MODE 0: plain. MODE 1: bias + SiLU. MODE 3: bias.
// ============================================================
template<int MODE>
__global__ __launch_bounds__(256, 2) void gemm_kernel(
    const float* __restrict__ A,
    const float* __restrict__ B,
    const float* __restrict__ bias,
    float* __restrict__ C,
    int M, int Ntot, int K)
{
    __shared__ __align__(16) float As[2][16][264];   // dup pairs: col 2m,2m+1 = A[m]
    __shared__ __align__(16) float Bs[2][16][128];
    const int bx = blockIdx.x, by = blockIdx.y, bz = blockIdx.z;
    const float* Bp = B + (size_t)bz * K * Ntot;
    float* Cp = C + (size_t)bz * M * Ntot;
    const int tid = threadIdx.x;
    const int n0 = bx * 128, m0 = by * 128;
    const int tx = tid & 15, ty = tid >> 4;

    const int arow = tid >> 2;            // 0..63
    const int acol = (tid & 3) * 4;       // 0,4,8,12

    const unsigned int sBs = (unsigned int)__cvta_generic_to_shared(&Bs[0][0][0]);

    auto loadB = [&](int k0, int bufI) {
        #pragma unroll
        for (int q = 0; q < 2; q++) {
            int c   = tid + q * 256;
            int row = c >> 5;
            int col = (c & 31) * 4;
            int n   = n0 + col;
            int sz  = (n + 4 <= Ntot) ? 16 : 0;
            const float* g = Bp + (size_t)(k0 + row) * Ntot + (sz ? n : 0);
            cp_async16(sBs + (unsigned int)(((bufI * 16 + row) * 128 + col) * 4), g, sz);
        }
        cp_commit();
    };

    float4 Ar0, Ar1;
    auto loadA = [&](int k0) {
        Ar0 = *(const float4*)&A[(size_t)(m0 + arow) * K + k0 + acol];
        Ar1 = *(const float4*)&A[(size_t)(m0 + arow + 64) * K + k0 + acol];
    };
    auto storeA = [&](int bufI) {
        int c0 = 2 * arow;
        *(float2*)&As[bufI][acol + 0][c0]       = make_float2(Ar0.x, Ar0.x);
        *(float2*)&As[bufI][acol + 1][c0]       = make_float2(Ar0.y, Ar0.y);
        *(float2*)&As[bufI][acol + 2][c0]       = make_float2(Ar0.z, Ar0.z);
        *(float2*)&As[bufI][acol + 3][c0]       = make_float2(Ar0.w, Ar0.w);
        *(float2*)&As[bufI][acol + 0][c0 + 128] = make_float2(Ar1.x, Ar1.x);
        *(float2*)&As[bufI][acol + 1][c0 + 128] = make_float2(Ar1.y, Ar1.y);
        *(float2*)&As[bufI][acol + 2][c0 + 128] = make_float2(Ar1.z, Ar1.z);
        *(float2*)&As[bufI][acol + 3][c0 + 128] = make_float2(Ar1.w, Ar1.w);
    };

    ull acc[8][4];
    #pragma unroll
    for (int i = 0; i < 8; i++)
        #pragma unroll
        for (int j = 0; j < 4; j++) acc[i][j] = 0ull;

    const int nStages = K >> 4;

    loadA(0);
    loadB(0, 0);
    storeA(0);
    cp_wait0();
    __syncthreads();

    for (int s = 0; s < nStages; s++) {
        const int buf = s & 1, nxt = buf ^ 1;
        const bool more = (s + 1 < nStages);
        if (more) {
            loadA((s + 1) << 4);
            loadB((s + 1) << 4, nxt);
        }
        #pragma unroll
        for (int kk = 0; kk < 16; kk++) {
            ulonglong2 a01 = *(const ulonglong2*)&As[buf][kk][8 * ty];
            ulonglong2 a23 = *(const ulonglong2*)&As[buf][kk][8 * ty + 4];
            ulonglong2 a45 = *(const ulonglong2*)&As[buf][kk][128 + 8 * ty];
            ulonglong2 a67 = *(const ulonglong2*)&As[buf][kk][128 + 8 * ty + 4];
            ulonglong2 b01 = *(const ulonglong2*)&Bs[buf][kk][4 * tx];
            ulonglong2 b23 = *(const ulonglong2*)&Bs[buf][kk][64 + 4 * tx];
            ull ad[8] = {a01.x, a01.y, a23.x, a23.y, a45.x, a45.y, a67.x, a67.y};
            ull bb[4] = {b01.x, b01.y, b23.x, b23.y};
            #pragma unroll
            for (int i = 0; i < 8; i++)
                #pragma unroll
                for (int j = 0; j < 4; j++)
                    fma2(acc[i][j], ad[i], bb[j]);
        }
        if (more) {
            storeA(nxt);
            cp_wait0();
        }
        __syncthreads();
    }

    #pragma unroll
    for (int i = 0; i < 8; i++) {
        int m = m0 + ((i < 4) ? (ty * 4 + i) : (64 + ty * 4 + i - 4));
        float bv = (MODE >= 1) ? bias[m] : 0.f;
        #pragma unroll
        for (int jp = 0; jp < 4; jp++) {
            float2 v2 = upk2(acc[i][jp]);
            int nbase = n0 + ((jp < 2) ? (tx * 4 + 2 * jp) : (64 + tx * 4 + 2 * (jp - 2)));
            float vx = v2.x + bv, vy = v2.y + bv;
            if (MODE == 1) {
                vx = vx / (1.f + __expf(-vx));
                vy = vy / (1.f + __expf(-vy));
            }
            if (nbase + 1 < Ntot) {
                *(float2*)&Cp[(size_t)m * Ntot + nbase] = make_float2(vx, vy);
            } else if (nbase < Ntot) {
                Cp[(size_t)m * Ntot + nbase] = vx;
            }
        }
    }
}

// ============================================================
extern "C" void kernel_launch(void* const* d_in, const int* in_sizes, int n_in,
                              void* d_out, int out_size)
{
    const float* x      = (const float*)d_in[0];
    const float* w_qkv  = (const float*)d_in[1];
    const float* w_gate = (const float*)d_in[2];
    const float* b_gate = (const float*)d_in[3];
    const float* w_proj = (const float*)d_in[4];
    const float* b_proj = (const float*)d_in[5];
    float* out = (float*)d_out;

    float2 *Xc, *Qc;
    float  *ybuf, *t;
    cudaGetSymbolAddress((void**)&Xc,   g_Xc);
    cudaGetSymbolAddress((void**)&Qc,   g_Qc);
    cudaGetSymbolAddress((void**)&ybuf, g_y);
    cudaGetSymbolAddress((void**)&t,    g_t);

    const float inv64 = 1.0f / 64.0f;

    // 1. gate: t = SiLU(Wg * x + bg)
    {
        dim3 g(NPIX / 128, CH / 128, BATCH);
        gemm_kernel<1><<<g, 256>>>(w_gate, x, b_gate, t, CH, NPIX, CH);
    }
    // 2. X = rfft2(x), ortho -> interleaved complex
    fft2_fwd_kernel<<<PLANES, 256>>>(x, Xc, inv64);
    // 3. QKV = Wqkv * X, complex via interleaved pairs (one GEMM, Ntot=4224 floats)
    {
        dim3 g((2 * FREQ) / 128, CH3 / 128, BATCH);
        gemm_kernel<0><<<g, 256>>>(w_qkv, (const float*)Xc, nullptr,
                                   (float*)Qc, CH3, 2 * FREQ, CH);
    }
    // 4-6. fused: conj(q)*k -> irfft2(ortho) -> softmax -> rfft2(bwd) -> Xc
    mid_fused_kernel<<<PLANES, 256>>>(Qc, Xc);
    // 7. y = irfft2(conj(A)*v) * t, ortho
    prod_ifft2_gate_kernel<<<PLANES, 256>>>(Xc, CH, 0,
                                            Qc, CH3, 1024,
                                            t, ybuf, inv64);
    // 8. out = Wp * y + bp
    {
        dim3 g(NPIX / 128, CH / 128, BATCH);
        gemm_kernel<3><<<g, 256>>>(w_proj, ybuf, b_proj, out, CH, NPIX, CH);
    }
}

// round 6
// speedup vs baseline: 1.1433x; 1.1433x over previous
#include <cuda_runtime.h>
#include <cstdint>
#include <math.h>

#define BATCH 8
#define CH    512
#define CH3   1536
#define HH    64
#define NPIX  4096          // 64*64
#define WR    33            // rfft width 64/2+1
#define FREQ  2112          // 64*33
#define PLANES (BATCH*CH)   // 4096

// ---- static scratch (no allocations allowed) ----
__device__ float2 g_Xc[BATCH*CH*FREQ];    // interleaved {re,im}
__device__ float2 g_Qc[BATCH*CH3*FREQ];   // interleaved {re,im}
__device__ float  g_y[BATCH*CH*NPIX];
__device__ float  g_t[BATCH*CH*NPIX];

#define TWO_PI_OVER_64 0.09817477042468103f

// ---- packed f32x2 helpers ----
typedef unsigned long long ull;

__device__ __forceinline__ ull pk2(float lo, float hi) {
    ull r;
    asm("mov.b64 %0, {%1, %2};" : "=l"(r) : "f"(lo), "f"(hi));
    return r;
}
__device__ __forceinline__ ull dup2(float v) { return pk2(v, v); }
__device__ __forceinline__ float2 upk2(ull v) {
    float2 f;
    asm("mov.b64 {%0, %1}, %2;" : "=f"(f.x), "=f"(f.y) : "l"(v));
    return f;
}
__device__ __forceinline__ void fma2(ull& d, ull a, ull b) {
    asm("fma.rn.f32x2 %0, %1, %2, %0;" : "+l"(d) : "l"(a), "l"(b));
}
__device__ __forceinline__ ull lds_u64(const float2* p) {
    return *reinterpret_cast<const ull*>(p);
}
__device__ __forceinline__ void cp_async16(unsigned int saddr, const void* g, int sz) {
    asm volatile("cp.async.cg.shared.global [%0], [%1], 16, %2;\n"
                 :: "r"(saddr), "l"(g), "r"(sz));
}
__device__ __forceinline__ void cp_commit() { asm volatile("cp.async.commit_group;\n"); }
__device__ __forceinline__ void cp_wait0()  { asm volatile("cp.async.wait_group 0;\n" ::: "memory"); }

// ============================================================
// Forward rfft2 of one 64x64 real plane -> interleaved complex.
// ============================================================
__global__ __launch_bounds__(256) void fft2_fwd_kernel(
    const float* __restrict__ in,
    float2* __restrict__ outc,
    float scale)
{
    __shared__ float  sp[HH][65];
    __shared__ float2 t2[HH][WR];
    __shared__ float2 TAf[64];        // {cos, -sin}
    __shared__ float2 TB2f[64];       // {sin,  cos}
    const int tid = threadIdx.x;
    const float* p = in + (size_t)blockIdx.x * NPIX;

    if (tid < 64) {
        float s, c; sincosf(TWO_PI_OVER_64 * (float)tid, &s, &c);
        TAf[tid]  = make_float2(c, -s);
        TB2f[tid] = make_float2(s,  c);
    }
    for (int i = tid; i < NPIX; i += 256) sp[i >> 6][i & 63] = p[i];
    __syncthreads();

    // Stage A: transform along w. 2 h x 4 kw per thread (kw 0..31).
    {
        const int hg  = tid & 31;
        const int kwg = tid >> 5;
        ull acc0[4] = {0,0,0,0};
        ull acc1[4] = {0,0,0,0};
        int idx[4], stp[4];
        #pragma unroll
        for (int j = 0; j < 4; j++) { idx[j] = 0; stp[j] = 4*kwg + j; }
        #pragma unroll 4
        for (int w = 0; w < 64; w++) {
            ull v0 = dup2(sp[hg][w]);
            ull v1 = dup2(sp[hg + 32][w]);
            #pragma unroll
            for (int j = 0; j < 4; j++) {
                ull T = lds_u64(&TAf[idx[j]]);
                fma2(acc0[j], v0, T);
                fma2(acc1[j], v1, T);
                idx[j] = (idx[j] + stp[j]) & 63;
            }
        }
        #pragma unroll
        for (int j = 0; j < 4; j++) {
            t2[hg][4*kwg + j]      = upk2(acc0[j]);
            t2[hg + 32][4*kwg + j] = upk2(acc1[j]);
        }
        if (tid < 64) {
            float s = 0.f;
            #pragma unroll 8
            for (int w = 0; w < 64; w += 2) s += sp[tid][w] - sp[tid][w + 1];
            t2[tid][32] = make_float2(s, 0.f);
        }
    }
    __syncthreads();

    // Stage B: transform along h. 2 kh x 4 kw per thread.
    {
        const int kwg = tid & 7;
        const int khg = tid >> 3;
        ull acc0[4] = {0,0,0,0};
        ull acc1[4] = {0,0,0,0};
        int idx = 0;
        #pragma unroll 4
        for (int h = 0; h < 64; h++) {
            int idx2 = idx ^ ((h & 1) << 5);
            ull Ta1 = lds_u64(&TAf[idx]);
            ull Ta2 = lds_u64(&TB2f[idx]);
            ull Tb1 = lds_u64(&TAf[idx2]);
            ull Tb2 = lds_u64(&TB2f[idx2]);
            #pragma unroll
            for (int j = 0; j < 4; j++) {
                float2 u = t2[h][4*kwg + j];
                ull ud = dup2(u.x), vd = dup2(u.y);
                fma2(acc0[j], ud, Ta1); fma2(acc0[j], vd, Ta2);
                fma2(acc1[j], ud, Tb1); fma2(acc1[j], vd, Tb2);
            }
            idx = (idx + khg) & 63;
        }
        float2* ob = outc + (size_t)blockIdx.x * FREQ;
        #pragma unroll
        for (int j = 0; j < 4; j++) {
            float2 r0 = upk2(acc0[j]);
            float2 r1 = upk2(acc1[j]);
            int n = 4*kwg + j;
            ob[khg*WR + n]      = make_float2(r0.x * scale, r0.y * scale);
            ob[(khg+32)*WR + n] = make_float2(r1.x * scale, r1.y * scale);
        }
        if (tid < 64) {
            const int kh = tid;
            float yr = 0.f, yi = 0.f;
            int ix = 0;
            #pragma unroll 8
            for (int h = 0; h < 64; h++) {
                float2 T = TAf[ix];
                float tr = t2[h][32].x;
                yr = fmaf(tr, T.x, yr);
                yi = fmaf(tr, T.y, yi);
                ix = (ix + kh) & 63;
            }
            ob[kh*WR + 32] = make_float2(yr * scale, yi * scale);
        }
    }
}

// ============================================================
// Fused middle: conj(q)*k -> irfft2(ortho) -> softmax ->
// rfft2(backward norm) -> outc. Plane never leaves smem.
// ============================================================
__global__ __launch_bounds__(256) void mid_fused_kernel(
    const float2* __restrict__ qc,
    float2* __restrict__ outc)
{
    __shared__ float2 y2[FREQ];       // also reused as plane [64][65] floats
    __shared__ float2 u2[FREQ];
    __shared__ float2 Tcs[64];        // {cos,  sin}
    __shared__ float2 Tns[64];        // {-sin, cos}
    __shared__ float2 Tcn[64];        // {cos, -sin}
    __shared__ float2 Tsc[64];        // {sin,  cos}
    __shared__ float  red[256];
    float* pl = (float*)y2;

    const int tid = threadIdx.x;
    const int plane = blockIdx.x;
    const int b  = plane >> 9;
    const int ch = plane & 511;
    const float2* qp = qc + ((size_t)b * CH3 + ch) * FREQ;
    const float2* kp = qc + ((size_t)b * CH3 + 512 + ch) * FREQ;

    if (tid < 64) {
        float s, c; sincosf(TWO_PI_OVER_64 * (float)tid, &s, &c);
        Tcs[tid] = make_float2(c,  s);
        Tns[tid] = make_float2(-s, c);
        Tcn[tid] = make_float2(c, -s);
        Tsc[tid] = make_float2(s,  c);
    }
    // Phase 1: Y = conj(q)*k
    for (int i = tid; i < FREQ; i += 256) {
        float2 q = qp[i], k = kp[i];
        y2[i] = make_float2(q.x*k.x + q.y*k.y, q.x*k.y - q.y*k.x);
    }
    __syncthreads();

    // Phase 2: inverse along kh: y2 -> u2
    {
        const int kwg = tid & 7;
        const int hg  = tid >> 3;
        ull acc0[4] = {0,0,0,0};
        ull acc1[4] = {0,0,0,0};
        int idx = 0;
        #pragma unroll 4
        for (int kh = 0; kh < 64; kh++) {
            int idx2 = idx ^ ((kh & 1) << 5);
            ull Ta1 = lds_u64(&Tcs[idx]);
            ull Ta2 = lds_u64(&Tns[idx]);
            ull Tb1 = lds_u64(&Tcs[idx2]);
            ull Tb2 = lds_u64(&Tns[idx2]);
            #pragma unroll
            for (int j = 0; j < 4; j++) {
                float2 y = y2[kh*WR + 4*kwg + j];
                ull yr = dup2(y.x), yi = dup2(y.y);
                fma2(acc0[j], yr, Ta1); fma2(acc0[j], yi, Ta2);
                fma2(acc1[j], yr, Tb1); fma2(acc1[j], yi, Tb2);
            }
            idx = (idx + hg) & 63;
        }
        float2 tmp0[4], tmp1[4];
        #pragma unroll
        for (int j = 0; j < 4; j++) { tmp0[j] = upk2(acc0[j]); tmp1[j] = upk2(acc1[j]); }
        float2 ny = make_float2(0.f, 0.f);
        if (tid < 64) {
            const int h = tid;
            int ix = 0;
            #pragma unroll 8
            for (int kh = 0; kh < 64; kh++) {
                float2 T = Tcs[ix];
                float2 y = y2[kh*WR + 32];
                ny.x = fmaf(y.x, T.x, fmaf(-y.y, T.y, ny.x));
                ny.y = fmaf(y.x, T.y, fmaf( y.y, T.x, ny.y));
                ix = (ix + h) & 63;
            }
        }
        #pragma unroll
        for (int j = 0; j < 4; j++) {
            u2[hg*WR + 4*kwg + j]        = tmp0[j];
            u2[(hg + 32)*WR + 4*kwg + j] = tmp1[j];
        }
        if (tid < 64) u2[tid*WR + 32] = ny;
    }
    __syncthreads();

    // Phase 3: inverse along kw (Hermitian) -> real plane pl (stride 65), *1/64
    {
        const int wg = tid & 7;
        const int hg = tid >> 3;
        const float scale = 1.0f / 64.0f;
        float accP[2][4] = {{0,0,0,0},{0,0,0,0}};
        float accM[2][4] = {{0,0,0,0},{0,0,0,0}};
        int idx[4], stp[4];
        #pragma unroll
        for (int j = 0; j < 4; j++) { stp[j] = 4*wg + j; idx[j] = stp[j]; }
        float res[2][8];
        #pragma unroll 2
        for (int kw = 1; kw < 32; kw++) {
            float sgn = (kw & 1) ? -1.f : 1.f;
            float2 ua = u2[hg*WR + kw];
            float2 ub = u2[(hg + 32)*WR + kw];
            #pragma unroll
            for (int j = 0; j < 4; j++) {
                float2 T = Tcs[idx[j]];
                float ta = fmaf(ua.x, T.x, -ua.y * T.y);
                float tb = fmaf(ub.x, T.x, -ub.y * T.y);
                accP[0][j] += ta;  accM[0][j] = fmaf(sgn, ta, accM[0][j]);
                accP[1][j] += tb;  accM[1][j] = fmaf(sgn, tb, accM[1][j]);
                idx[j] = (idx[j] + stp[j]) & 63;
            }
        }
        float dcA = u2[hg*WR].x,        nyA = u2[hg*WR + 32].x;
        float dcB = u2[(hg + 32)*WR].x, nyB = u2[(hg + 32)*WR + 32].x;
        #pragma unroll
        for (int j = 0; j < 4; j++) {
            float ps = (j & 1) ? -1.f : 1.f;
            float baseA = fmaf(ps, nyA, dcA);
            float baseB = fmaf(ps, nyB, dcB);
            res[0][j]     = (2.f*accP[0][j] + baseA) * scale;
            res[0][j + 4] = (2.f*accM[0][j] + baseA) * scale;
            res[1][j]     = (2.f*accP[1][j] + baseB) * scale;
            res[1][j + 4] = (2.f*accM[1][j] + baseB) * scale;
        }
        __syncthreads();
        #pragma unroll
        for (int j = 0; j < 4; j++) {
            int w = 4*wg + j;
            pl[hg*65 + w]             = res[0][j];
            pl[hg*65 + w + 32]        = res[0][j + 4];
            pl[(hg + 32)*65 + w]      = res[1][j];
            pl[(hg + 32)*65 + w + 32] = res[1][j + 4];
        }
    }
    __syncthreads();

    // Phase 4: softmax over the 4096 plane values (stride-65 layout)
    {
        float m = -3.4e38f;
        for (int i = tid; i < NPIX; i += 256) {
            float v = pl[(i >> 6)*65 + (i & 63)];
            m = fmaxf(m, v);
        }
        red[tid] = m; __syncthreads();
        for (int s = 128; s > 0; s >>= 1) { if (tid < s) red[tid] = fmaxf(red[tid], red[tid + s]); __syncthreads(); }
        const float M = red[0];
        __syncthreads();
        float sum = 0.f;
        for (int i = tid; i < NPIX; i += 256) {
            int a = (i >> 6)*65 + (i & 63);
            float e = __expf(pl[a] - M);
            pl[a] = e; sum += e;
        }
        red[tid] = sum; __syncthreads();
        for (int s = 128; s > 0; s >>= 1) { if (tid < s) red[tid] += red[tid + s]; __syncthreads(); }
        const float inv = 1.f / red[0];
        __syncthreads();
        for (int i = tid; i < NPIX; i += 256) {
            int a = (i >> 6)*65 + (i & 63);
            pl[a] *= inv;
        }
    }
    __syncthreads();

    // Phase 5: forward rfft along w: pl -> u2
    {
        const int hg  = tid & 31;
        const int kwg = tid >> 5;
        ull acc0[4] = {0,0,0,0};
        ull acc1[4] = {0,0,0,0};
        int idx[4], stp[4];
        #pragma unroll
        for (int j = 0; j < 4; j++) { idx[j] = 0; stp[j] = 4*kwg + j; }
        #pragma unroll 4
        for (int w = 0; w < 64; w++) {
            ull v0 = dup2(pl[hg*65 + w]);
            ull v1 = dup2(pl[(hg + 32)*65 + w]);
            #pragma unroll
            for (int j = 0; j < 4; j++) {
                ull T = lds_u64(&Tcn[idx[j]]);
                fma2(acc0[j], v0, T);
                fma2(acc1[j], v1, T);
                idx[j] = (idx[j] + stp[j]) & 63;
            }
        }
        float ny = 0.f;
        if (tid < 64) {
            #pragma unroll 8
            for (int w = 0; w < 64; w += 2) ny += pl[tid*65 + w] - pl[tid*65 + w + 1];
        }
        __syncthreads();
        #pragma unroll
        for (int j = 0; j < 4; j++) {
            u2[hg*WR + 4*kwg + j]        = upk2(acc0[j]);
            u2[(hg + 32)*WR + 4*kwg + j] = upk2(acc1[j]);
        }
        if (tid < 64) u2[tid*WR + 32] = make_float2(ny, 0.f);
    }
    __syncthreads();

    // Phase 6: forward fft along h: u2 -> global (scale 1, backward norm)
    {
        const int kwg = tid & 7;
        const int khg = tid >> 3;
        ull acc0[4] = {0,0,0,0};
        ull acc1[4] = {0,0,0,0};
        int idx = 0;
        #pragma unroll 4
        for (int h = 0; h < 64; h++) {
            int idx2 = idx ^ ((h & 1) << 5);
            ull Ta1 = lds_u64(&Tcn[idx]);
            ull Ta2 = lds_u64(&Tsc[idx]);
            ull Tb1 = lds_u64(&Tcn[idx2]);
            ull Tb2 = lds_u64(&Tsc[idx2]);
            #pragma unroll
            for (int j = 0; j < 4; j++) {
                float2 u = u2[h*WR + 4*kwg + j];
                ull ud = dup2(u.x), vd = dup2(u.y);
                fma2(acc0[j], ud, Ta1); fma2(acc0[j], vd, Ta2);
                fma2(acc1[j], ud, Tb1); fma2(acc1[j], vd, Tb2);
            }
            idx = (idx + khg) & 63;
        }
        float2* ob = outc + (size_t)plane * FREQ;
        #pragma unroll
        for (int j = 0; j < 4; j++) {
            int n = 4*kwg + j;
            ob[khg*WR + n]      = upk2(acc0[j]);
            ob[(khg+32)*WR + n] = upk2(acc1[j]);
        }
        if (tid < 64) {
            const int kh = tid;
            float yr = 0.f, yi = 0.f;
            int ix = 0;
            #pragma unroll 8
            for (int h = 0; h < 64; h++) {
                float2 T = Tcn[ix];
                float tr = u2[h*WR + 32].x;
                yr = fmaf(tr, T.x, yr);
                yi = fmaf(tr, T.y, yi);
                ix = (ix + kh) & 63;
            }
            ob[kh*WR + 32] = make_float2(yr, yi);
        }
    }
}

// ============================================================
// Fused: Y = conj(a)*b, irfft2(Y), multiply by gate, write plane.
// ============================================================
__global__ __launch_bounds__(256) void prod_ifft2_gate_kernel(
    const float2* __restrict__ ac, int aCPB, int aOff,
    const float2* __restrict__ bc, int bCPB, int bOff,
    const float* __restrict__ gate,
    float* __restrict__ out, float scale)
{
    __shared__ float2 y2[FREQ];
    __shared__ float2 u2[FREQ];
    __shared__ float2 TI1f[64];       // {cos,  sin}
    __shared__ float2 TI2f[64];       // {-sin, cos}
    const int tid = threadIdx.x;
    const int plane = blockIdx.x;
    const int b  = plane >> 9;
    const int ch = plane & 511;
    const float2* ap = ac + ((size_t)b * aCPB + aOff + ch) * FREQ;
    const float2* bp = bc + ((size_t)b * bCPB + bOff + ch) * FREQ;

    if (tid < 64) {
        float s, c; sincosf(TWO_PI_OVER_64 * (float)tid, &s, &c);
        TI1f[tid] = make_float2(c,  s);
        TI2f[tid] = make_float2(-s, c);
    }
    for (int i = tid; i < FREQ; i += 256) {
        float2 a = ap[i], bb = bp[i];
        y2[i] = make_float2(a.x*bb.x + a.y*bb.y, a.x*bb.y - a.y*bb.x);
    }
    __syncthreads();

    // Stage A: inverse along kh
    {
        const int kwg = tid & 7;
        const int hg  = tid >> 3;
        ull acc0[4] = {0,0,0,0};
        ull acc1[4] = {0,0,0,0};
        int idx = 0;
        #pragma unroll 4
        for (int kh = 0; kh < 64; kh++) {
            int idx2 = idx ^ ((kh & 1) << 5);
            ull Ta1 = lds_u64(&TI1f[idx]);
            ull Ta2 = lds_u64(&TI2f[idx]);
            ull Tb1 = lds_u64(&TI1f[idx2]);
            ull Tb2 = lds_u64(&TI2f[idx2]);
            #pragma unroll
            for (int j = 0; j < 4; j++) {
                float2 y = y2[kh*WR + 4*kwg + j];
                ull yr = dup2(y.x), yi = dup2(y.y);
                fma2(acc0[j], yr, Ta1); fma2(acc0[j], yi, Ta2);
                fma2(acc1[j], yr, Tb1); fma2(acc1[j], yi, Tb2);
            }
            idx = (idx + hg) & 63;
        }
        #pragma unroll
        for (int j = 0; j < 4; j++) {
            u2[hg*WR + 4*kwg + j]        = upk2(acc0[j]);
            u2[(hg + 32)*WR + 4*kwg + j] = upk2(acc1[j]);
        }
        if (tid < 64) {
            const int h = tid;
            float ur = 0.f, ui = 0.f;
            int ix = 0;
            #pragma unroll 8
            for (int kh = 0; kh < 64; kh++) {
                float2 T = TI1f[ix];
                float2 y = y2[kh*WR + 32];
                ur = fmaf(y.x, T.x, fmaf(-y.y, T.y, ur));
                ui = fmaf(y.x, T.y, fmaf( y.y, T.x, ui));
                ix = (ix + h) & 63;
            }
            u2[h*WR + 32] = make_float2(ur, ui);
        }
    }
    __syncthreads();

    // Stage B: inverse along kw (Hermitian), gate-multiply, store
    {
        const int wg = tid & 7;
        const int hg = tid >> 3;
        float accP[2][4] = {{0,0,0,0},{0,0,0,0}};
        float accM[2][4] = {{0,0,0,0},{0,0,0,0}};
        int idx[4], stp[4];
        #pragma unroll
        for (int j = 0; j < 4; j++) { stp[j] = 4*wg + j; idx[j] = stp[j]; }
        #pragma unroll 2
        for (int kw = 1; kw < 32; kw++) {
            float sgn = (kw & 1) ? -1.f : 1.f;
            float2 ua = u2[hg*WR + kw];
            float2 ub = u2[(hg + 32)*WR + kw];
            #pragma unroll
            for (int j = 0; j < 4; j++) {
                float2 T = TI1f[idx[j]];
                float ta = fmaf(ua.x, T.x, -ua.y * T.y);
                float tb = fmaf(ub.x, T.x, -ub.y * T.y);
                accP[0][j] += ta;  accM[0][j] = fmaf(sgn, ta, accM[0][j]);
                accP[1][j] += tb;  accM[1][j] = fmaf(sgn, tb, accM[1][j]);
                idx[j] = (idx[j] + stp[j]) & 63;
            }
        }
        float* op = out + (size_t)plane * NPIX;
        const float* gp = gate + (size_t)plane * NPIX;
        float dcA = u2[hg*WR].x,        nyA = u2[hg*WR + 32].x;
        float dcB = u2[(hg + 32)*WR].x, nyB = u2[(hg + 32)*WR + 32].x;
        #pragma unroll
        for (int j = 0; j < 4; j++) {
            int w = 4*wg + j;
            float ps = (j & 1) ? -1.f : 1.f;
            float baseA = fmaf(ps, nyA, dcA);
            float baseB = fmaf(ps, nyB, dcB);
            op[hg*64 + w]             = (2.f*accP[0][j] + baseA) * scale * gp[hg*64 + w];
            op[hg*64 + w + 32]        = (2.f*accM[0][j] + baseA) * scale * gp[hg*64 + w + 32];
            op[(hg + 32)*64 + w]      = (2.f*accP[1][j] + baseB) * scale * gp[(hg + 32)*64 + w];
            op[(hg + 32)*64 + w + 32] = (2.f*accM[1][j] + baseB) * scale * gp[(hg + 32)*64 + w + 32];
        }
    }
}

// ============================================================
// Packed-f32x2 GEMM, double-buffered (cp.async B, reg-staged A),
// A plain in smem, dup to pairs in registers (R4-proven config).
// C[m,n] = sum_k A[m,k]*B[k,n]; 128x128x16 tiles, 256 thr, 2 CTA/SM.
// MODE 0: plain. MODE 1: bias + SiLU. MODE 3: bias.
// ============================================================
template<int MODE>
__global__ __launch_bounds__(256, 2) void gemm_kernel(
    const float* __restrict__ A,
    const float* __restrict__ B,
    const float* __restrict__ bias,
    float* __restrict__ C,
    int M, int Ntot, int K)
{
    __shared__ __align__(16) float As[2][16][132];
    __shared__ __align__(16) float Bs[2][16][128];
    const int bx = blockIdx.x, by = blockIdx.y, bz = blockIdx.z;
    const float* Bp = B + (size_t)bz * K * Ntot;
    float* Cp = C + (size_t)bz * M * Ntot;
    const int tid = threadIdx.x;
    const int n0 = bx * 128, m0 = by * 128;
    const int tx = tid & 15, ty = tid >> 4;

    const int arow = tid >> 2;            // 0..63
    const int acol = (tid & 3) * 4;       // 0,4,8,12

    const unsigned int sBs = (unsigned int)__cvta_generic_to_shared(&Bs[0][0][0]);

    auto loadB = [&](int k0, int bufI) {
        #pragma unroll
        for (int q = 0; q < 2; q++) {
            int c   = tid + q * 256;
            int row = c >> 5;
            int col = (c & 31) * 4;
            int n   = n0 + col;
            int sz  = (n + 4 <= Ntot) ? 16 : 0;
            const float* g = Bp + (size_t)(k0 + row) * Ntot + (sz ? n : 0);
            cp_async16(sBs + (unsigned int)(((bufI * 16 + row) * 128 + col) * 4), g, sz);
        }
        cp_commit();
    };

    float4 Ar0, Ar1;
    auto loadA = [&](int k0) {
        Ar0 = *(const float4*)&A[(size_t)(m0 + arow) * K + k0 + acol];
        Ar1 = *(const float4*)&A[(size_t)(m0 + arow + 64) * K + k0 + acol];
    };
    auto storeA = [&](int bufI) {
        As[bufI][acol + 0][arow]      = Ar0.x;
        As[bufI][acol + 1][arow]      = Ar0.y;
        As[bufI][acol + 2][arow]      = Ar0.z;
        As[bufI][acol + 3][arow]      = Ar0.w;
        As[bufI][acol + 0][arow + 64] = Ar1.x;
        As[bufI][acol + 1][arow + 64] = Ar1.y;
        As[bufI][acol + 2][arow + 64] = Ar1.z;
        As[bufI][acol + 3][arow + 64] = Ar1.w;
    };

    ull acc[8][4];
    #pragma unroll
    for (int i = 0; i < 8; i++)
        #pragma unroll
        for (int j = 0; j < 4; j++) acc[i][j] = 0ull;

    const int nStages = K >> 4;

    loadA(0);
    loadB(0, 0);
    storeA(0);
    cp_wait0();
    __syncthreads();

    for (int s = 0; s < nStages; s++) {
        const int buf = s & 1, nxt = buf ^ 1;
        const bool more = (s + 1 < nStages);
        if (more) {
            loadA((s + 1) << 4);
            loadB((s + 1) << 4, nxt);
        }
        #pragma unroll
        for (int kk = 0; kk < 16; kk++) {
            ulonglong2 b01 = *(const ulonglong2*)&Bs[buf][kk][4 * tx];
            ulonglong2 b23 = *(const ulonglong2*)&Bs[buf][kk][64 + 4 * tx];
            float4 a0 = *(const float4*)&As[buf][kk][4 * ty];
            float4 a1 = *(const float4*)&As[buf][kk][64 + 4 * ty];
            ull bb[4] = {b01.x, b01.y, b23.x, b23.y};
            ull ad[8] = {dup2(a0.x), dup2(a0.y), dup2(a0.z), dup2(a0.w),
                         dup2(a1.x), dup2(a1.y), dup2(a1.z), dup2(a1.w)};
            #pragma unroll
            for (int i = 0; i < 8; i++)
                #pragma unroll
                for (int j = 0; j < 4; j++)
                    fma2(acc[i][j], ad[i], bb[j]);
        }
        if (more) {
            storeA(nxt);
            cp_wait0();
        }
        __syncthreads();
    }

    #pragma unroll
    for (int i = 0; i < 8; i++) {
        int m = m0 + ((i < 4) ? (ty * 4 + i) : (64 + ty * 4 + i - 4));
        float bv = (MODE >= 1) ? bias[m] : 0.f;
        #pragma unroll
        for (int jp = 0; jp < 4; jp++) {
            float2 v2 = upk2(acc[i][jp]);
            int nbase = n0 + ((jp < 2) ? (tx * 4 + 2 * jp) : (64 + tx * 4 + 2 * (jp - 2)));
            float vx = v2.x + bv, vy = v2.y + bv;
            if (MODE == 1) {
                vx = vx / (1.f + __expf(-vx));
                vy = vy / (1.f + __expf(-vy));
            }
            if (nbase + 1 < Ntot) {
                *(float2*)&Cp[(size_t)m * Ntot + nbase] = make_float2(vx, vy);
            } else if (nbase < Ntot) {
                Cp[(size_t)m * Ntot + nbase] = vx;
            }
        }
    }
}

// ============================================================
extern "C" void kernel_launch(void* const* d_in, const int* in_sizes, int n_in,
                              void* d_out, int out_size)
{
    const float* x      = (const float*)d_in[0];
    const float* w_qkv  = (const float*)d_in[1];
    const float* w_gate = (const float*)d_in[2];
    const float* b_gate = (const float*)d_in[3];
    const float* w_proj = (const float*)d_in[4];
    const float* b_proj = (const float*)d_in[5];
    float* out = (float*)d_out;

    float2 *Xc, *Qc;
    float  *ybuf, *t;
    cudaGetSymbolAddress((void**)&Xc,   g_Xc);
    cudaGetSymbolAddress((void**)&Qc,   g_Qc);
    cudaGetSymbolAddress((void**)&ybuf, g_y);
    cudaGetSymbolAddress((void**)&t,    g_t);

    const float inv64 = 1.0f / 64.0f;

    // 1. gate: t = SiLU(Wg * x + bg)
    {
        dim3 g(NPIX / 128, CH / 128, BATCH);
        gemm_kernel<1><<<g, 256>>>(w_gate, x, b_gate, t, CH, NPIX, CH);
    }
    // 2. X = rfft2(x), ortho -> interleaved complex
    fft2_fwd_kernel<<<PLANES, 256>>>(x, Xc, inv64);
    // 3. QKV = Wqkv * X, complex via interleaved pairs (one GEMM, Ntot=4224)
    {
        dim3 g((2 * FREQ) / 128, CH3 / 128, BATCH);
        gemm_kernel<0><<<g, 256>>>(w_qkv, (const float*)Xc, nullptr,
                                   (float*)Qc, CH3, 2 * FREQ, CH);
    }
    // 4-6. fused: conj(q)*k -> irfft2(ortho) -> softmax -> rfft2(bwd) -> Xc
    mid_fused_kernel<<<PLANES, 256>>>(Qc, Xc);
    // 7. y = irfft2(conj(A)*v) * t, ortho
    prod_ifft2_gate_kernel<<<PLANES, 256>>>(Xc, CH, 0,
                                            Qc, CH3, 1024,
                                            t, ybuf, inv64);
    // 8. out = Wp * y + bp
    {
        dim3 g(NPIX / 128, CH / 128, BATCH);
        gemm_kernel<3><<<g, 256>>>(w_proj, ybuf, b_proj, out, CH, NPIX, CH);
    }
}

// round 7
// speedup vs baseline: 1.5313x; 1.3394x over previous
#include <cuda_runtime.h>
#include <cstdint>
#include <math.h>

#define BATCH 8
#define CH    512
#define CH3   1536
#define HH    64
#define NPIX  4096          // 64*64
#define WR    33            // rfft width 64/2+1
#define FREQ  2112          // 64*33
#define PLANES (BATCH*CH)   // 4096

// ---- static scratch (no allocations allowed) ----
__device__ float2 g_Xc[BATCH*CH*FREQ];    // interleaved {re,im}
__device__ float2 g_Qc[BATCH*CH3*FREQ];   // interleaved {re,im}
__device__ float  g_y[BATCH*CH*NPIX];
__device__ float  g_t[BATCH*CH*NPIX];

#define TWO_PI_OVER_64 0.09817477042468103f

// ---- packed f32x2 helpers (GEMM) ----
typedef unsigned long long ull;

__device__ __forceinline__ ull pk2(float lo, float hi) {
    ull r;
    asm("mov.b64 %0, {%1, %2};" : "=l"(r) : "f"(lo), "f"(hi));
    return r;
}
__device__ __forceinline__ ull dup2(float v) { return pk2(v, v); }
__device__ __forceinline__ float2 upk2(ull v) {
    float2 f;
    asm("mov.b64 {%0, %1}, %2;" : "=f"(f.x), "=f"(f.y) : "l"(v));
    return f;
}
__device__ __forceinline__ void fma2(ull& d, ull a, ull b) {
    asm("fma.rn.f32x2 %0, %1, %2, %0;" : "+l"(d) : "l"(a), "l"(b));
}
__device__ __forceinline__ void cp_async16(unsigned int saddr, const void* g, int sz) {
    asm volatile("cp.async.cg.shared.global [%0], [%1], 16, %2;\n"
                 :: "r"(saddr), "l"(g), "r"(sz));
}
__device__ __forceinline__ void cp_commit() { asm volatile("cp.async.commit_group;\n"); }
__device__ __forceinline__ void cp_wait0()  { asm volatile("cp.async.wait_group 0;\n" ::: "memory"); }

// ---- complex helpers ----
__device__ __forceinline__ float2 cadd(float2 a, float2 b){ return make_float2(a.x+b.x, a.y+b.y); }
__device__ __forceinline__ float2 csub(float2 a, float2 b){ return make_float2(a.x-b.x, a.y-b.y); }
__device__ __forceinline__ float2 cmul(float2 a, float2 t){ return make_float2(a.x*t.x - a.y*t.y, a.x*t.y + a.y*t.x); }

template<int S>   // S=+1 inverse (e^{+i}), S=-1 forward (e^{-i})
__device__ __forceinline__ float2 muliS(float2 a) {
    return (S > 0) ? make_float2(-a.y, a.x) : make_float2(a.y, -a.x);
}

// In-register 8-point DFT: z[n] -> Z[k] = sum_n z[n] e^{S*2*pi*i*n*k/8}
template<int S>
__device__ __forceinline__ void dft8(float2 z[8]) {
    const float C = 0.70710678118654752f;
    const float sf = (S > 0) ? 1.f : -1.f;
    float2 t0 = cadd(z[0], z[4]), t1 = csub(z[0], z[4]);
    float2 t2 = cadd(z[2], z[6]), t3 = csub(z[2], z[6]);
    float2 E0 = cadd(t0, t2), E2 = csub(t0, t2);
    float2 t3r = muliS<S>(t3);
    float2 E1 = cadd(t1, t3r), E3 = csub(t1, t3r);
    float2 s0 = cadd(z[1], z[5]), s1 = csub(z[1], z[5]);
    float2 s2 = cadd(z[3], z[7]), s3 = csub(z[3], z[7]);
    float2 O0 = cadd(s0, s2), O2 = csub(s0, s2);
    float2 s3r = muliS<S>(s3);
    float2 O1 = cadd(s1, s3r), O3 = csub(s1, s3r);
    float2 W1O1 = make_float2(C*(O1.x - sf*O1.y), C*(O1.y + sf*O1.x));
    float2 W2O2 = muliS<S>(O2);
    float2 W3O3 = make_float2(C*(-O3.x - sf*O3.y), C*(-O3.y + sf*O3.x));
    z[0] = cadd(E0, O0);  z[4] = csub(E0, O0);
    z[1] = cadd(E1, W1O1); z[5] = csub(E1, W1O1);
    z[2] = cadd(E2, W2O2); z[6] = csub(E2, W2O2);
    z[3] = cadd(E3, W3O3); z[7] = csub(E3, W3O3);
}

// ============================================================
// Warp-cooperative 64-pt FFT phases. 256 threads = 32 groups x 8.
// Data layouts: spectra stored as arr[33*row_or_kh + col].
// ============================================================

// Inverse FFT along kh of y2[64][33] -> u2[64][33].
// Group 0 handles cols {0,32} packed (both conj-symmetric -> real results
// stored as {u0,u32} in col 0). Groups 1..31: plain complex col g.
__device__ __forceinline__ void ifft_cols(const float2* __restrict__ y2, float2* __restrict__ u2,
                                          const float2* Ti, int tid)
{
    const int g = tid >> 3, sub = tid & 7;
    float2 z[8];
    if (g == 0) {
        #pragma unroll
        for (int n1 = 0; n1 < 8; n1++) {
            int m = 8*n1 + sub;
            float2 A = y2[33*m], B = y2[33*m + 32];
            z[n1] = make_float2(A.x - B.y, A.y + B.x);    // A + i*B
        }
    } else {
        #pragma unroll
        for (int n1 = 0; n1 < 8; n1++) z[n1] = y2[33*(8*n1 + sub) + g];
    }
    dft8<1>(z);
    #pragma unroll
    for (int k1 = 1; k1 < 8; k1++) z[k1] = cmul(z[k1], Ti[k1*sub]);
    #pragma unroll
    for (int k1 = 0; k1 < 8; k1++) u2[33*(8*k1 + sub) + g] = z[k1];
    __syncwarp();
    #pragma unroll
    for (int j = 0; j < 8; j++) z[j] = u2[33*(8*sub + j) + g];   // sub = k1 now
    dft8<1>(z);
    __syncwarp();
    #pragma unroll
    for (int k2 = 0; k2 < 8; k2++) u2[33*(sub + 8*k2) + g] = z[k2];
}

// Inverse FFT along kw of Hermitian rows of u2 (pairs of rows packed into one
// complex FFT). Results: zres[k2] = {x_h0[w], x_h1[w]}, w = sub + 8*k2.
// Uses the pair's own 66-slot region of u2 as scratch.
__device__ __forceinline__ void ifft_rows(float2* __restrict__ u2, const float2* Ti, int tid,
                                          float2 zres[8])
{
    const int r = tid >> 3, sub = tid & 7;
    float2* R = u2 + 66*r;     // row h0 = R[0..32] (col0 packed {u0,u32}), row h1 = R[33..65]
    float2 z[8];
    #pragma unroll
    for (int n1 = 0; n1 < 8; n1++) {
        int m = 8*n1 + sub;
        float2 A, B;
        if (m == 0)       { A = make_float2(R[0].x, 0.f);  B = make_float2(R[33].x, 0.f); }
        else if (m == 32) { A = make_float2(R[0].y, 0.f);  B = make_float2(R[33].y, 0.f); }
        else if (m < 32)  { A = R[m];                      B = R[33 + m]; }
        else {
            float2 Am = R[64 - m];      A = make_float2(Am.x, -Am.y);
            float2 Bm = R[33 + 64 - m]; B = make_float2(Bm.x, -Bm.y);
        }
        z[n1] = make_float2(A.x - B.y, A.y + B.x);        // A + i*B
    }
    __syncwarp();   // all gathers done before scratch overwrites
    dft8<1>(z);
    #pragma unroll
    for (int k1 = 1; k1 < 8; k1++) z[k1] = cmul(z[k1], Ti[k1*sub]);
    #pragma unroll
    for (int k1 = 0; k1 < 8; k1++) R[8*k1 + sub] = z[k1];
    __syncwarp();
    #pragma unroll
    for (int j = 0; j < 8; j++) z[j] = R[8*sub + j];
    dft8<1>(z);
    #pragma unroll
    for (int k2 = 0; k2 < 8; k2++) zres[k2] = z[k2];
}

// Forward FFT along w of a real plane (stride plstride), row pairs packed.
// Unpacks to Hermitian spectra T stored at u2[33*h + k], k=0..32
// (T[h][0], T[h][32] exactly real).
__device__ __forceinline__ void fft_rows(const float* __restrict__ pl, int plstride,
                                         float2* __restrict__ u2, const float2* Tf, int tid)
{
    const int r = tid >> 3, sub = tid & 7;
    const float* p0 = pl + (2*r) * plstride;
    const float* p1 = pl + (2*r + 1) * plstride;
    float2* R = u2 + 66*r;
    float2 z[8];
    #pragma unroll
    for (int n1 = 0; n1 < 8; n1++) {
        int m = 8*n1 + sub;
        z[n1] = make_float2(p0[m], p1[m]);
    }
    dft8<-1>(z);
    #pragma unroll
    for (int k1 = 1; k1 < 8; k1++) z[k1] = cmul(z[k1], Tf[k1*sub]);
    #pragma unroll
    for (int k1 = 0; k1 < 8; k1++) R[8*k1 + sub] = z[k1];
    __syncwarp();
    #pragma unroll
    for (int j = 0; j < 8; j++) z[j] = R[8*sub + j];
    dft8<-1>(z);
    __syncwarp();
    #pragma unroll
    for (int k2 = 0; k2 < 8; k2++) R[sub + 8*k2] = z[k2];   // full Z[0..63]
    __syncwarp();
    // unpack: thread sub handles k = sub, sub+8, sub+16, sub+24 (+32 if sub==0)
    float2 Zk[5], Zm[5];
    #pragma unroll
    for (int q = 0; q < 4; q++) { int k = sub + 8*q; Zk[q] = R[k]; Zm[q] = R[(64 - k) & 63]; }
    if (sub == 0) { Zk[4] = R[32]; Zm[4] = R[32]; }
    __syncwarp();   // all Z reads done before T overwrites
    #pragma unroll
    for (int q = 0; q < 4; q++) {
        int k = sub + 8*q;
        R[k]      = make_float2(0.5f*(Zk[q].x + Zm[q].x), 0.5f*(Zk[q].y - Zm[q].y)); // T0
        R[33 + k] = make_float2(0.5f*(Zk[q].y + Zm[q].y), 0.5f*(Zm[q].x - Zk[q].x)); // T1
    }
    if (sub == 0) {
        R[32] = make_float2(Zk[4].x, 0.f);
        R[65] = make_float2(Zk[4].y, 0.f);
    }
}

// Forward FFT along h of u2[64][33] columns (cols 0 & 32 real -> packed),
// writes full 64x33 spectrum to global ob, scaled.
__device__ __forceinline__ void fft_cols_store(float2* __restrict__ u2, const float2* Tf, int tid,
                                               float2* __restrict__ ob, float scale)
{
    const int g = tid >> 3, sub = tid & 7;
    float2 z[8];
    if (g == 0) {
        #pragma unroll
        for (int n1 = 0; n1 < 8; n1++) {
            int h = 8*n1 + sub;
            z[n1] = make_float2(u2[33*h].x, u2[33*h + 32].x);   // a + i*b, both real
        }
    } else {
        #pragma unroll
        for (int n1 = 0; n1 < 8; n1++) z[n1] = u2[33*(8*n1 + sub) + g];
    }
    dft8<-1>(z);
    #pragma unroll
    for (int k1 = 1; k1 < 8; k1++) z[k1] = cmul(z[k1], Tf[k1*sub]);
    #pragma unroll
    for (int k1 = 0; k1 < 8; k1++) u2[33*(8*k1 + sub) + g] = z[k1];
    __syncwarp();
    #pragma unroll
    for (int j = 0; j < 8; j++) z[j] = u2[33*(8*sub + j) + g];
    dft8<-1>(z);
    __syncwarp();
    if (g != 0) {
        #pragma unroll
        for (int k2 = 0; k2 < 8; k2++) {
            int kh = sub + 8*k2;
            ob[kh*33 + g] = make_float2(z[k2].x * scale, z[k2].y * scale);
        }
    } else {
        #pragma unroll
        for (int k2 = 0; k2 < 8; k2++) u2[33*(sub + 8*k2)] = z[k2];
    }
    __syncwarp();
    if (g == 0) {
        // unpack packed col: outputs cols 0 and 32 for all kh
        #pragma unroll
        for (int j = 0; j < 8; j++) {
            int k = 8*sub + j;
            float2 Zk = u2[33*k];
            float2 Zm = u2[33*((64 - k) & 63)];
            ob[k*33 + 0]  = make_float2(0.5f*(Zk.x + Zm.x)*scale, 0.5f*(Zk.y - Zm.y)*scale);
            ob[k*33 + 32] = make_float2(0.5f*(Zk.y + Zm.y)*scale, 0.5f*(Zm.x - Zk.x)*scale);
        }
    }
}

// ============================================================
// Forward rfft2 of one 64x64 real plane -> interleaved complex.
// ============================================================
__global__ __launch_bounds__(256) void fft2_fwd_kernel(
    const float* __restrict__ in,
    float2* __restrict__ outc,
    float scale)
{
    __shared__ float  sp[HH * 65];
    __shared__ float2 u2[FREQ];
    __shared__ float2 Tf[64];
    const int tid = threadIdx.x;
    const float* p = in + (size_t)blockIdx.x * NPIX;

    if (tid < 64) {
        float s, c; sincosf(TWO_PI_OVER_64 * (float)tid, &s, &c);
        Tf[tid] = make_float2(c, -s);
    }
    for (int i = tid; i < NPIX; i += 256) sp[(i >> 6)*65 + (i & 63)] = p[i];
    __syncthreads();

    fft_rows(sp, 65, u2, Tf, tid);
    __syncthreads();
    fft_cols_store(u2, Tf, tid, outc + (size_t)blockIdx.x * FREQ, scale);
}

// ============================================================
// Fused middle: conj(q)*k -> irfft2(ortho) -> softmax ->
// rfft2(backward norm) -> outc. Plane never leaves smem.
// ============================================================
__global__ __launch_bounds__(256) void mid_fused_kernel(
    const float2* __restrict__ qc,
    float2* __restrict__ outc)
{
    __shared__ float2 y2[FREQ];       // product / reused as real plane [64][65]
    __shared__ float2 u2[FREQ];
    __shared__ float2 Tf[64];         // {cos, -sin}
    __shared__ float2 Ti[64];         // {cos,  sin}
    __shared__ float  red[256];
    float* pl = (float*)y2;

    const int tid = threadIdx.x;
    const int plane = blockIdx.x;
    const int b  = plane >> 9;
    const int ch = plane & 511;
    const float2* qp = qc + ((size_t)b * CH3 + ch) * FREQ;
    const float2* kp = qc + ((size_t)b * CH3 + 512 + ch) * FREQ;

    if (tid < 64) {
        float s, c; sincosf(TWO_PI_OVER_64 * (float)tid, &s, &c);
        Tf[tid] = make_float2(c, -s);
        Ti[tid] = make_float2(c,  s);
    }
    // Phase 1: Y = conj(q)*k
    for (int i = tid; i < FREQ; i += 256) {
        float2 q = qp[i], k = kp[i];
        y2[i] = make_float2(q.x*k.x + q.y*k.y, q.x*k.y - q.y*k.x);
    }
    __syncthreads();

    // Phase 2: inverse along kh
    ifft_cols(y2, u2, Ti, tid);
    __syncthreads();

    // Phase 3: inverse along kw -> real plane pl, * 1/64
    {
        float2 zres[8];
        ifft_rows(u2, Ti, tid, zres);
        const int r = tid >> 3, sub = tid & 7;
        const float s = 1.0f / 64.0f;
        #pragma unroll
        for (int k2 = 0; k2 < 8; k2++) {
            int w = sub + 8*k2;
            pl[(2*r)*65 + w]     = zres[k2].x * s;
            pl[(2*r + 1)*65 + w] = zres[k2].y * s;
        }
    }
    __syncthreads();

    // Phase 4: softmax over the 4096 plane values
    {
        float m = -3.4e38f;
        for (int i = tid; i < NPIX; i += 256) {
            float v = pl[(i >> 6)*65 + (i & 63)];
            m = fmaxf(m, v);
        }
        red[tid] = m; __syncthreads();
        for (int s = 128; s > 0; s >>= 1) { if (tid < s) red[tid] = fmaxf(red[tid], red[tid + s]); __syncthreads(); }
        const float M = red[0];
        __syncthreads();
        float sum = 0.f;
        for (int i = tid; i < NPIX; i += 256) {
            int a = (i >> 6)*65 + (i & 63);
            float e = __expf(pl[a] - M);
            pl[a] = e; sum += e;
        }
        red[tid] = sum; __syncthreads();
        for (int s = 128; s > 0; s >>= 1) { if (tid < s) red[tid] += red[tid + s]; __syncthreads(); }
        const float inv = 1.f / red[0];
        __syncthreads();
        for (int i = tid; i < NPIX; i += 256) {
            int a = (i >> 6)*65 + (i & 63);
            pl[a] *= inv;
        }
    }
    __syncthreads();

    // Phase 5: forward along w (row pairs) -> T in u2
    fft_rows(pl, 65, u2, Tf, tid);
    __syncthreads();

    // Phase 6: forward along h -> global (scale 1, backward norm)
    fft_cols_store(u2, Tf, tid, outc + (size_t)plane * FREQ, 1.0f);
}

// ============================================================
// Fused: Y = conj(a)*b, irfft2(Y), multiply by gate, write plane.
// ============================================================
__global__ __launch_bounds__(256) void prod_ifft2_gate_kernel(
    const float2* __restrict__ ac, int aCPB, int aOff,
    const float2* __restrict__ bc, int bCPB, int bOff,
    const float* __restrict__ gate,
    float* __restrict__ out, float scale)
{
    __shared__ float2 y2[FREQ];
    __shared__ float2 u2[FREQ];
    __shared__ float2 Ti[64];
    const int tid = threadIdx.x;
    const int plane = blockIdx.x;
    const int b  = plane >> 9;
    const int ch = plane & 511;
    const float2* ap = ac + ((size_t)b * aCPB + aOff + ch) * FREQ;
    const float2* bp = bc + ((size_t)b * bCPB + bOff + ch) * FREQ;

    if (tid < 64) {
        float s, c; sincosf(TWO_PI_OVER_64 * (float)tid, &s, &c);
        Ti[tid] = make_float2(c, s);
    }
    for (int i = tid; i < FREQ; i += 256) {
        float2 a = ap[i], bb = bp[i];
        y2[i] = make_float2(a.x*bb.x + a.y*bb.y, a.x*bb.y - a.y*bb.x);
    }
    __syncthreads();

    ifft_cols(y2, u2, Ti, tid);
    __syncthreads();

    {
        float2 zres[8];
        ifft_rows(u2, Ti, tid, zres);
        const int r = tid >> 3, sub = tid & 7;
        float* op = out + (size_t)plane * NPIX;
        const float* gp = gate + (size_t)plane * NPIX;
        #pragma unroll
        for (int k2 = 0; k2 < 8; k2++) {
            int w = sub + 8*k2;
            op[(2*r)*64 + w]     = zres[k2].x * scale * gp[(2*r)*64 + w];
            op[(2*r + 1)*64 + w] = zres[k2].y * scale * gp[(2*r + 1)*64 + w];
        }
    }
}

// ============================================================
// Packed-f32x2 GEMM, double-buffered (cp.async B, reg-staged A),
// A plain in smem, dup to pairs in registers (R4-proven config).
// MODE 0: plain. MODE 1: bias + SiLU. MODE 3: bias.
// ============================================================
template<int MODE>
__global__ __launch_bounds__(256, 2) void gemm_kernel(
    const float* __restrict__ A,
    const float* __restrict__ B,
    const float* __restrict__ bias,
    float* __restrict__ C,
    int M, int Ntot, int K)
{
    __shared__ __align__(16) float As[2][16][132];
    __shared__ __align__(16) float Bs[2][16][128];
    const int bx = blockIdx.x, by = blockIdx.y, bz = blockIdx.z;
    const float* Bp = B + (size_t)bz * K * Ntot;
    float* Cp = C + (size_t)bz * M * Ntot;
    const int tid = threadIdx.x;
    const int n0 = bx * 128, m0 = by * 128;
    const int tx = tid & 15, ty = tid >> 4;

    const int arow = tid >> 2;
    const int acol = (tid & 3) * 4;

    const unsigned int sBs = (unsigned int)__cvta_generic_to_shared(&Bs[0][0][0]);

    auto loadB = [&](int k0, int bufI) {
        #pragma unroll
        for (int q = 0; q < 2; q++) {
            int c   = tid + q * 256;
            int row = c >> 5;
            int col = (c & 31) * 4;
            int n   = n0 + col;
            int sz  = (n + 4 <= Ntot) ? 16 : 0;
            const float* g = Bp + (size_t)(k0 + row) * Ntot + (sz ? n : 0);
            cp_async16(sBs + (unsigned int)(((bufI * 16 + row) * 128 + col) * 4), g, sz);
        }
        cp_commit();
    };

    float4 Ar0, Ar1;
    auto loadA = [&](int k0) {
        Ar0 = *(const float4*)&A[(size_t)(m0 + arow) * K + k0 + acol];
        Ar1 = *(const float4*)&A[(size_t)(m0 + arow + 64) * K + k0 + acol];
    };
    auto storeA = [&](int bufI) {
        As[bufI][acol + 0][arow]      = Ar0.x;
        As[bufI][acol + 1][arow]      = Ar0.y;
        As[bufI][acol + 2][arow]      = Ar0.z;
        As[bufI][acol + 3][arow]      = Ar0.w;
        As[bufI][acol + 0][arow + 64] = Ar1.x;
        As[bufI][acol + 1][arow + 64] = Ar1.y;
        As[bufI][acol + 2][arow + 64] = Ar1.z;
        As[bufI][acol + 3][arow + 64] = Ar1.w;
    };

    ull acc[8][4];
    #pragma unroll
    for (int i = 0; i < 8; i++)
        #pragma unroll
        for (int j = 0; j < 4; j++) acc[i][j] = 0ull;

    const int nStages = K >> 4;

    loadA(0);
    loadB(0, 0);
    storeA(0);
    cp_wait0();
    __syncthreads();

    for (int s = 0; s < nStages; s++) {
        const int buf = s & 1, nxt = buf ^ 1;
        const bool more = (s + 1 < nStages);
        if (more) {
            loadA((s + 1) << 4);
            loadB((s + 1) << 4, nxt);
        }
        #pragma unroll
        for (int kk = 0; kk < 16; kk++) {
            ulonglong2 b01 = *(const ulonglong2*)&Bs[buf][kk][4 * tx];
            ulonglong2 b23 = *(const ulonglong2*)&Bs[buf][kk][64 + 4 * tx];
            float4 a0 = *(const float4*)&As[buf][kk][4 * ty];
            float4 a1 = *(const float4*)&As[buf][kk][64 + 4 * ty];
            ull bb[4] = {b01.x, b01.y, b23.x, b23.y};
            ull ad[8] = {dup2(a0.x), dup2(a0.y), dup2(a0.z), dup2(a0.w),
                         dup2(a1.x), dup2(a1.y), dup2(a1.z), dup2(a1.w)};
            #pragma unroll
            for (int i = 0; i < 8; i++)
                #pragma unroll
                for (int j = 0; j < 4; j++)
                    fma2(acc[i][j], ad[i], bb[j]);
        }
        if (more) {
            storeA(nxt);
            cp_wait0();
        }
        __syncthreads();
    }

    #pragma unroll
    for (int i = 0; i < 8; i++) {
        int m = m0 + ((i < 4) ? (ty * 4 + i) : (64 + ty * 4 + i - 4));
        float bv = (MODE >= 1) ? bias[m] : 0.f;
        #pragma unroll
        for (int jp = 0; jp < 4; jp++) {
            float2 v2 = upk2(acc[i][jp]);
            int nbase = n0 + ((jp < 2) ? (tx * 4 + 2 * jp) : (64 + tx * 4 + 2 * (jp - 2)));
            float vx = v2.x + bv, vy = v2.y + bv;
            if (MODE == 1) {
                vx = vx / (1.f + __expf(-vx));
                vy = vy / (1.f + __expf(-vy));
            }
            if (nbase + 1 < Ntot) {
                *(float2*)&Cp[(size_t)m * Ntot + nbase] = make_float2(vx, vy);
            } else if (nbase < Ntot) {
                Cp[(size_t)m * Ntot + nbase] = vx;
            }
        }
    }
}

// ============================================================
extern "C" void kernel_launch(void* const* d_in, const int* in_sizes, int n_in,
                              void* d_out, int out_size)
{
    const float* x      = (const float*)d_in[0];
    const float* w_qkv  = (const float*)d_in[1];
    const float* w_gate = (const float*)d_in[2];
    const float* b_gate = (const float*)d_in[3];
    const float* w_proj = (const float*)d_in[4];
    const float* b_proj = (const float*)d_in[5];
    float* out = (float*)d_out;

    float2 *Xc, *Qc;
    float  *ybuf, *t;
    cudaGetSymbolAddress((void**)&Xc,   g_Xc);
    cudaGetSymbolAddress((void**)&Qc,   g_Qc);
    cudaGetSymbolAddress((void**)&ybuf, g_y);
    cudaGetSymbolAddress((void**)&t,    g_t);

    const float inv64 = 1.0f / 64.0f;

    // 1. gate: t = SiLU(Wg * x + bg)
    {
        dim3 g(NPIX / 128, CH / 128, BATCH);
        gemm_kernel<1><<<g, 256>>>(w_gate, x, b_gate, t, CH, NPIX, CH);
    }
    // 2. X = rfft2(x), ortho -> interleaved complex
    fft2_fwd_kernel<<<PLANES, 256>>>(x, Xc, inv64);
    // 3. QKV = Wqkv * X, complex via interleaved pairs (one GEMM, Ntot=4224)
    {
        dim3 g((2 * FREQ) / 128, CH3 / 128, BATCH);
        gemm_kernel<0><<<g, 256>>>(w_qkv, (const float*)Xc, nullptr,
                                   (float*)Qc, CH3, 2 * FREQ, CH);
    }
    // 4-6. fused: conj(q)*k -> irfft2(ortho) -> softmax -> rfft2(bwd) -> Xc
    mid_fused_kernel<<<PLANES, 256>>>(Qc, Xc);
    // 7. y = irfft2(conj(A)*v) * t, ortho
    prod_ifft2_gate_kernel<<<PLANES, 256>>>(Xc, CH, 0,
                                            Qc, CH3, 1024,
                                            t, ybuf, inv64);
    // 8. out = Wp * y + bp
    {
        dim3 g(NPIX / 128, CH / 128, BATCH);
        gemm_kernel<3><<<g, 256>>>(w_proj, ybuf, b_proj, out, CH, NPIX, CH);
    }
}

// round 8
// speedup vs baseline: 2.4206x; 1.5807x over previous
#include <cuda_runtime.h>
#include <cuda_bf16.h>
#include <cstdint>
#include <math.h>

#define BATCH 8
#define CH    512
#define CH3   1536
#define HH    64
#define NPIX  4096          // 64*64
#define WR    33            // rfft width 64/2+1
#define FREQ  2112          // 64*33
#define PLANES (BATCH*CH)   // 4096
#define NQKV  4224          // 2*FREQ floats per plane-row (interleaved complex)

// ---- static scratch (no allocations allowed) ----
__device__ float2 g_Xc[BATCH*CH*FREQ];    // interleaved {re,im}
__device__ float2 g_Qc[BATCH*CH3*FREQ];   // interleaved {re,im}
__device__ float  g_y[BATCH*CH*NPIX];
__device__ float  g_t[BATCH*CH*NPIX];
// bf16 split buffers (lifetimes sequential; reused across steps)
__device__ __nv_bfloat16 g_wh[CH3*CH];
__device__ __nv_bfloat16 g_wl[CH3*CH];
__device__ __nv_bfloat16 g_bh[BATCH*CH*NQKV];
__device__ __nv_bfloat16 g_bl[BATCH*CH*NQKV];

#define TWO_PI_OVER_64 0.09817477042468103f

// ---- cp.async helpers ----
__device__ __forceinline__ void cp_async16(unsigned int saddr, const void* g) {
    asm volatile("cp.async.cg.shared.global [%0], [%1], 16;\n" :: "r"(saddr), "l"(g));
}
__device__ __forceinline__ void cp_commit() { asm volatile("cp.async.commit_group;\n"); }
__device__ __forceinline__ void cp_wait0()  { asm volatile("cp.async.wait_group 0;\n" ::: "memory"); }

// ---- tensor-core helpers ----
__device__ __forceinline__ void mma16816(float* d, const unsigned* a, const unsigned* b) {
    asm volatile("mma.sync.aligned.m16n8k16.row.col.f32.bf16.bf16.f32 "
        "{%0,%1,%2,%3}, {%4,%5,%6,%7}, {%8,%9}, {%0,%1,%2,%3};"
        : "+f"(d[0]), "+f"(d[1]), "+f"(d[2]), "+f"(d[3])
        : "r"(a[0]), "r"(a[1]), "r"(a[2]), "r"(a[3]), "r"(b[0]), "r"(b[1]));
}
__device__ __forceinline__ void ldsm4(unsigned* r, unsigned addr) {
    asm volatile("ldmatrix.sync.aligned.m8n8.x4.shared.b16 {%0,%1,%2,%3}, [%4];"
        : "=r"(r[0]), "=r"(r[1]), "=r"(r[2]), "=r"(r[3]) : "r"(addr));
}
__device__ __forceinline__ void ldsm4t(unsigned* r, unsigned addr) {
    asm volatile("ldmatrix.sync.aligned.m8n8.x4.trans.shared.b16 {%0,%1,%2,%3}, [%4];"
        : "=r"(r[0]), "=r"(r[1]), "=r"(r[2]), "=r"(r[3]) : "r"(addr));
}

// ---- complex helpers (plane kernels) ----
__device__ __forceinline__ float2 cadd(float2 a, float2 b){ return make_float2(a.x+b.x, a.y+b.y); }
__device__ __forceinline__ float2 csub(float2 a, float2 b){ return make_float2(a.x-b.x, a.y-b.y); }
__device__ __forceinline__ float2 cmul(float2 a, float2 t){ return make_float2(a.x*t.x - a.y*t.y, a.x*t.y + a.y*t.x); }

template<int S>
__device__ __forceinline__ float2 muliS(float2 a) {
    return (S > 0) ? make_float2(-a.y, a.x) : make_float2(a.y, -a.x);
}

template<int S>
__device__ __forceinline__ void dft8(float2 z[8]) {
    const float C = 0.70710678118654752f;
    const float sf = (S > 0) ? 1.f : -1.f;
    float2 t0 = cadd(z[0], z[4]), t1 = csub(z[0], z[4]);
    float2 t2 = cadd(z[2], z[6]), t3 = csub(z[2], z[6]);
    float2 E0 = cadd(t0, t2), E2 = csub(t0, t2);
    float2 t3r = muliS<S>(t3);
    float2 E1 = cadd(t1, t3r), E3 = csub(t1, t3r);
    float2 s0 = cadd(z[1], z[5]), s1 = csub(z[1], z[5]);
    float2 s2 = cadd(z[3], z[7]), s3 = csub(z[3], z[7]);
    float2 O0 = cadd(s0, s2), O2 = csub(s0, s2);
    float2 s3r = muliS<S>(s3);
    float2 O1 = cadd(s1, s3r), O3 = csub(s1, s3r);
    float2 W1O1 = make_float2(C*(O1.x - sf*O1.y), C*(O1.y + sf*O1.x));
    float2 W2O2 = muliS<S>(O2);
    float2 W3O3 = make_float2(C*(-O3.x - sf*O3.y), C*(-O3.y + sf*O3.x));
    z[0] = cadd(E0, O0);  z[4] = csub(E0, O0);
    z[1] = cadd(E1, W1O1); z[5] = csub(E1, W1O1);
    z[2] = cadd(E2, W2O2); z[6] = csub(E2, W2O2);
    z[3] = cadd(E3, W3O3); z[7] = csub(E3, W3O3);
}

// ============================================================
// Warp-cooperative 64-pt FFT phases (R7, unchanged).
// ============================================================
__device__ __forceinline__ void ifft_cols(const float2* __restrict__ y2, float2* __restrict__ u2,
                                          const float2* Ti, int tid)
{
    const int g = tid >> 3, sub = tid & 7;
    float2 z[8];
    if (g == 0) {
        #pragma unroll
        for (int n1 = 0; n1 < 8; n1++) {
            int m = 8*n1 + sub;
            float2 A = y2[33*m], B = y2[33*m + 32];
            z[n1] = make_float2(A.x - B.y, A.y + B.x);
        }
    } else {
        #pragma unroll
        for (int n1 = 0; n1 < 8; n1++) z[n1] = y2[33*(8*n1 + sub) + g];
    }
    dft8<1>(z);
    #pragma unroll
    for (int k1 = 1; k1 < 8; k1++) z[k1] = cmul(z[k1], Ti[k1*sub]);
    #pragma unroll
    for (int k1 = 0; k1 < 8; k1++) u2[33*(8*k1 + sub) + g] = z[k1];
    __syncwarp();
    #pragma unroll
    for (int j = 0; j < 8; j++) z[j] = u2[33*(8*sub + j) + g];
    dft8<1>(z);
    __syncwarp();
    #pragma unroll
    for (int k2 = 0; k2 < 8; k2++) u2[33*(sub + 8*k2) + g] = z[k2];
}

__device__ __forceinline__ void ifft_rows(float2* __restrict__ u2, const float2* Ti, int tid,
                                          float2 zres[8])
{
    const int r = tid >> 3, sub = tid & 7;
    float2* R = u2 + 66*r;
    float2 z[8];
    #pragma unroll
    for (int n1 = 0; n1 < 8; n1++) {
        int m = 8*n1 + sub;
        float2 A, B;
        if (m == 0)       { A = make_float2(R[0].x, 0.f);  B = make_float2(R[33].x, 0.f); }
        else if (m == 32) { A = make_float2(R[0].y, 0.f);  B = make_float2(R[33].y, 0.f); }
        else if (m < 32)  { A = R[m];                      B = R[33 + m]; }
        else {
            float2 Am = R[64 - m];      A = make_float2(Am.x, -Am.y);
            float2 Bm = R[33 + 64 - m]; B = make_float2(Bm.x, -Bm.y);
        }
        z[n1] = make_float2(A.x - B.y, A.y + B.x);
    }
    __syncwarp();
    dft8<1>(z);
    #pragma unroll
    for (int k1 = 1; k1 < 8; k1++) z[k1] = cmul(z[k1], Ti[k1*sub]);
    #pragma unroll
    for (int k1 = 0; k1 < 8; k1++) R[8*k1 + sub] = z[k1];
    __syncwarp();
    #pragma unroll
    for (int j = 0; j < 8; j++) z[j] = R[8*sub + j];
    dft8<1>(z);
    #pragma unroll
    for (int k2 = 0; k2 < 8; k2++) zres[k2] = z[k2];
}

__device__ __forceinline__ void fft_rows(const float* __restrict__ pl, int plstride,
                                         float2* __restrict__ u2, const float2* Tf, int tid)
{
    const int r = tid >> 3, sub = tid & 7;
    const float* p0 = pl + (2*r) * plstride;
    const float* p1 = pl + (2*r + 1) * plstride;
    float2* R = u2 + 66*r;
    float2 z[8];
    #pragma unroll
    for (int n1 = 0; n1 < 8; n1++) {
        int m = 8*n1 + sub;
        z[n1] = make_float2(p0[m], p1[m]);
    }
    dft8<-1>(z);
    #pragma unroll
    for (int k1 = 1; k1 < 8; k1++) z[k1] = cmul(z[k1], Tf[k1*sub]);
    #pragma unroll
    for (int k1 = 0; k1 < 8; k1++) R[8*k1 + sub] = z[k1];
    __syncwarp();
    #pragma unroll
    for (int j = 0; j < 8; j++) z[j] = R[8*sub + j];
    dft8<-1>(z);
    __syncwarp();
    #pragma unroll
    for (int k2 = 0; k2 < 8; k2++) R[sub + 8*k2] = z[k2];
    __syncwarp();
    float2 Zk[5], Zm[5];
    #pragma unroll
    for (int q = 0; q < 4; q++) { int k = sub + 8*q; Zk[q] = R[k]; Zm[q] = R[(64 - k) & 63]; }
    if (sub == 0) { Zk[4] = R[32]; Zm[4] = R[32]; }
    __syncwarp();
    #pragma unroll
    for (int q = 0; q < 4; q++) {
        int k = sub + 8*q;
        R[k]      = make_float2(0.5f*(Zk[q].x + Zm[q].x), 0.5f*(Zk[q].y - Zm[q].y));
        R[33 + k] = make_float2(0.5f*(Zk[q].y + Zm[q].y), 0.5f*(Zm[q].x - Zk[q].x));
    }
    if (sub == 0) {
        R[32] = make_float2(Zk[4].x, 0.f);
        R[65] = make_float2(Zk[4].y, 0.f);
    }
}

__device__ __forceinline__ void fft_cols_store(float2* __restrict__ u2, const float2* Tf, int tid,
                                               float2* __restrict__ ob, float scale)
{
    const int g = tid >> 3, sub = tid & 7;
    float2 z[8];
    if (g == 0) {
        #pragma unroll
        for (int n1 = 0; n1 < 8; n1++) {
            int h = 8*n1 + sub;
            z[n1] = make_float2(u2[33*h].x, u2[33*h + 32].x);
        }
    } else {
        #pragma unroll
        for (int n1 = 0; n1 < 8; n1++) z[n1] = u2[33*(8*n1 + sub) + g];
    }
    dft8<-1>(z);
    #pragma unroll
    for (int k1 = 1; k1 < 8; k1++) z[k1] = cmul(z[k1], Tf[k1*sub]);
    #pragma unroll
    for (int k1 = 0; k1 < 8; k1++) u2[33*(8*k1 + sub) + g] = z[k1];
    __syncwarp();
    #pragma unroll
    for (int j = 0; j < 8; j++) z[j] = u2[33*(8*sub + j) + g];
    dft8<-1>(z);
    __syncwarp();
    if (g != 0) {
        #pragma unroll
        for (int k2 = 0; k2 < 8; k2++) {
            int kh = sub + 8*k2;
            ob[kh*33 + g] = make_float2(z[k2].x * scale, z[k2].y * scale);
        }
    } else {
        #pragma unroll
        for (int k2 = 0; k2 < 8; k2++) u2[33*(sub + 8*k2)] = z[k2];
    }
    __syncwarp();
    if (g == 0) {
        #pragma unroll
        for (int j = 0; j < 8; j++) {
            int k = 8*sub + j;
            float2 Zk = u2[33*k];
            float2 Zm = u2[33*((64 - k) & 63)];
            ob[k*33 + 0]  = make_float2(0.5f*(Zk.x + Zm.x)*scale, 0.5f*(Zk.y - Zm.y)*scale);
            ob[k*33 + 32] = make_float2(0.5f*(Zk.y + Zm.y)*scale, 0.5f*(Zm.x - Zk.x)*scale);
        }
    }
}

// ============================================================
// fp32 -> (hi, lo) bf16 split, grid-strided, float4 vectorized.
// n must be a multiple of 4 (all our sizes are).
// ============================================================
__global__ __launch_bounds__(256) void split_kernel(
    const float* __restrict__ in,
    __nv_bfloat16* __restrict__ hi, __nv_bfloat16* __restrict__ lo, int n4)
{
    int i = blockIdx.x * 256 + threadIdx.x;
    int stride = gridDim.x * 256;
    for (; i < n4; i += stride) {
        float4 v = ((const float4*)in)[i];
        __nv_bfloat16 h0 = __float2bfloat16(v.x);
        __nv_bfloat16 h1 = __float2bfloat16(v.y);
        __nv_bfloat16 h2 = __float2bfloat16(v.z);
        __nv_bfloat16 h3 = __float2bfloat16(v.w);
        __nv_bfloat162 H01, H23, L01, L23;
        H01.x = h0; H01.y = h1; H23.x = h2; H23.y = h3;
        L01.x = __float2bfloat16(v.x - __bfloat162float(h0));
        L01.y = __float2bfloat16(v.y - __bfloat162float(h1));
        L23.x = __float2bfloat16(v.z - __bfloat162float(h2));
        L23.y = __float2bfloat16(v.w - __bfloat162float(h3));
        ((__nv_bfloat162*)hi)[2*i]     = H01;
        ((__nv_bfloat162*)hi)[2*i + 1] = H23;
        ((__nv_bfloat162*)lo)[2*i]     = L01;
        ((__nv_bfloat162*)lo)[2*i + 1] = L23;
    }
}

// ============================================================
// Split-bf16 tensor-core GEMM: C = A*B (+epilogue), fp32 out.
// A: M x K (weights, hi/lo bf16). B: per-batch K x Ntot (hi/lo bf16).
// D += Ahi*Bhi + Ahi*Blo + Alo*Bhi  (fp32 accum).
// 128x128x16 tiles, 256 thr = 8 warps (2M x 4N, 64x32 each).
// MODE 0: plain. MODE 1: bias+SiLU. MODE 3: bias.
// ============================================================
#define BKt 16
#define APAD 24    // A smem row pitch (bf16)
#define BPAD 136   // B smem row pitch (bf16)

template<int MODE>
__global__ __launch_bounds__(256) void mma_gemm(
    const __nv_bfloat16* __restrict__ Ah, const __nv_bfloat16* __restrict__ Al,
    const __nv_bfloat16* __restrict__ Bh, const __nv_bfloat16* __restrict__ Bl,
    const float* __restrict__ bias,
    float* __restrict__ C,
    int M, int Ntot, int K)
{
    __shared__ __align__(16) __nv_bfloat16 sAh[2][128][APAD];
    __shared__ __align__(16) __nv_bfloat16 sAl[2][128][APAD];
    __shared__ __align__(16) __nv_bfloat16 sBh[2][BKt][BPAD];
    __shared__ __align__(16) __nv_bfloat16 sBl[2][BKt][BPAD];

    const int bx = blockIdx.x, by = blockIdx.y, bz = blockIdx.z;
    const int n0 = bx * 128, m0 = by * 128;
    const __nv_bfloat16* Bhp = Bh + (size_t)bz * K * Ntot;
    const __nv_bfloat16* Blp = Bl + (size_t)bz * K * Ntot;
    float* Cp = C + (size_t)bz * M * Ntot;

    const int tid  = threadIdx.x;
    const int lane = tid & 31;
    const int wid  = tid >> 5;
    const int wm   = wid >> 2;         // 0..1
    const int wn   = wid & 3;          // 0..3

    const unsigned uAh = (unsigned)__cvta_generic_to_shared(&sAh[0][0][0]);
    const unsigned uAl = (unsigned)__cvta_generic_to_shared(&sAl[0][0][0]);
    const unsigned uBh = (unsigned)__cvta_generic_to_shared(&sBh[0][0][0]);
    const unsigned uBl = (unsigned)__cvta_generic_to_shared(&sBl[0][0][0]);

    // cp.async assignments
    const int arow = tid >> 1;              // 0..127
    const int achk = (tid & 1) * 8;         // col 0 or 8
    const int brow = tid >> 4;              // 0..15
    const int bchk = (tid & 15) * 8;        // col 0..120

    auto loadTiles = [&](int k0, int bufI) {
        cp_async16(uAh + (unsigned)(((bufI*128 + arow)*APAD + achk)*2),
                   Ah + (size_t)(m0 + arow) * K + k0 + achk);
        cp_async16(uAl + (unsigned)(((bufI*128 + arow)*APAD + achk)*2),
                   Al + (size_t)(m0 + arow) * K + k0 + achk);
        cp_async16(uBh + (unsigned)(((bufI*BKt + brow)*BPAD + bchk)*2),
                   Bhp + (size_t)(k0 + brow) * Ntot + n0 + bchk);
        cp_async16(uBl + (unsigned)(((bufI*BKt + brow)*BPAD + bchk)*2),
                   Blp + (size_t)(k0 + brow) * Ntot + n0 + bchk);
        cp_commit();
    };

    float acc[4][4][4];
    #pragma unroll
    for (int i = 0; i < 4; i++)
        #pragma unroll
        for (int j = 0; j < 4; j++)
            #pragma unroll
            for (int q = 0; q < 4; q++) acc[i][j][q] = 0.f;

    // ldmatrix lane-address offsets (bytes) within a buffer
    const unsigned aOff = (unsigned)(((lane & 15) * APAD + (lane >> 4) * 8) * 2);
    const unsigned bOff = (unsigned)(((lane & 15) * BPAD + 32*wn + (lane >> 4) * 8) * 2);

    const int nStages = K / BKt;
    loadTiles(0, 0);
    cp_wait0();
    __syncthreads();

    for (int s = 0; s < nStages; s++) {
        const int buf = s & 1, nxt = buf ^ 1;
        const bool more = (s + 1 < nStages);
        if (more) loadTiles((s + 1) * BKt, nxt);

        unsigned aH[4][4], aL[4][4], bH[2][4], bL[2][4];
        #pragma unroll
        for (int mf = 0; mf < 4; mf++) {
            unsigned rowbase = (unsigned)((buf*128 + 64*wm + 16*mf) * APAD * 2);
            ldsm4(aH[mf], uAh + rowbase + aOff);
            ldsm4(aL[mf], uAl + rowbase + aOff);
        }
        #pragma unroll
        for (int np = 0; np < 2; np++) {
            unsigned cb = (unsigned)((buf*BKt*BPAD + 16*np) * 2);
            ldsm4t(bH[np], uBh + cb + bOff);
            ldsm4t(bL[np], uBl + cb + bOff);
        }
        #pragma unroll
        for (int mf = 0; mf < 4; mf++)
            #pragma unroll
            for (int nf = 0; nf < 4; nf++) {
                const unsigned* bh = &bH[nf >> 1][2*(nf & 1)];
                const unsigned* bl = &bL[nf >> 1][2*(nf & 1)];
                mma16816(acc[mf][nf], aH[mf], bh);
                mma16816(acc[mf][nf], aH[mf], bl);
                mma16816(acc[mf][nf], aL[mf], bh);
            }
        if (more) cp_wait0();
        __syncthreads();
    }

    // epilogue
    const int rbase = m0 + 64*wm + (lane >> 2);
    const int cbase = n0 + 32*wn + 2*(lane & 3);
    #pragma unroll
    for (int mf = 0; mf < 4; mf++) {
        #pragma unroll
        for (int half = 0; half < 2; half++) {
            int m = rbase + 16*mf + 8*half;
            float bv = (MODE >= 1) ? bias[m] : 0.f;
            #pragma unroll
            for (int nf = 0; nf < 4; nf++) {
                int c = cbase + 8*nf;
                float vx = acc[mf][nf][2*half + 0] + bv;
                float vy = acc[mf][nf][2*half + 1] + bv;
                if (MODE == 1) {
                    vx = vx / (1.f + __expf(-vx));
                    vy = vy / (1.f + __expf(-vy));
                }
                *(float2*)&Cp[(size_t)m * Ntot + c] = make_float2(vx, vy);
            }
        }
    }
}

// ============================================================
// Plane kernels (R7, unchanged)
// ============================================================
__global__ __launch_bounds__(256) void fft2_fwd_kernel(
    const float* __restrict__ in, float2* __restrict__ outc, float scale)
{
    __shared__ float  sp[HH * 65];
    __shared__ float2 u2[FREQ];
    __shared__ float2 Tf[64];
    const int tid = threadIdx.x;
    const float* p = in + (size_t)blockIdx.x * NPIX;

    if (tid < 64) {
        float s, c; sincosf(TWO_PI_OVER_64 * (float)tid, &s, &c);
        Tf[tid] = make_float2(c, -s);
    }
    for (int i = tid; i < NPIX; i += 256) sp[(i >> 6)*65 + (i & 63)] = p[i];
    __syncthreads();

    fft_rows(sp, 65, u2, Tf, tid);
    __syncthreads();
    fft_cols_store(u2, Tf, tid, outc + (size_t)blockIdx.x * FREQ, scale);
}

__global__ __launch_bounds__(256) void mid_fused_kernel(
    const float2* __restrict__ qc, float2* __restrict__ outc)
{
    __shared__ float2 y2[FREQ];
    __shared__ float2 u2[FREQ];
    __shared__ float2 Tf[64];
    __shared__ float2 Ti[64];
    __shared__ float  red[256];
    float* pl = (float*)y2;

    const int tid = threadIdx.x;
    const int plane = blockIdx.x;
    const int b  = plane >> 9;
    const int ch = plane & 511;
    const float2* qp = qc + ((size_t)b * CH3 + ch) * FREQ;
    const float2* kp = qc + ((size_t)b * CH3 + 512 + ch) * FREQ;

    if (tid < 64) {
        float s, c; sincosf(TWO_PI_OVER_64 * (float)tid, &s, &c);
        Tf[tid] = make_float2(c, -s);
        Ti[tid] = make_float2(c,  s);
    }
    for (int i = tid; i < FREQ; i += 256) {
        float2 q = qp[i], k = kp[i];
        y2[i] = make_float2(q.x*k.x + q.y*k.y, q.x*k.y - q.y*k.x);
    }
    __syncthreads();

    ifft_cols(y2, u2, Ti, tid);
    __syncthreads();

    {
        float2 zres[8];
        ifft_rows(u2, Ti, tid, zres);
        const int r = tid >> 3, sub = tid & 7;
        const float s = 1.0f / 64.0f;
        #pragma unroll
        for (int k2 = 0; k2 < 8; k2++) {
            int w = sub + 8*k2;
            pl[(2*r)*65 + w]     = zres[k2].x * s;
            pl[(2*r + 1)*65 + w] = zres[k2].y * s;
        }
    }
    __syncthreads();

    {
        float m = -3.4e38f;
        for (int i = tid; i < NPIX; i += 256) {
            float v = pl[(i >> 6)*65 + (i & 63)];
            m = fmaxf(m, v);
        }
        red[tid] = m; __syncthreads();
        for (int s = 128; s > 0; s >>= 1) { if (tid < s) red[tid] = fmaxf(red[tid], red[tid + s]); __syncthreads(); }
        const float M = red[0];
        __syncthreads();
        float sum = 0.f;
        for (int i = tid; i < NPIX; i += 256) {
            int a = (i >> 6)*65 + (i & 63);
            float e = __expf(pl[a] - M);
            pl[a] = e; sum += e;
        }
        red[tid] = sum; __syncthreads();
        for (int s = 128; s > 0; s >>= 1) { if (tid < s) red[tid] += red[tid + s]; __syncthreads(); }
        const float inv = 1.f / red[0];
        __syncthreads();
        for (int i = tid; i < NPIX; i += 256) {
            int a = (i >> 6)*65 + (i & 63);
            pl[a] *= inv;
        }
    }
    __syncthreads();

    fft_rows(pl, 65, u2, Tf, tid);
    __syncthreads();
    fft_cols_store(u2, Tf, tid, outc + (size_t)plane * FREQ, 1.0f);
}

__global__ __launch_bounds__(256) void prod_ifft2_gate_kernel(
    const float2* __restrict__ ac, int aCPB, int aOff,
    const float2* __restrict__ bc, int bCPB, int bOff,
    const float* __restrict__ gate,
    float* __restrict__ out, float scale)
{
    __shared__ float2 y2[FREQ];
    __shared__ float2 u2[FREQ];
    __shared__ float2 Ti[64];
    const int tid = threadIdx.x;
    const int plane = blockIdx.x;
    const int b  = plane >> 9;
    const int ch = plane & 511;
    const float2* ap = ac + ((size_t)b * aCPB + aOff + ch) * FREQ;
    const float2* bp = bc + ((size_t)b * bCPB + bOff + ch) * FREQ;

    if (tid < 64) {
        float s, c; sincosf(TWO_PI_OVER_64 * (float)tid, &s, &c);
        Ti[tid] = make_float2(c, s);
    }
    for (int i = tid; i < FREQ; i += 256) {
        float2 a = ap[i], bb = bp[i];
        y2[i] = make_float2(a.x*bb.x + a.y*bb.y, a.x*bb.y - a.y*bb.x);
    }
    __syncthreads();

    ifft_cols(y2, u2, Ti, tid);
    __syncthreads();

    {
        float2 zres[8];
        ifft_rows(u2, Ti, tid, zres);
        const int r = tid >> 3, sub = tid & 7;
        float* op = out + (size_t)plane * NPIX;
        const float* gp = gate + (size_t)plane * NPIX;
        #pragma unroll
        for (int k2 = 0; k2 < 8; k2++) {
            int w = sub + 8*k2;
            op[(2*r)*64 + w]     = zres[k2].x * scale * gp[(2*r)*64 + w];
            op[(2*r + 1)*64 + w] = zres[k2].y * scale * gp[(2*r + 1)*64 + w];
        }
    }
}

// ============================================================
extern "C" void kernel_launch(void* const* d_in, const int* in_sizes, int n_in,
                              void* d_out, int out_size)
{
    const float* x      = (const float*)d_in[0];
    const float* w_qkv  = (const float*)d_in[1];
    const float* w_gate = (const float*)d_in[2];
    const float* b_gate = (const float*)d_in[3];
    const float* w_proj = (const float*)d_in[4];
    const float* b_proj = (const float*)d_in[5];
    float* out = (float*)d_out;

    float2 *Xc, *Qc;
    float  *ybuf, *t;
    __nv_bfloat16 *wh, *wl, *bh, *bl;
    cudaGetSymbolAddress((void**)&Xc,   g_Xc);
    cudaGetSymbolAddress((void**)&Qc,   g_Qc);
    cudaGetSymbolAddress((void**)&ybuf, g_y);
    cudaGetSymbolAddress((void**)&t,    g_t);
    cudaGetSymbolAddress((void**)&wh,   g_wh);
    cudaGetSymbolAddress((void**)&wl,   g_wl);
    cudaGetSymbolAddress((void**)&bh,   g_bh);
    cudaGetSymbolAddress((void**)&bl,   g_bl);

    const float inv64 = 1.0f / 64.0f;
    const int SPLIT_BLKS = 1184;   // 8 waves of 148

    // 1. split gate weight + x, then gate GEMM: t = SiLU(Wg*x + bg)
    split_kernel<<<SPLIT_BLKS, 256>>>(w_gate, wh, wl, (CH*CH)/4);
    split_kernel<<<SPLIT_BLKS, 256>>>(x, bh, bl, (BATCH*CH*NPIX)/4);
    {
        dim3 g(NPIX / 128, CH / 128, BATCH);
        mma_gemm<1><<<g, 256>>>(wh, wl, bh, bl, b_gate, t, CH, NPIX, CH);
    }
    // 2. X = rfft2(x), ortho
    fft2_fwd_kernel<<<PLANES, 256>>>(x, Xc, inv64);
    // 3. split qkv weight + Xc, then QKV GEMM (complex interleaved, Ntot=4224)
    split_kernel<<<SPLIT_BLKS, 256>>>(w_qkv, wh, wl, (CH3*CH)/4);
    split_kernel<<<SPLIT_BLKS, 256>>>((const float*)Xc, bh, bl, (BATCH*CH*NQKV)/4);
    {
        dim3 g(NQKV / 128, CH3 / 128, BATCH);
        mma_gemm<0><<<g, 256>>>(wh, wl, bh, bl, nullptr, (float*)Qc, CH3, NQKV, CH);
    }
    // 4-6. fused middle: conj(q)*k -> irfft2 -> softmax -> rfft2 -> Xc
    mid_fused_kernel<<<PLANES, 256>>>(Qc, Xc);
    // 7. y = irfft2(conj(A)*v) * t
    prod_ifft2_gate_kernel<<<PLANES, 256>>>(Xc, CH, 0,
                                            Qc, CH3, 1024,
                                            t, ybuf, inv64);
    // 8. split proj weight + y, then proj GEMM: out = Wp*y + bp
    split_kernel<<<SPLIT_BLKS, 256>>>(w_proj, wh, wl, (CH*CH)/4);
    split_kernel<<<SPLIT_BLKS, 256>>>(ybuf, bh, bl, (BATCH*CH*NPIX)/4);
    {
        dim3 g(NPIX / 128, CH / 128, BATCH);
        mma_gemm<3><<<g, 256>>>(wh, wl, bh, bl, b_proj, out, CH, NPIX, CH);
    }
}

// round 9
// speedup vs baseline: 2.4477x; 1.0112x over previous
#include <cuda_runtime.h>
#include <cuda_bf16.h>
#include <cstdint>
#include <math.h>

#define BATCH 8
#define CH    512
#define CH3   1536
#define HH    64
#define NPIX  4096          // 64*64
#define WR    33            // rfft width 64/2+1
#define FREQ  2112          // 64*33
#define PLANES (BATCH*CH)   // 4096
#define NQKV  4224          // 2*FREQ floats per plane-row (interleaved complex)

// ---- static scratch (no allocations allowed) ----
__device__ float2 g_Xc[BATCH*CH*FREQ];    // interleaved {re,im}
__device__ float2 g_Qc[BATCH*CH3*FREQ];   // interleaved {re,im}
__device__ float  g_y[BATCH*CH*NPIX];
__device__ float  g_t[BATCH*CH*NPIX];
// bf16 split buffers (lifetimes sequential; reused across steps)
__device__ __nv_bfloat16 g_wh[CH3*CH];
__device__ __nv_bfloat16 g_wl[CH3*CH];
__device__ __nv_bfloat16 g_bh[BATCH*CH*NQKV];
__device__ __nv_bfloat16 g_bl[BATCH*CH*NQKV];

#define TWO_PI_OVER_64 0.09817477042468103f

// ---- cp.async helpers ----
__device__ __forceinline__ void cp_async16(unsigned int saddr, const void* g) {
    asm volatile("cp.async.cg.shared.global [%0], [%1], 16;\n" :: "r"(saddr), "l"(g));
}
__device__ __forceinline__ void cp_commit() { asm volatile("cp.async.commit_group;\n"); }
__device__ __forceinline__ void cp_wait0()  { asm volatile("cp.async.wait_group 0;\n" ::: "memory"); }

// ---- tensor-core helpers ----
__device__ __forceinline__ void mma16816(float* d, const unsigned* a, const unsigned* b) {
    asm volatile("mma.sync.aligned.m16n8k16.row.col.f32.bf16.bf16.f32 "
        "{%0,%1,%2,%3}, {%4,%5,%6,%7}, {%8,%9}, {%0,%1,%2,%3};"
        : "+f"(d[0]), "+f"(d[1]), "+f"(d[2]), "+f"(d[3])
        : "r"(a[0]), "r"(a[1]), "r"(a[2]), "r"(a[3]), "r"(b[0]), "r"(b[1]));
}
__device__ __forceinline__ void ldsm4(unsigned* r, unsigned addr) {
    asm volatile("ldmatrix.sync.aligned.m8n8.x4.shared.b16 {%0,%1,%2,%3}, [%4];"
        : "=r"(r[0]), "=r"(r[1]), "=r"(r[2]), "=r"(r[3]) : "r"(addr));
}
__device__ __forceinline__ void ldsm4t(unsigned* r, unsigned addr) {
    asm volatile("ldmatrix.sync.aligned.m8n8.x4.trans.shared.b16 {%0,%1,%2,%3}, [%4];"
        : "=r"(r[0]), "=r"(r[1]), "=r"(r[2]), "=r"(r[3]) : "r"(addr));
}

// ---- complex helpers (plane kernels) ----
__device__ __forceinline__ float2 cadd(float2 a, float2 b){ return make_float2(a.x+b.x, a.y+b.y); }
__device__ __forceinline__ float2 csub(float2 a, float2 b){ return make_float2(a.x-b.x, a.y-b.y); }
__device__ __forceinline__ float2 cmul(float2 a, float2 t){ return make_float2(a.x*t.x - a.y*t.y, a.x*t.y + a.y*t.x); }

template<int S>
__device__ __forceinline__ float2 muliS(float2 a) {
    return (S > 0) ? make_float2(-a.y, a.x) : make_float2(a.y, -a.x);
}

template<int S>
__device__ __forceinline__ void dft8(float2 z[8]) {
    const float C = 0.70710678118654752f;
    const float sf = (S > 0) ? 1.f : -1.f;
    float2 t0 = cadd(z[0], z[4]), t1 = csub(z[0], z[4]);
    float2 t2 = cadd(z[2], z[6]), t3 = csub(z[2], z[6]);
    float2 E0 = cadd(t0, t2), E2 = csub(t0, t2);
    float2 t3r = muliS<S>(t3);
    float2 E1 = cadd(t1, t3r), E3 = csub(t1, t3r);
    float2 s0 = cadd(z[1], z[5]), s1 = csub(z[1], z[5]);
    float2 s2 = cadd(z[3], z[7]), s3 = csub(z[3], z[7]);
    float2 O0 = cadd(s0, s2), O2 = csub(s0, s2);
    float2 s3r = muliS<S>(s3);
    float2 O1 = cadd(s1, s3r), O3 = csub(s1, s3r);
    float2 W1O1 = make_float2(C*(O1.x - sf*O1.y), C*(O1.y + sf*O1.x));
    float2 W2O2 = muliS<S>(O2);
    float2 W3O3 = make_float2(C*(-O3.x - sf*O3.y), C*(-O3.y + sf*O3.x));
    z[0] = cadd(E0, O0);  z[4] = csub(E0, O0);
    z[1] = cadd(E1, W1O1); z[5] = csub(E1, W1O1);
    z[2] = cadd(E2, W2O2); z[6] = csub(E2, W2O2);
    z[3] = cadd(E3, W3O3); z[7] = csub(E3, W3O3);
}

// ============================================================
// Warp-cooperative 64-pt FFT phases (R7, unchanged).
// ============================================================
__device__ __forceinline__ void ifft_cols(const float2* __restrict__ y2, float2* __restrict__ u2,
                                          const float2* Ti, int tid)
{
    const int g = tid >> 3, sub = tid & 7;
    float2 z[8];
    if (g == 0) {
        #pragma unroll
        for (int n1 = 0; n1 < 8; n1++) {
            int m = 8*n1 + sub;
            float2 A = y2[33*m], B = y2[33*m + 32];
            z[n1] = make_float2(A.x - B.y, A.y + B.x);
        }
    } else {
        #pragma unroll
        for (int n1 = 0; n1 < 8; n1++) z[n1] = y2[33*(8*n1 + sub) + g];
    }
    dft8<1>(z);
    #pragma unroll
    for (int k1 = 1; k1 < 8; k1++) z[k1] = cmul(z[k1], Ti[k1*sub]);
    #pragma unroll
    for (int k1 = 0; k1 < 8; k1++) u2[33*(8*k1 + sub) + g] = z[k1];
    __syncwarp();
    #pragma unroll
    for (int j = 0; j < 8; j++) z[j] = u2[33*(8*sub + j) + g];
    dft8<1>(z);
    __syncwarp();
    #pragma unroll
    for (int k2 = 0; k2 < 8; k2++) u2[33*(sub + 8*k2) + g] = z[k2];
}

__device__ __forceinline__ void ifft_rows(float2* __restrict__ u2, const float2* Ti, int tid,
                                          float2 zres[8])
{
    const int r = tid >> 3, sub = tid & 7;
    float2* R = u2 + 66*r;
    float2 z[8];
    #pragma unroll
    for (int n1 = 0; n1 < 8; n1++) {
        int m = 8*n1 + sub;
        float2 A, B;
        if (m == 0)       { A = make_float2(R[0].x, 0.f);  B = make_float2(R[33].x, 0.f); }
        else if (m == 32) { A = make_float2(R[0].y, 0.f);  B = make_float2(R[33].y, 0.f); }
        else if (m < 32)  { A = R[m];                      B = R[33 + m]; }
        else {
            float2 Am = R[64 - m];      A = make_float2(Am.x, -Am.y);
            float2 Bm = R[33 + 64 - m]; B = make_float2(Bm.x, -Bm.y);
        }
        z[n1] = make_float2(A.x - B.y, A.y + B.x);
    }
    __syncwarp();
    dft8<1>(z);
    #pragma unroll
    for (int k1 = 1; k1 < 8; k1++) z[k1] = cmul(z[k1], Ti[k1*sub]);
    #pragma unroll
    for (int k1 = 0; k1 < 8; k1++) R[8*k1 + sub] = z[k1];
    __syncwarp();
    #pragma unroll
    for (int j = 0; j < 8; j++) z[j] = R[8*sub + j];
    dft8<1>(z);
    #pragma unroll
    for (int k2 = 0; k2 < 8; k2++) zres[k2] = z[k2];
}

__device__ __forceinline__ void fft_rows(const float* __restrict__ pl, int plstride,
                                         float2* __restrict__ u2, const float2* Tf, int tid)
{
    const int r = tid >> 3, sub = tid & 7;
    const float* p0 = pl + (2*r) * plstride;
    const float* p1 = pl + (2*r + 1) * plstride;
    float2* R = u2 + 66*r;
    float2 z[8];
    #pragma unroll
    for (int n1 = 0; n1 < 8; n1++) {
        int m = 8*n1 + sub;
        z[n1] = make_float2(p0[m], p1[m]);
    }
    dft8<-1>(z);
    #pragma unroll
    for (int k1 = 1; k1 < 8; k1++) z[k1] = cmul(z[k1], Tf[k1*sub]);
    #pragma unroll
    for (int k1 = 0; k1 < 8; k1++) R[8*k1 + sub] = z[k1];
    __syncwarp();
    #pragma unroll
    for (int j = 0; j < 8; j++) z[j] = R[8*sub + j];
    dft8<-1>(z);
    __syncwarp();
    #pragma unroll
    for (int k2 = 0; k2 < 8; k2++) R[sub + 8*k2] = z[k2];
    __syncwarp();
    float2 Zk[5], Zm[5];
    #pragma unroll
    for (int q = 0; q < 4; q++) { int k = sub + 8*q; Zk[q] = R[k]; Zm[q] = R[(64 - k) & 63]; }
    if (sub == 0) { Zk[4] = R[32]; Zm[4] = R[32]; }
    __syncwarp();
    #pragma unroll
    for (int q = 0; q < 4; q++) {
        int k = sub + 8*q;
        R[k]      = make_float2(0.5f*(Zk[q].x + Zm[q].x), 0.5f*(Zk[q].y - Zm[q].y));
        R[33 + k] = make_float2(0.5f*(Zk[q].y + Zm[q].y), 0.5f*(Zm[q].x - Zk[q].x));
    }
    if (sub == 0) {
        R[32] = make_float2(Zk[4].x, 0.f);
        R[65] = make_float2(Zk[4].y, 0.f);
    }
}

__device__ __forceinline__ void fft_cols_store(float2* __restrict__ u2, const float2* Tf, int tid,
                                               float2* __restrict__ ob, float scale)
{
    const int g = tid >> 3, sub = tid & 7;
    float2 z[8];
    if (g == 0) {
        #pragma unroll
        for (int n1 = 0; n1 < 8; n1++) {
            int h = 8*n1 + sub;
            z[n1] = make_float2(u2[33*h].x, u2[33*h + 32].x);
        }
    } else {
        #pragma unroll
        for (int n1 = 0; n1 < 8; n1++) z[n1] = u2[33*(8*n1 + sub) + g];
    }
    dft8<-1>(z);
    #pragma unroll
    for (int k1 = 1; k1 < 8; k1++) z[k1] = cmul(z[k1], Tf[k1*sub]);
    #pragma unroll
    for (int k1 = 0; k1 < 8; k1++) u2[33*(8*k1 + sub) + g] = z[k1];
    __syncwarp();
    #pragma unroll
    for (int j = 0; j < 8; j++) z[j] = u2[33*(8*sub + j) + g];
    dft8<-1>(z);
    __syncwarp();
    if (g != 0) {
        #pragma unroll
        for (int k2 = 0; k2 < 8; k2++) {
            int kh = sub + 8*k2;
            ob[kh*33 + g] = make_float2(z[k2].x * scale, z[k2].y * scale);
        }
    } else {
        #pragma unroll
        for (int k2 = 0; k2 < 8; k2++) u2[33*(sub + 8*k2)] = z[k2];
    }
    __syncwarp();
    if (g == 0) {
        #pragma unroll
        for (int j = 0; j < 8; j++) {
            int k = 8*sub + j;
            float2 Zk = u2[33*k];
            float2 Zm = u2[33*((64 - k) & 63)];
            ob[k*33 + 0]  = make_float2(0.5f*(Zk.x + Zm.x)*scale, 0.5f*(Zk.y - Zm.y)*scale);
            ob[k*33 + 32] = make_float2(0.5f*(Zk.y + Zm.y)*scale, 0.5f*(Zm.x - Zk.x)*scale);
        }
    }
}

// ============================================================
// fp32 -> (hi, lo) bf16 split, grid-strided, float4 vectorized.
// n must be a multiple of 4 (all our sizes are).
// ============================================================
__global__ __launch_bounds__(256) void split_kernel(
    const float* __restrict__ in,
    __nv_bfloat16* __restrict__ hi, __nv_bfloat16* __restrict__ lo, int n4)
{
    int i = blockIdx.x * 256 + threadIdx.x;
    int stride = gridDim.x * 256;
    for (; i < n4; i += stride) {
        float4 v = ((const float4*)in)[i];
        __nv_bfloat16 h0 = __float2bfloat16(v.x);
        __nv_bfloat16 h1 = __float2bfloat16(v.y);
        __nv_bfloat16 h2 = __float2bfloat16(v.z);
        __nv_bfloat16 h3 = __float2bfloat16(v.w);
        __nv_bfloat162 H01, H23, L01, L23;
        H01.x = h0; H01.y = h1; H23.x = h2; H23.y = h3;
        L01.x = __float2bfloat16(v.x - __bfloat162float(h0));
        L01.y = __float2bfloat16(v.y - __bfloat162float(h1));
        L23.x = __float2bfloat16(v.z - __bfloat162float(h2));
        L23.y = __float2bfloat16(v.w - __bfloat162float(h3));
        ((__nv_bfloat162*)hi)[2*i]     = H01;
        ((__nv_bfloat162*)hi)[2*i + 1] = H23;
        ((__nv_bfloat162*)lo)[2*i]     = L01;
        ((__nv_bfloat162*)lo)[2*i + 1] = L23;
    }
}

// ============================================================
// Split-bf16 tensor-core GEMM: C = A*B (+epilogue), fp32 out.
// A: M x K (weights, hi/lo bf16). B: per-batch K x Ntot (hi/lo bf16).
// D += Ahi*Bhi + Ahi*Blo + Alo*Bhi  (fp32 accum).
// 128x128x16 tiles, 256 thr = 8 warps (2M x 4N, 64x32 each).
// MODE 0: plain. MODE 1: bias+SiLU. MODE 3: bias.
// ============================================================
#define BKt 16
#define APAD 24    // A smem row pitch (bf16)
#define BPAD 136   // B smem row pitch (bf16)

template<int MODE>
__global__ __launch_bounds__(256) void mma_gemm(
    const __nv_bfloat16* __restrict__ Ah, const __nv_bfloat16* __restrict__ Al,
    const __nv_bfloat16* __restrict__ Bh, const __nv_bfloat16* __restrict__ Bl,
    const float* __restrict__ bias,
    float* __restrict__ C,
    int M, int Ntot, int K)
{
    __shared__ __align__(16) __nv_bfloat16 sAh[2][128][APAD];
    __shared__ __align__(16) __nv_bfloat16 sAl[2][128][APAD];
    __shared__ __align__(16) __nv_bfloat16 sBh[2][BKt][BPAD];
    __shared__ __align__(16) __nv_bfloat16 sBl[2][BKt][BPAD];

    const int bx = blockIdx.x, by = blockIdx.y, bz = blockIdx.z;
    const int n0 = bx * 128, m0 = by * 128;
    const __nv_bfloat16* Bhp = Bh + (size_t)bz * K * Ntot;
    const __nv_bfloat16* Blp = Bl + (size_t)bz * K * Ntot;
    float* Cp = C + (size_t)bz * M * Ntot;

    const int tid  = threadIdx.x;
    const int lane = tid & 31;
    const int wid  = tid >> 5;
    const int wm   = wid >> 2;         // 0..1
    const int wn   = wid & 3;          // 0..3

    const unsigned uAh = (unsigned)__cvta_generic_to_shared(&sAh[0][0][0]);
    const unsigned uAl = (unsigned)__cvta_generic_to_shared(&sAl[0][0][0]);
    const unsigned uBh = (unsigned)__cvta_generic_to_shared(&sBh[0][0][0]);
    const unsigned uBl = (unsigned)__cvta_generic_to_shared(&sBl[0][0][0]);

    // cp.async assignments
    const int arow = tid >> 1;              // 0..127
    const int achk = (tid & 1) * 8;         // col 0 or 8
    const int brow = tid >> 4;              // 0..15
    const int bchk = (tid & 15) * 8;        // col 0..120

    auto loadTiles = [&](int k0, int bufI) {
        cp_async16(uAh + (unsigned)(((bufI*128 + arow)*APAD + achk)*2),
                   Ah + (size_t)(m0 + arow) * K + k0 + achk);
        cp_async16(uAl + (unsigned)(((bufI*128 + arow)*APAD + achk)*2),
                   Al + (size_t)(m0 + arow) * K + k0 + achk);
        cp_async16(uBh + (unsigned)(((bufI*BKt + brow)*BPAD + bchk)*2),
                   Bhp + (size_t)(k0 + brow) * Ntot + n0 + bchk);
        cp_async16(uBl + (unsigned)(((bufI*BKt + brow)*BPAD + bchk)*2),
                   Blp + (size_t)(k0 + brow) * Ntot + n0 + bchk);
        cp_commit();
    };

    float acc[4][4][4];
    #pragma unroll
    for (int i = 0; i < 4; i++)
        #pragma unroll
        for (int j = 0; j < 4; j++)
            #pragma unroll
            for (int q = 0; q < 4; q++) acc[i][j][q] = 0.f;

    // ldmatrix lane-address offsets (bytes) within a buffer
    const unsigned aOff = (unsigned)(((lane & 15) * APAD + (lane >> 4) * 8) * 2);
    const unsigned bOff = (unsigned)(((lane & 15) * BPAD + 32*wn + (lane >> 4) * 8) * 2);

    const int nStages = K / BKt;
    loadTiles(0, 0);
    cp_wait0();
    __syncthreads();

    for (int s = 0; s < nStages; s++) {
        const int buf = s & 1, nxt = buf ^ 1;
        const bool more = (s + 1 < nStages);
        if (more) loadTiles((s + 1) * BKt, nxt);

        unsigned aH[4][4], aL[4][4], bH[2][4], bL[2][4];
        #pragma unroll
        for (int mf = 0; mf < 4; mf++) {
            unsigned rowbase = (unsigned)((buf*128 + 64*wm + 16*mf) * APAD * 2);
            ldsm4(aH[mf], uAh + rowbase + aOff);
            ldsm4(aL[mf], uAl + rowbase + aOff);
        }
        #pragma unroll
        for (int np = 0; np < 2; np++) {
            unsigned cb = (unsigned)((buf*BKt*BPAD + 16*np) * 2);
            ldsm4t(bH[np], uBh + cb + bOff);
            ldsm4t(bL[np], uBl + cb + bOff);
        }
        #pragma unroll
        for (int mf = 0; mf < 4; mf++)
            #pragma unroll
            for (int nf = 0; nf < 4; nf++) {
                const unsigned* bh = &bH[nf >> 1][2*(nf & 1)];
                const unsigned* bl = &bL[nf >> 1][2*(nf & 1)];
                mma16816(acc[mf][nf], aH[mf], bh);
                mma16816(acc[mf][nf], aH[mf], bl);
                mma16816(acc[mf][nf], aL[mf], bh);
            }
        if (more) cp_wait0();
        __syncthreads();
    }

    // epilogue
    const int rbase = m0 + 64*wm + (lane >> 2);
    const int cbase = n0 + 32*wn + 2*(lane & 3);
    #pragma unroll
    for (int mf = 0; mf < 4; mf++) {
        #pragma unroll
        for (int half = 0; half < 2; half++) {
            int m = rbase + 16*mf + 8*half;
            float bv = (MODE >= 1) ? bias[m] : 0.f;
            #pragma unroll
            for (int nf = 0; nf < 4; nf++) {
                int c = cbase + 8*nf;
                float vx = acc[mf][nf][2*half + 0] + bv;
                float vy = acc[mf][nf][2*half + 1] + bv;
                if (MODE == 1) {
                    vx = vx / (1.f + __expf(-vx));
                    vy = vy / (1.f + __expf(-vy));
                }
                *(float2*)&Cp[(size_t)m * Ntot + c] = make_float2(vx, vy);
            }
        }
    }
}

// ============================================================
// Plane kernels (R7, unchanged)
// ============================================================
__global__ __launch_bounds__(256) void fft2_fwd_kernel(
    const float* __restrict__ in, float2* __restrict__ outc, float scale)
{
    __shared__ float  sp[HH * 65];
    __shared__ float2 u2[FREQ];
    __shared__ float2 Tf[64];
    const int tid = threadIdx.x;
    const float* p = in + (size_t)blockIdx.x * NPIX;

    if (tid < 64) {
        float s, c; sincosf(TWO_PI_OVER_64 * (float)tid, &s, &c);
        Tf[tid] = make_float2(c, -s);
    }
    for (int i = tid; i < NPIX; i += 256) sp[(i >> 6)*65 + (i & 63)] = p[i];
    __syncthreads();

    fft_rows(sp, 65, u2, Tf, tid);
    __syncthreads();
    fft_cols_store(u2, Tf, tid, outc + (size_t)blockIdx.x * FREQ, scale);
}

__global__ __launch_bounds__(256) void mid_fused_kernel(
    const float2* __restrict__ qc, float2* __restrict__ outc)
{
    __shared__ float2 y2[FREQ];
    __shared__ float2 u2[FREQ];
    __shared__ float2 Tf[64];
    __shared__ float2 Ti[64];
    __shared__ float  red[256];
    float* pl = (float*)y2;

    const int tid = threadIdx.x;
    const int plane = blockIdx.x;
    const int b  = plane >> 9;
    const int ch = plane & 511;
    const float2* qp = qc + ((size_t)b * CH3 + ch) * FREQ;
    const float2* kp = qc + ((size_t)b * CH3 + 512 + ch) * FREQ;

    if (tid < 64) {
        float s, c; sincosf(TWO_PI_OVER_64 * (float)tid, &s, &c);
        Tf[tid] = make_float2(c, -s);
        Ti[tid] = make_float2(c,  s);
    }
    for (int i = tid; i < FREQ; i += 256) {
        float2 q = qp[i], k = kp[i];
        y2[i] = make_float2(q.x*k.x + q.y*k.y, q.x*k.y - q.y*k.x);
    }
    __syncthreads();

    ifft_cols(y2, u2, Ti, tid);
    __syncthreads();

    {
        float2 zres[8];
        ifft_rows(u2, Ti, tid, zres);
        const int r = tid >> 3, sub = tid & 7;
        const float s = 1.0f / 64.0f;
        #pragma unroll
        for (int k2 = 0; k2 < 8; k2++) {
            int w = sub + 8*k2;
            pl[(2*r)*65 + w]     = zres[k2].x * s;
            pl[(2*r + 1)*65 + w] = zres[k2].y * s;
        }
    }
    __syncthreads();

    {
        float m = -3.4e38f;
        for (int i = tid; i < NPIX; i += 256) {
            float v = pl[(i >> 6)*65 + (i & 63)];
            m = fmaxf(m, v);
        }
        red[tid] = m; __syncthreads();
        for (int s = 128; s > 0; s >>= 1) { if (tid < s) red[tid] = fmaxf(red[tid], red[tid + s]); __syncthreads(); }
        const float M = red[0];
        __syncthreads();
        float sum = 0.f;
        for (int i = tid; i < NPIX; i += 256) {
            int a = (i >> 6)*65 + (i & 63);
            float e = __expf(pl[a] - M);
            pl[a] = e; sum += e;
        }
        red[tid] = sum; __syncthreads();
        for (int s = 128; s > 0; s >>= 1) { if (tid < s) red[tid] += red[tid + s]; __syncthreads(); }
        const float inv = 1.f / red[0];
        __syncthreads();
        for (int i = tid; i < NPIX; i += 256) {
            int a = (i >> 6)*65 + (i & 63);
            pl[a] *= inv;
        }
    }
    __syncthreads();

    fft_rows(pl, 65, u2, Tf, tid);
    __syncthreads();
    fft_cols_store(u2, Tf, tid, outc + (size_t)plane * FREQ, 1.0f);
}

__global__ __launch_bounds__(256) void prod_ifft2_gate_kernel(
    const float2* __restrict__ ac, int aCPB, int aOff,
    const float2* __restrict__ bc, int bCPB, int bOff,
    const float* __restrict__ gate,
    float* __restrict__ out, float scale)
{
    __shared__ float2 y2[FREQ];
    __shared__ float2 u2[FREQ];
    __shared__ float2 Ti[64];
    const int tid = threadIdx.x;
    const int plane = blockIdx.x;
    const int b  = plane >> 9;
    const int ch = plane & 511;
    const float2* ap = ac + ((size_t)b * aCPB + aOff + ch) * FREQ;
    const float2* bp = bc + ((size_t)b * bCPB + bOff + ch) * FREQ;

    if (tid < 64) {
        float s, c; sincosf(TWO_PI_OVER_64 * (float)tid, &s, &c);
        Ti[tid] = make_float2(c, s);
    }
    for (int i = tid; i < FREQ; i += 256) {
        float2 a = ap[i], bb = bp[i];
        y2[i] = make_float2(a.x*bb.x + a.y*bb.y, a.x*bb.y - a.y*bb.x);
    }
    __syncthreads();

    ifft_cols(y2, u2, Ti, tid);
    __syncthreads();

    {
        float2 zres[8];
        ifft_rows(u2, Ti, tid, zres);
        const int r = tid >> 3, sub = tid & 7;
        float* op = out + (size_t)plane * NPIX;
        const float* gp = gate + (size_t)plane * NPIX;
        #pragma unroll
        for (int k2 = 0; k2 < 8; k2++) {
            int w = sub + 8*k2;
            op[(2*r)*64 + w]     = zres[k2].x * scale * gp[(2*r)*64 + w];
            op[(2*r + 1)*64 + w] = zres[k2].y * scale * gp[(2*r + 1)*64 + w];
        }
    }
}

// ============================================================
extern "C" void kernel_launch(void* const* d_in, const int* in_sizes, int n_in,
                              void* d_out, int out_size)
{
    const float* x      = (const float*)d_in[0];
    const float* w_qkv  = (const float*)d_in[1];
    const float* w_gate = (const float*)d_in[2];
    const float* b_gate = (const float*)d_in[3];
    const float* w_proj = (const float*)d_in[4];
    const float* b_proj = (const float*)d_in[5];
    float* out = (float*)d_out;

    float2 *Xc, *Qc;
    float  *ybuf, *t;
    __nv_bfloat16 *wh, *wl, *bh, *bl;
    cudaGetSymbolAddress((void**)&Xc,   g_Xc);
    cudaGetSymbolAddress((void**)&Qc,   g_Qc);
    cudaGetSymbolAddress((void**)&ybuf, g_y);
    cudaGetSymbolAddress((void**)&t,    g_t);
    cudaGetSymbolAddress((void**)&wh,   g_wh);
    cudaGetSymbolAddress((void**)&wl,   g_wl);
    cudaGetSymbolAddress((void**)&bh,   g_bh);
    cudaGetSymbolAddress((void**)&bl,   g_bl);

    const float inv64 = 1.0f / 64.0f;
    const int SPLIT_BLKS = 1184;   // 8 waves of 148

    // 1. split gate weight + x, then gate GEMM: t = SiLU(Wg*x + bg)
    split_kernel<<<SPLIT_BLKS, 256>>>(w_gate, wh, wl, (CH*CH)/4);
    split_kernel<<<SPLIT_BLKS, 256>>>(x, bh, bl, (BATCH*CH*NPIX)/4);
    {
        dim3 g(NPIX / 128, CH / 128, BATCH);
        mma_gemm<1><<<g, 256>>>(wh, wl, bh, bl, b_gate, t, CH, NPIX, CH);
    }
    // 2. X = rfft2(x), ortho
    fft2_fwd_kernel<<<PLANES, 256>>>(x, Xc, inv64);
    // 3. split qkv weight + Xc, then QKV GEMM (complex interleaved, Ntot=4224)
    split_kernel<<<SPLIT_BLKS, 256>>>(w_qkv, wh, wl, (CH3*CH)/4);
    split_kernel<<<SPLIT_BLKS, 256>>>((const float*)Xc, bh, bl, (BATCH*CH*NQKV)/4);
    {
        dim3 g(NQKV / 128, CH3 / 128, BATCH);
        mma_gemm<0><<<g, 256>>>(wh, wl, bh, bl, nullptr, (float*)Qc, CH3, NQKV, CH);
    }
    // 4-6. fused middle: conj(q)*k -> irfft2 -> softmax -> rfft2 -> Xc
    mid_fused_kernel<<<PLANES, 256>>>(Qc, Xc);
    // 7. y = irfft2(conj(A)*v) * t
    prod_ifft2_gate_kernel<<<PLANES, 256>>>(Xc, CH, 0,
                                            Qc, CH3, 1024,
                                            t, ybuf, inv64);
    // 8. split proj weight + y, then proj GEMM: out = Wp*y + bp
    split_kernel<<<SPLIT_BLKS, 256>>>(w_proj, wh, wl, (CH*CH)/4);
    split_kernel<<<SPLIT_BLKS, 256>>>(ybuf, bh, bl, (BATCH*CH*NPIX)/4);
    {
        dim3 g(NPIX / 128, CH / 128, BATCH);
        mma_gemm<3><<<g, 256>>>(wh, wl, bh, bl, b_proj, out, CH, NPIX, CH);
    }
}

// round 10
// speedup vs baseline: 2.5208x; 1.0299x over previous
#include <cuda_runtime.h>
#include <cuda_bf16.h>
#include <cstdint>
#include <math.h>

#define BATCH 8
#define CH    512
#define CH3   1536
#define HH    64
#define NPIX  4096          // 64*64
#define WR    33            // rfft width 64/2+1
#define FREQ  2112          // 64*33
#define PLANES (BATCH*CH)   // 4096
#define NQKV  4224          // 2*FREQ floats per plane-row (interleaved complex)

// ---- static scratch (no allocations allowed) ----
__device__ float2 g_Xc[BATCH*CH*FREQ];    // interleaved {re,im} (mid output)
__device__ float2 g_Qc[BATCH*CH3*FREQ];   // interleaved {re,im}
__device__ float  g_t[BATCH*CH*NPIX];
// bf16 split buffers (lifetimes sequential; reused across steps)
__device__ __nv_bfloat16 g_wh[CH3*CH];
__device__ __nv_bfloat16 g_wl[CH3*CH];
__device__ __nv_bfloat16 g_bh[BATCH*CH*NQKV];
__device__ __nv_bfloat16 g_bl[BATCH*CH*NQKV];

#define TWO_PI_OVER_64 0.09817477042468103f

// ---- cp.async helpers ----
__device__ __forceinline__ void cp_async16(unsigned int saddr, const void* g) {
    asm volatile("cp.async.cg.shared.global [%0], [%1], 16;\n" :: "r"(saddr), "l"(g));
}
__device__ __forceinline__ void cp_commit() { asm volatile("cp.async.commit_group;\n"); }
__device__ __forceinline__ void cp_wait0()  { asm volatile("cp.async.wait_group 0;\n" ::: "memory"); }

// ---- tensor-core helpers ----
__device__ __forceinline__ void mma16816(float* d, const unsigned* a, const unsigned* b) {
    asm volatile("mma.sync.aligned.m16n8k16.row.col.f32.bf16.bf16.f32 "
        "{%0,%1,%2,%3}, {%4,%5,%6,%7}, {%8,%9}, {%0,%1,%2,%3};"
        : "+f"(d[0]), "+f"(d[1]), "+f"(d[2]), "+f"(d[3])
        : "r"(a[0]), "r"(a[1]), "r"(a[2]), "r"(a[3]), "r"(b[0]), "r"(b[1]));
}
__device__ __forceinline__ void ldsm4(unsigned* r, unsigned addr) {
    asm volatile("ldmatrix.sync.aligned.m8n8.x4.shared.b16 {%0,%1,%2,%3}, [%4];"
        : "=r"(r[0]), "=r"(r[1]), "=r"(r[2]), "=r"(r[3]) : "r"(addr));
}
__device__ __forceinline__ void ldsm4t(unsigned* r, unsigned addr) {
    asm volatile("ldmatrix.sync.aligned.m8n8.x4.trans.shared.b16 {%0,%1,%2,%3}, [%4];"
        : "=r"(r[0]), "=r"(r[1]), "=r"(r[2]), "=r"(r[3]) : "r"(addr));
}

// ---- bf16 hi/lo split store of a float2 ----
__device__ __forceinline__ void split_store2(__nv_bfloat162* __restrict__ h,
                                             __nv_bfloat162* __restrict__ l,
                                             size_t idx, float2 v) {
    __nv_bfloat16 hx = __float2bfloat16(v.x);
    __nv_bfloat16 hy = __float2bfloat16(v.y);
    __nv_bfloat162 H, L;
    H.x = hx; H.y = hy;
    L.x = __float2bfloat16(v.x - __bfloat162float(hx));
    L.y = __float2bfloat16(v.y - __bfloat162float(hy));
    h[idx] = H; l[idx] = L;
}

// ---- complex helpers (plane kernels) ----
__device__ __forceinline__ float2 cadd(float2 a, float2 b){ return make_float2(a.x+b.x, a.y+b.y); }
__device__ __forceinline__ float2 csub(float2 a, float2 b){ return make_float2(a.x-b.x, a.y-b.y); }
__device__ __forceinline__ float2 cmul(float2 a, float2 t){ return make_float2(a.x*t.x - a.y*t.y, a.x*t.y + a.y*t.x); }

template<int S>
__device__ __forceinline__ float2 muliS(float2 a) {
    return (S > 0) ? make_float2(-a.y, a.x) : make_float2(a.y, -a.x);
}

template<int S>
__device__ __forceinline__ void dft8(float2 z[8]) {
    const float C = 0.70710678118654752f;
    const float sf = (S > 0) ? 1.f : -1.f;
    float2 t0 = cadd(z[0], z[4]), t1 = csub(z[0], z[4]);
    float2 t2 = cadd(z[2], z[6]), t3 = csub(z[2], z[6]);
    float2 E0 = cadd(t0, t2), E2 = csub(t0, t2);
    float2 t3r = muliS<S>(t3);
    float2 E1 = cadd(t1, t3r), E3 = csub(t1, t3r);
    float2 s0 = cadd(z[1], z[5]), s1 = csub(z[1], z[5]);
    float2 s2 = cadd(z[3], z[7]), s3 = csub(z[3], z[7]);
    float2 O0 = cadd(s0, s2), O2 = csub(s0, s2);
    float2 s3r = muliS<S>(s3);
    float2 O1 = cadd(s1, s3r), O3 = csub(s1, s3r);
    float2 W1O1 = make_float2(C*(O1.x - sf*O1.y), C*(O1.y + sf*O1.x));
    float2 W2O2 = muliS<S>(O2);
    float2 W3O3 = make_float2(C*(-O3.x - sf*O3.y), C*(-O3.y + sf*O3.x));
    z[0] = cadd(E0, O0);  z[4] = csub(E0, O0);
    z[1] = cadd(E1, W1O1); z[5] = csub(E1, W1O1);
    z[2] = cadd(E2, W2O2); z[6] = csub(E2, W2O2);
    z[3] = cadd(E3, W3O3); z[7] = csub(E3, W3O3);
}

// ============================================================
// Warp-cooperative 64-pt FFT phases.
// ============================================================
__device__ __forceinline__ void ifft_cols(const float2* __restrict__ y2, float2* __restrict__ u2,
                                          const float2* Ti, int tid)
{
    const int g = tid >> 3, sub = tid & 7;
    float2 z[8];
    if (g == 0) {
        #pragma unroll
        for (int n1 = 0; n1 < 8; n1++) {
            int m = 8*n1 + sub;
            float2 A = y2[33*m], B = y2[33*m + 32];
            z[n1] = make_float2(A.x - B.y, A.y + B.x);
        }
    } else {
        #pragma unroll
        for (int n1 = 0; n1 < 8; n1++) z[n1] = y2[33*(8*n1 + sub) + g];
    }
    dft8<1>(z);
    #pragma unroll
    for (int k1 = 1; k1 < 8; k1++) z[k1] = cmul(z[k1], Ti[k1*sub]);
    #pragma unroll
    for (int k1 = 0; k1 < 8; k1++) u2[33*(8*k1 + sub) + g] = z[k1];
    __syncwarp();
    #pragma unroll
    for (int j = 0; j < 8; j++) z[j] = u2[33*(8*sub + j) + g];
    dft8<1>(z);
    __syncwarp();
    #pragma unroll
    for (int k2 = 0; k2 < 8; k2++) u2[33*(sub + 8*k2) + g] = z[k2];
}

__device__ __forceinline__ void ifft_rows(float2* __restrict__ u2, const float2* Ti, int tid,
                                          float2 zres[8])
{
    const int r = tid >> 3, sub = tid & 7;
    float2* R = u2 + 66*r;
    float2 z[8];
    #pragma unroll
    for (int n1 = 0; n1 < 8; n1++) {
        int m = 8*n1 + sub;
        float2 A, B;
        if (m == 0)       { A = make_float2(R[0].x, 0.f);  B = make_float2(R[33].x, 0.f); }
        else if (m == 32) { A = make_float2(R[0].y, 0.f);  B = make_float2(R[33].y, 0.f); }
        else if (m < 32)  { A = R[m];                      B = R[33 + m]; }
        else {
            float2 Am = R[64 - m];      A = make_float2(Am.x, -Am.y);
            float2 Bm = R[33 + 64 - m]; B = make_float2(Bm.x, -Bm.y);
        }
        z[n1] = make_float2(A.x - B.y, A.y + B.x);
    }
    __syncwarp();
    dft8<1>(z);
    #pragma unroll
    for (int k1 = 1; k1 < 8; k1++) z[k1] = cmul(z[k1], Ti[k1*sub]);
    #pragma unroll
    for (int k1 = 0; k1 < 8; k1++) R[8*k1 + sub] = z[k1];
    __syncwarp();
    #pragma unroll
    for (int j = 0; j < 8; j++) z[j] = R[8*sub + j];
    dft8<1>(z);
    #pragma unroll
    for (int k2 = 0; k2 < 8; k2++) zres[k2] = z[k2];
}

__device__ __forceinline__ void fft_rows(const float* __restrict__ pl, int plstride,
                                         float2* __restrict__ u2, const float2* Tf, int tid)
{
    const int r = tid >> 3, sub = tid & 7;
    const float* p0 = pl + (2*r) * plstride;
    const float* p1 = pl + (2*r + 1) * plstride;
    float2* R = u2 + 66*r;
    float2 z[8];
    #pragma unroll
    for (int n1 = 0; n1 < 8; n1++) {
        int m = 8*n1 + sub;
        z[n1] = make_float2(p0[m], p1[m]);
    }
    dft8<-1>(z);
    #pragma unroll
    for (int k1 = 1; k1 < 8; k1++) z[k1] = cmul(z[k1], Tf[k1*sub]);
    #pragma unroll
    for (int k1 = 0; k1 < 8; k1++) R[8*k1 + sub] = z[k1];
    __syncwarp();
    #pragma unroll
    for (int j = 0; j < 8; j++) z[j] = R[8*sub + j];
    dft8<-1>(z);
    __syncwarp();
    #pragma unroll
    for (int k2 = 0; k2 < 8; k2++) R[sub + 8*k2] = z[k2];
    __syncwarp();
    float2 Zk[5], Zm[5];
    #pragma unroll
    for (int q = 0; q < 4; q++) { int k = sub + 8*q; Zk[q] = R[k]; Zm[q] = R[(64 - k) & 63]; }
    if (sub == 0) { Zk[4] = R[32]; Zm[4] = R[32]; }
    __syncwarp();
    #pragma unroll
    for (int q = 0; q < 4; q++) {
        int k = sub + 8*q;
        R[k]      = make_float2(0.5f*(Zk[q].x + Zm[q].x), 0.5f*(Zk[q].y - Zm[q].y));
        R[33 + k] = make_float2(0.5f*(Zk[q].y + Zm[q].y), 0.5f*(Zm[q].x - Zk[q].x));
    }
    if (sub == 0) {
        R[32] = make_float2(Zk[4].x, 0.f);
        R[65] = make_float2(Zk[4].y, 0.f);
    }
}

// Forward FFT along h; OUT=0: fp32 float2 to ob; OUT=1: bf16 hi/lo split to obh/obl.
template<int OUT>
__device__ __forceinline__ void fft_cols_store(float2* __restrict__ u2, const float2* Tf, int tid,
                                               float2* __restrict__ ob,
                                               __nv_bfloat162* __restrict__ obh,
                                               __nv_bfloat162* __restrict__ obl,
                                               float scale)
{
    const int g = tid >> 3, sub = tid & 7;
    float2 z[8];
    if (g == 0) {
        #pragma unroll
        for (int n1 = 0; n1 < 8; n1++) {
            int h = 8*n1 + sub;
            z[n1] = make_float2(u2[33*h].x, u2[33*h + 32].x);
        }
    } else {
        #pragma unroll
        for (int n1 = 0; n1 < 8; n1++) z[n1] = u2[33*(8*n1 + sub) + g];
    }
    dft8<-1>(z);
    #pragma unroll
    for (int k1 = 1; k1 < 8; k1++) z[k1] = cmul(z[k1], Tf[k1*sub]);
    #pragma unroll
    for (int k1 = 0; k1 < 8; k1++) u2[33*(8*k1 + sub) + g] = z[k1];
    __syncwarp();
    #pragma unroll
    for (int j = 0; j < 8; j++) z[j] = u2[33*(8*sub + j) + g];
    dft8<-1>(z);
    __syncwarp();
    if (g != 0) {
        #pragma unroll
        for (int k2 = 0; k2 < 8; k2++) {
            int kh = sub + 8*k2;
            float2 v = make_float2(z[k2].x * scale, z[k2].y * scale);
            if (OUT == 0) ob[kh*33 + g] = v;
            else          split_store2(obh, obl, kh*33 + g, v);
        }
    } else {
        #pragma unroll
        for (int k2 = 0; k2 < 8; k2++) u2[33*(sub + 8*k2)] = z[k2];
    }
    __syncwarp();
    if (g == 0) {
        #pragma unroll
        for (int j = 0; j < 8; j++) {
            int k = 8*sub + j;
            float2 Zk = u2[33*k];
            float2 Zm = u2[33*((64 - k) & 63)];
            float2 v0 = make_float2(0.5f*(Zk.x + Zm.x)*scale, 0.5f*(Zk.y - Zm.y)*scale);
            float2 v32 = make_float2(0.5f*(Zk.y + Zm.y)*scale, 0.5f*(Zm.x - Zk.x)*scale);
            if (OUT == 0) {
                ob[k*33 + 0]  = v0;
                ob[k*33 + 32] = v32;
            } else {
                split_store2(obh, obl, k*33 + 0,  v0);
                split_store2(obh, obl, k*33 + 32, v32);
            }
        }
    }
}

// ============================================================
// fp32 -> (hi, lo) bf16 split, grid-strided, float4 vectorized.
// ============================================================
__global__ __launch_bounds__(256) void split_kernel(
    const float* __restrict__ in,
    __nv_bfloat16* __restrict__ hi, __nv_bfloat16* __restrict__ lo, int n4)
{
    int i = blockIdx.x * 256 + threadIdx.x;
    int stride = gridDim.x * 256;
    for (; i < n4; i += stride) {
        float4 v = ((const float4*)in)[i];
        split_store2((__nv_bfloat162*)hi, (__nv_bfloat162*)lo, 2*i,     make_float2(v.x, v.y));
        split_store2((__nv_bfloat162*)hi, (__nv_bfloat162*)lo, 2*i + 1, make_float2(v.z, v.w));
    }
}

// ============================================================
// Split-bf16 tensor-core GEMM (R9, unchanged).
// MODE 0: plain. MODE 1: bias+SiLU. MODE 3: bias.
// ============================================================
#define BKt 16
#define APAD 24
#define BPAD 136

template<int MODE>
__global__ __launch_bounds__(256) void mma_gemm(
    const __nv_bfloat16* __restrict__ Ah, const __nv_bfloat16* __restrict__ Al,
    const __nv_bfloat16* __restrict__ Bh, const __nv_bfloat16* __restrict__ Bl,
    const float* __restrict__ bias,
    float* __restrict__ C,
    int M, int Ntot, int K)
{
    __shared__ __align__(16) __nv_bfloat16 sAh[2][128][APAD];
    __shared__ __align__(16) __nv_bfloat16 sAl[2][128][APAD];
    __shared__ __align__(16) __nv_bfloat16 sBh[2][BKt][BPAD];
    __shared__ __align__(16) __nv_bfloat16 sBl[2][BKt][BPAD];

    const int bx = blockIdx.x, by = blockIdx.y, bz = blockIdx.z;
    const int n0 = bx * 128, m0 = by * 128;
    const __nv_bfloat16* Bhp = Bh + (size_t)bz * K * Ntot;
    const __nv_bfloat16* Blp = Bl + (size_t)bz * K * Ntot;
    float* Cp = C + (size_t)bz * M * Ntot;

    const int tid  = threadIdx.x;
    const int lane = tid & 31;
    const int wid  = tid >> 5;
    const int wm   = wid >> 2;
    const int wn   = wid & 3;

    const unsigned uAh = (unsigned)__cvta_generic_to_shared(&sAh[0][0][0]);
    const unsigned uAl = (unsigned)__cvta_generic_to_shared(&sAl[0][0][0]);
    const unsigned uBh = (unsigned)__cvta_generic_to_shared(&sBh[0][0][0]);
    const unsigned uBl = (unsigned)__cvta_generic_to_shared(&sBl[0][0][0]);

    const int arow = tid >> 1;
    const int achk = (tid & 1) * 8;
    const int brow = tid >> 4;
    const int bchk = (tid & 15) * 8;

    auto loadTiles = [&](int k0, int bufI) {
        cp_async16(uAh + (unsigned)(((bufI*128 + arow)*APAD + achk)*2),
                   Ah + (size_t)(m0 + arow) * K + k0 + achk);
        cp_async16(uAl + (unsigned)(((bufI*128 + arow)*APAD + achk)*2),
                   Al + (size_t)(m0 + arow) * K + k0 + achk);
        cp_async16(uBh + (unsigned)(((bufI*BKt + brow)*BPAD + bchk)*2),
                   Bhp + (size_t)(k0 + brow) * Ntot + n0 + bchk);
        cp_async16(uBl + (unsigned)(((bufI*BKt + brow)*BPAD + bchk)*2),
                   Blp + (size_t)(k0 + brow) * Ntot + n0 + bchk);
        cp_commit();
    };

    float acc[4][4][4];
    #pragma unroll
    for (int i = 0; i < 4; i++)
        #pragma unroll
        for (int j = 0; j < 4; j++)
            #pragma unroll
            for (int q = 0; q < 4; q++) acc[i][j][q] = 0.f;

    const unsigned aOff = (unsigned)(((lane & 15) * APAD + (lane >> 4) * 8) * 2);
    const unsigned bOff = (unsigned)(((lane & 15) * BPAD + 32*wn + (lane >> 4) * 8) * 2);

    const int nStages = K / BKt;
    loadTiles(0, 0);
    cp_wait0();
    __syncthreads();

    for (int s = 0; s < nStages; s++) {
        const int buf = s & 1, nxt = buf ^ 1;
        const bool more = (s + 1 < nStages);
        if (more) loadTiles((s + 1) * BKt, nxt);

        unsigned aH[4][4], aL[4][4], bH[2][4], bL[2][4];
        #pragma unroll
        for (int mf = 0; mf < 4; mf++) {
            unsigned rowbase = (unsigned)((buf*128 + 64*wm + 16*mf) * APAD * 2);
            ldsm4(aH[mf], uAh + rowbase + aOff);
            ldsm4(aL[mf], uAl + rowbase + aOff);
        }
        #pragma unroll
        for (int np = 0; np < 2; np++) {
            unsigned cb = (unsigned)((buf*BKt*BPAD + 16*np) * 2);
            ldsm4t(bH[np], uBh + cb + bOff);
            ldsm4t(bL[np], uBl + cb + bOff);
        }
        #pragma unroll
        for (int mf = 0; mf < 4; mf++)
            #pragma unroll
            for (int nf = 0; nf < 4; nf++) {
                const unsigned* bh = &bH[nf >> 1][2*(nf & 1)];
                const unsigned* bl = &bL[nf >> 1][2*(nf & 1)];
                mma16816(acc[mf][nf], aH[mf], bh);
                mma16816(acc[mf][nf], aH[mf], bl);
                mma16816(acc[mf][nf], aL[mf], bh);
            }
        if (more) cp_wait0();
        __syncthreads();
    }

    const int rbase = m0 + 64*wm + (lane >> 2);
    const int cbase = n0 + 32*wn + 2*(lane & 3);
    #pragma unroll
    for (int mf = 0; mf < 4; mf++) {
        #pragma unroll
        for (int half = 0; half < 2; half++) {
            int m = rbase + 16*mf + 8*half;
            float bv = (MODE >= 1) ? bias[m] : 0.f;
            #pragma unroll
            for (int nf = 0; nf < 4; nf++) {
                int c = cbase + 8*nf;
                float vx = acc[mf][nf][2*half + 0] + bv;
                float vy = acc[mf][nf][2*half + 1] + bv;
                if (MODE == 1) {
                    vx = vx / (1.f + __expf(-vx));
                    vy = vy / (1.f + __expf(-vy));
                }
                *(float2*)&Cp[(size_t)m * Ntot + c] = make_float2(vx, vy);
            }
        }
    }
}

// ============================================================
// Forward rfft2 of one 64x64 real plane -> bf16 hi/lo split output.
// ============================================================
__global__ __launch_bounds__(256) void fft2_fwd_bf16_kernel(
    const float* __restrict__ in,
    __nv_bfloat162* __restrict__ outh, __nv_bfloat162* __restrict__ outl,
    float scale)
{
    __shared__ float  sp[HH * 65];
    __shared__ float2 u2[FREQ];
    __shared__ float2 Tf[64];
    const int tid = threadIdx.x;
    const float* p = in + (size_t)blockIdx.x * NPIX;

    if (tid < 64) {
        float s, c; sincosf(TWO_PI_OVER_64 * (float)tid, &s, &c);
        Tf[tid] = make_float2(c, -s);
    }
    for (int i = tid; i < NPIX; i += 256) sp[(i >> 6)*65 + (i & 63)] = p[i];
    __syncthreads();

    fft_rows(sp, 65, u2, Tf, tid);
    __syncthreads();
    fft_cols_store<1>(u2, Tf, tid, nullptr,
                      outh + (size_t)blockIdx.x * FREQ,
                      outl + (size_t)blockIdx.x * FREQ, scale);
}

// ============================================================
// Fused middle (R7/R9, fp32 output to Xc).
// ============================================================
__global__ __launch_bounds__(256) void mid_fused_kernel(
    const float2* __restrict__ qc, float2* __restrict__ outc)
{
    __shared__ float2 y2[FREQ];
    __shared__ float2 u2[FREQ];
    __shared__ float2 Tf[64];
    __shared__ float2 Ti[64];
    __shared__ float  red[256];
    float* pl = (float*)y2;

    const int tid = threadIdx.x;
    const int plane = blockIdx.x;
    const int b  = plane >> 9;
    const int ch = plane & 511;
    const float2* qp = qc + ((size_t)b * CH3 + ch) * FREQ;
    const float2* kp = qc + ((size_t)b * CH3 + 512 + ch) * FREQ;

    if (tid < 64) {
        float s, c; sincosf(TWO_PI_OVER_64 * (float)tid, &s, &c);
        Tf[tid] = make_float2(c, -s);
        Ti[tid] = make_float2(c,  s);
    }
    for (int i = tid; i < FREQ; i += 256) {
        float2 q = qp[i], k = kp[i];
        y2[i] = make_float2(q.x*k.x + q.y*k.y, q.x*k.y - q.y*k.x);
    }
    __syncthreads();

    ifft_cols(y2, u2, Ti, tid);
    __syncthreads();

    {
        float2 zres[8];
        ifft_rows(u2, Ti, tid, zres);
        const int r = tid >> 3, sub = tid & 7;
        const float s = 1.0f / 64.0f;
        #pragma unroll
        for (int k2 = 0; k2 < 8; k2++) {
            int w = sub + 8*k2;
            pl[(2*r)*65 + w]     = zres[k2].x * s;
            pl[(2*r + 1)*65 + w] = zres[k2].y * s;
        }
    }
    __syncthreads();

    {
        float m = -3.4e38f;
        for (int i = tid; i < NPIX; i += 256) {
            float v = pl[(i >> 6)*65 + (i & 63)];
            m = fmaxf(m, v);
        }
        red[tid] = m; __syncthreads();
        for (int s = 128; s > 0; s >>= 1) { if (tid < s) red[tid] = fmaxf(red[tid], red[tid + s]); __syncthreads(); }
        const float M = red[0];
        __syncthreads();
        float sum = 0.f;
        for (int i = tid; i < NPIX; i += 256) {
            int a = (i >> 6)*65 + (i & 63);
            float e = __expf(pl[a] - M);
            pl[a] = e; sum += e;
        }
        red[tid] = sum; __syncthreads();
        for (int s = 128; s > 0; s >>= 1) { if (tid < s) red[tid] += red[tid + s]; __syncthreads(); }
        const float inv = 1.f / red[0];
        __syncthreads();
        for (int i = tid; i < NPIX; i += 256) {
            int a = (i >> 6)*65 + (i & 63);
            pl[a] *= inv;
        }
    }
    __syncthreads();

    fft_rows(pl, 65, u2, Tf, tid);
    __syncthreads();
    fft_cols_store<0>(u2, Tf, tid, outc + (size_t)plane * FREQ, nullptr, nullptr, 1.0f);
}

// ============================================================
// Fused: Y = conj(a)*b, irfft2(Y), gate-multiply, bf16 hi/lo out.
// ============================================================
__global__ __launch_bounds__(256) void prod_ifft2_gate_bf16_kernel(
    const float2* __restrict__ ac, int aCPB, int aOff,
    const float2* __restrict__ bc, int bCPB, int bOff,
    const float* __restrict__ gate,
    __nv_bfloat162* __restrict__ outh, __nv_bfloat162* __restrict__ outl,
    float scale)
{
    __shared__ float2 y2[FREQ];     // reused as staging plane (stride 65)
    __shared__ float2 u2[FREQ];
    __shared__ float2 Ti[64];
    float* pl = (float*)y2;
    const int tid = threadIdx.x;
    const int plane = blockIdx.x;
    const int b  = plane >> 9;
    const int ch = plane & 511;
    const float2* ap = ac + ((size_t)b * aCPB + aOff + ch) * FREQ;
    const float2* bp = bc + ((size_t)b * bCPB + bOff + ch) * FREQ;

    if (tid < 64) {
        float s, c; sincosf(TWO_PI_OVER_64 * (float)tid, &s, &c);
        Ti[tid] = make_float2(c, s);
    }
    for (int i = tid; i < FREQ; i += 256) {
        float2 a = ap[i], bb = bp[i];
        y2[i] = make_float2(a.x*bb.x + a.y*bb.y, a.x*bb.y - a.y*bb.x);
    }
    __syncthreads();

    ifft_cols(y2, u2, Ti, tid);
    __syncthreads();

    {
        float2 zres[8];
        ifft_rows(u2, Ti, tid, zres);
        __syncthreads();   // y2 fully consumed (ifft_cols read it) before pl overwrite
        const int r = tid >> 3, sub = tid & 7;
        #pragma unroll
        for (int k2 = 0; k2 < 8; k2++) {
            int w = sub + 8*k2;
            pl[(2*r)*65 + w]     = zres[k2].x * scale;
            pl[(2*r + 1)*65 + w] = zres[k2].y * scale;
        }
    }
    __syncthreads();

    // gate-multiply + split + coalesced bf162 stores
    {
        const float2* gp2 = (const float2*)(gate + (size_t)plane * NPIX);
        __nv_bfloat162* oh = outh + (size_t)plane * (NPIX/2);
        __nv_bfloat162* ol = outl + (size_t)plane * (NPIX/2);
        for (int i = tid; i < NPIX/2; i += 256) {
            int row = (2*i) >> 6, col = (2*i) & 63;
            float2 g = gp2[i];
            float2 v = make_float2(pl[row*65 + col] * g.x, pl[row*65 + col + 1] * g.y);
            split_store2(oh, ol, i, v);
        }
    }
}

// ============================================================
extern "C" void kernel_launch(void* const* d_in, const int* in_sizes, int n_in,
                              void* d_out, int out_size)
{
    const float* x      = (const float*)d_in[0];
    const float* w_qkv  = (const float*)d_in[1];
    const float* w_gate = (const float*)d_in[2];
    const float* b_gate = (const float*)d_in[3];
    const float* w_proj = (const float*)d_in[4];
    const float* b_proj = (const float*)d_in[5];
    float* out = (float*)d_out;

    float2 *Xc, *Qc;
    float  *t;
    __nv_bfloat16 *wh, *wl, *bh, *bl;
    cudaGetSymbolAddress((void**)&Xc,   g_Xc);
    cudaGetSymbolAddress((void**)&Qc,   g_Qc);
    cudaGetSymbolAddress((void**)&t,    g_t);
    cudaGetSymbolAddress((void**)&wh,   g_wh);
    cudaGetSymbolAddress((void**)&wl,   g_wl);
    cudaGetSymbolAddress((void**)&bh,   g_bh);
    cudaGetSymbolAddress((void**)&bl,   g_bl);

    const float inv64 = 1.0f / 64.0f;
    const int SPLIT_BLKS = 1184;

    // 1. split gate weight + x, then gate GEMM: t = SiLU(Wg*x + bg)
    split_kernel<<<SPLIT_BLKS, 256>>>(w_gate, wh, wl, (CH*CH)/4);
    split_kernel<<<SPLIT_BLKS, 256>>>(x, bh, bl, (BATCH*CH*NPIX)/4);
    {
        dim3 g(NPIX / 128, CH / 128, BATCH);
        mma_gemm<1><<<g, 256>>>(wh, wl, bh, bl, b_gate, t, CH, NPIX, CH);
    }
    // 2. X = rfft2(x), ortho -> DIRECT bf16 hi/lo into GEMM B buffers
    fft2_fwd_bf16_kernel<<<PLANES, 256>>>(x, (__nv_bfloat162*)bh, (__nv_bfloat162*)bl, inv64);
    // 3. split qkv weight, then QKV GEMM (complex interleaved, Ntot=4224)
    split_kernel<<<SPLIT_BLKS, 256>>>(w_qkv, wh, wl, (CH3*CH)/4);
    {
        dim3 g(NQKV / 128, CH3 / 128, BATCH);
        mma_gemm<0><<<g, 256>>>(wh, wl, bh, bl, nullptr, (float*)Qc, CH3, NQKV, CH);
    }
    // 4-6. fused middle: conj(q)*k -> irfft2 -> softmax -> rfft2 -> Xc
    mid_fused_kernel<<<PLANES, 256>>>(Qc, Xc);
    // 7. y = irfft2(conj(A)*v) * t -> DIRECT bf16 hi/lo into GEMM B buffers
    prod_ifft2_gate_bf16_kernel<<<PLANES, 256>>>(Xc, CH, 0,
                                                 Qc, CH3, 1024,
                                                 t, (__nv_bfloat162*)bh, (__nv_bfloat162*)bl,
                                                 inv64);
    // 8. split proj weight, then proj GEMM: out = Wp*y + bp
    split_kernel<<<SPLIT_BLKS, 256>>>(w_proj, wh, wl, (CH*CH)/4);
    {
        dim3 g(NPIX / 128, CH / 128, BATCH);
        mma_gemm<3><<<g, 256>>>(wh, wl, bh, bl, b_proj, out, CH, NPIX, CH);
    }
}

// round 11
// speedup vs baseline: 2.6379x; 1.0464x over previous
#include <cuda_runtime.h>
#include <cuda_bf16.h>
#include <cstdint>
#include <math.h>

#define BATCH 8
#define CH    512
#define CH3   1536
#define HH    64
#define NPIX  4096          // 64*64
#define WR    33            // rfft width 64/2+1
#define FREQ  2112          // 64*33
#define PLANES (BATCH*CH)   // 4096
#define NQKV  4224          // 2*FREQ floats per plane-row (interleaved complex)

// ---- static scratch (no allocations allowed) ----
__device__ float2 g_Xc[BATCH*CH*FREQ];    // interleaved {re,im} (mid output)
__device__ float2 g_Qc[BATCH*CH3*FREQ];   // interleaved {re,im}
__device__ float  g_t[BATCH*CH*NPIX];
// bf16 split buffers
__device__ __nv_bfloat16 g_wh[CH3*CH];
__device__ __nv_bfloat16 g_wl[CH3*CH];
__device__ __nv_bfloat16 g_bh[BATCH*CH*NQKV];    // x-split / y-split
__device__ __nv_bfloat16 g_bl[BATCH*CH*NQKV];
__device__ __nv_bfloat16 g_b2h[BATCH*CH*NQKV];   // spectrum split
__device__ __nv_bfloat16 g_b2l[BATCH*CH*NQKV];

#define TWO_PI_OVER_64 0.09817477042468103f

// ---- cp.async helpers ----
__device__ __forceinline__ void cp_async16(unsigned int saddr, const void* g) {
    asm volatile("cp.async.cg.shared.global [%0], [%1], 16;\n" :: "r"(saddr), "l"(g));
}
__device__ __forceinline__ void cp_commit() { asm volatile("cp.async.commit_group;\n"); }
__device__ __forceinline__ void cp_wait0()  { asm volatile("cp.async.wait_group 0;\n" ::: "memory"); }

// ---- tensor-core helpers ----
__device__ __forceinline__ void mma16816(float* d, const unsigned* a, const unsigned* b) {
    asm volatile("mma.sync.aligned.m16n8k16.row.col.f32.bf16.bf16.f32 "
        "{%0,%1,%2,%3}, {%4,%5,%6,%7}, {%8,%9}, {%0,%1,%2,%3};"
        : "+f"(d[0]), "+f"(d[1]), "+f"(d[2]), "+f"(d[3])
        : "r"(a[0]), "r"(a[1]), "r"(a[2]), "r"(a[3]), "r"(b[0]), "r"(b[1]));
}
__device__ __forceinline__ void ldsm4(unsigned* r, unsigned addr) {
    asm volatile("ldmatrix.sync.aligned.m8n8.x4.shared.b16 {%0,%1,%2,%3}, [%4];"
        : "=r"(r[0]), "=r"(r[1]), "=r"(r[2]), "=r"(r[3]) : "r"(addr));
}
__device__ __forceinline__ void ldsm4t(unsigned* r, unsigned addr) {
    asm volatile("ldmatrix.sync.aligned.m8n8.x4.trans.shared.b16 {%0,%1,%2,%3}, [%4];"
        : "=r"(r[0]), "=r"(r[1]), "=r"(r[2]), "=r"(r[3]) : "r"(addr));
}

// ---- bf16 hi/lo split store of a float2 ----
__device__ __forceinline__ void split_store2(__nv_bfloat162* __restrict__ h,
                                             __nv_bfloat162* __restrict__ l,
                                             size_t idx, float2 v) {
    __nv_bfloat16 hx = __float2bfloat16(v.x);
    __nv_bfloat16 hy = __float2bfloat16(v.y);
    __nv_bfloat162 H, L;
    H.x = hx; H.y = hy;
    L.x = __float2bfloat16(v.x - __bfloat162float(hx));
    L.y = __float2bfloat16(v.y - __bfloat162float(hy));
    h[idx] = H; l[idx] = L;
}

// ---- complex helpers ----
__device__ __forceinline__ float2 cadd(float2 a, float2 b){ return make_float2(a.x+b.x, a.y+b.y); }
__device__ __forceinline__ float2 csub(float2 a, float2 b){ return make_float2(a.x-b.x, a.y-b.y); }
__device__ __forceinline__ float2 cmul(float2 a, float2 t){ return make_float2(a.x*t.x - a.y*t.y, a.x*t.y + a.y*t.x); }

template<int S>
__device__ __forceinline__ float2 muliS(float2 a) {
    return (S > 0) ? make_float2(-a.y, a.x) : make_float2(a.y, -a.x);
}

template<int S>
__device__ __forceinline__ void dft8(float2 z[8]) {
    const float C = 0.70710678118654752f;
    const float sf = (S > 0) ? 1.f : -1.f;
    float2 t0 = cadd(z[0], z[4]), t1 = csub(z[0], z[4]);
    float2 t2 = cadd(z[2], z[6]), t3 = csub(z[2], z[6]);
    float2 E0 = cadd(t0, t2), E2 = csub(t0, t2);
    float2 t3r = muliS<S>(t3);
    float2 E1 = cadd(t1, t3r), E3 = csub(t1, t3r);
    float2 s0 = cadd(z[1], z[5]), s1 = csub(z[1], z[5]);
    float2 s2 = cadd(z[3], z[7]), s3 = csub(z[3], z[7]);
    float2 O0 = cadd(s0, s2), O2 = csub(s0, s2);
    float2 s3r = muliS<S>(s3);
    float2 O1 = cadd(s1, s3r), O3 = csub(s1, s3r);
    float2 W1O1 = make_float2(C*(O1.x - sf*O1.y), C*(O1.y + sf*O1.x));
    float2 W2O2 = muliS<S>(O2);
    float2 W3O3 = make_float2(C*(-O3.x - sf*O3.y), C*(-O3.y + sf*O3.x));
    z[0] = cadd(E0, O0);  z[4] = csub(E0, O0);
    z[1] = cadd(E1, W1O1); z[5] = csub(E1, W1O1);
    z[2] = cadd(E2, W2O2); z[6] = csub(E2, W2O2);
    z[3] = cadd(E3, W3O3); z[7] = csub(E3, W3O3);
}

// ============================================================
// Warp-cooperative 64-pt FFT phases.
// ============================================================
__device__ __forceinline__ void ifft_cols(const float2* __restrict__ y2, float2* __restrict__ u2,
                                          const float2* Ti, int tid)
{
    const int g = tid >> 3, sub = tid & 7;
    float2 z[8];
    if (g == 0) {
        #pragma unroll
        for (int n1 = 0; n1 < 8; n1++) {
            int m = 8*n1 + sub;
            float2 A = y2[33*m], B = y2[33*m + 32];
            z[n1] = make_float2(A.x - B.y, A.y + B.x);
        }
    } else {
        #pragma unroll
        for (int n1 = 0; n1 < 8; n1++) z[n1] = y2[33*(8*n1 + sub) + g];
    }
    dft8<1>(z);
    #pragma unroll
    for (int k1 = 1; k1 < 8; k1++) z[k1] = cmul(z[k1], Ti[k1*sub]);
    #pragma unroll
    for (int k1 = 0; k1 < 8; k1++) u2[33*(8*k1 + sub) + g] = z[k1];
    __syncwarp();
    #pragma unroll
    for (int j = 0; j < 8; j++) z[j] = u2[33*(8*sub + j) + g];
    dft8<1>(z);
    __syncwarp();
    #pragma unroll
    for (int k2 = 0; k2 < 8; k2++) u2[33*(sub + 8*k2) + g] = z[k2];
}

__device__ __forceinline__ void ifft_rows(float2* __restrict__ u2, const float2* Ti, int tid,
                                          float2 zres[8])
{
    const int r = tid >> 3, sub = tid & 7;
    float2* R = u2 + 66*r;
    float2 z[8];
    #pragma unroll
    for (int n1 = 0; n1 < 8; n1++) {
        int m = 8*n1 + sub;
        float2 A, B;
        if (m == 0)       { A = make_float2(R[0].x, 0.f);  B = make_float2(R[33].x, 0.f); }
        else if (m == 32) { A = make_float2(R[0].y, 0.f);  B = make_float2(R[33].y, 0.f); }
        else if (m < 32)  { A = R[m];                      B = R[33 + m]; }
        else {
            float2 Am = R[64 - m];      A = make_float2(Am.x, -Am.y);
            float2 Bm = R[33 + 64 - m]; B = make_float2(Bm.x, -Bm.y);
        }
        z[n1] = make_float2(A.x - B.y, A.y + B.x);
    }
    __syncwarp();
    dft8<1>(z);
    #pragma unroll
    for (int k1 = 1; k1 < 8; k1++) z[k1] = cmul(z[k1], Ti[k1*sub]);
    #pragma unroll
    for (int k1 = 0; k1 < 8; k1++) R[8*k1 + sub] = z[k1];
    __syncwarp();
    #pragma unroll
    for (int j = 0; j < 8; j++) z[j] = R[8*sub + j];
    dft8<1>(z);
    #pragma unroll
    for (int k2 = 0; k2 < 8; k2++) zres[k2] = z[k2];
}

__device__ __forceinline__ void fft_rows(const float* __restrict__ pl, int plstride,
                                         float2* __restrict__ u2, const float2* Tf, int tid)
{
    const int r = tid >> 3, sub = tid & 7;
    const float* p0 = pl + (2*r) * plstride;
    const float* p1 = pl + (2*r + 1) * plstride;
    float2* R = u2 + 66*r;
    float2 z[8];
    #pragma unroll
    for (int n1 = 0; n1 < 8; n1++) {
        int m = 8*n1 + sub;
        z[n1] = make_float2(p0[m], p1[m]);
    }
    dft8<-1>(z);
    #pragma unroll
    for (int k1 = 1; k1 < 8; k1++) z[k1] = cmul(z[k1], Tf[k1*sub]);
    #pragma unroll
    for (int k1 = 0; k1 < 8; k1++) R[8*k1 + sub] = z[k1];
    __syncwarp();
    #pragma unroll
    for (int j = 0; j < 8; j++) z[j] = R[8*sub + j];
    dft8<-1>(z);
    __syncwarp();
    #pragma unroll
    for (int k2 = 0; k2 < 8; k2++) R[sub + 8*k2] = z[k2];
    __syncwarp();
    float2 Zk[5], Zm[5];
    #pragma unroll
    for (int q = 0; q < 4; q++) { int k = sub + 8*q; Zk[q] = R[k]; Zm[q] = R[(64 - k) & 63]; }
    if (sub == 0) { Zk[4] = R[32]; Zm[4] = R[32]; }
    __syncwarp();
    #pragma unroll
    for (int q = 0; q < 4; q++) {
        int k = sub + 8*q;
        R[k]      = make_float2(0.5f*(Zk[q].x + Zm[q].x), 0.5f*(Zk[q].y - Zm[q].y));
        R[33 + k] = make_float2(0.5f*(Zk[q].y + Zm[q].y), 0.5f*(Zm[q].x - Zk[q].x));
    }
    if (sub == 0) {
        R[32] = make_float2(Zk[4].x, 0.f);
        R[65] = make_float2(Zk[4].y, 0.f);
    }
}

// Forward FFT along h; finishes IN SMEM: u2[kh*33 + k] holds the scaled
// final spectrum (row-major). pc = 64-entry float2 side buffer.
__device__ __forceinline__ void fft_cols_finish(float2* __restrict__ u2, float2* __restrict__ pc,
                                                const float2* Tf, int tid, float scale)
{
    const int g = tid >> 3, sub = tid & 7;
    float2 z[8];
    if (g == 0) {
        #pragma unroll
        for (int n1 = 0; n1 < 8; n1++) {
            int h = 8*n1 + sub;
            z[n1] = make_float2(u2[33*h].x, u2[33*h + 32].x);
        }
    } else {
        #pragma unroll
        for (int n1 = 0; n1 < 8; n1++) z[n1] = u2[33*(8*n1 + sub) + g];
    }
    dft8<-1>(z);
    #pragma unroll
    for (int k1 = 1; k1 < 8; k1++) z[k1] = cmul(z[k1], Tf[k1*sub]);
    #pragma unroll
    for (int k1 = 0; k1 < 8; k1++) u2[33*(8*k1 + sub) + g] = z[k1];
    __syncwarp();
    #pragma unroll
    for (int j = 0; j < 8; j++) z[j] = u2[33*(8*sub + j) + g];
    dft8<-1>(z);
    __syncwarp();
    if (g != 0) {
        #pragma unroll
        for (int k2 = 0; k2 < 8; k2++) {
            int kh = sub + 8*k2;
            u2[kh*33 + g] = make_float2(z[k2].x * scale, z[k2].y * scale);
        }
    } else {
        #pragma unroll
        for (int k2 = 0; k2 < 8; k2++) pc[sub + 8*k2] = z[k2];   // packed col to side buf
    }
    __syncwarp();
    if (g == 0) {
        #pragma unroll
        for (int j = 0; j < 8; j++) {
            int k = 8*sub + j;
            float2 Zk = pc[k];
            float2 Zm = pc[(64 - k) & 63];
            u2[k*33 + 0]  = make_float2(0.5f*(Zk.x + Zm.x)*scale, 0.5f*(Zk.y - Zm.y)*scale);
            u2[k*33 + 32] = make_float2(0.5f*(Zk.y + Zm.y)*scale, 0.5f*(Zm.x - Zk.x)*scale);
        }
    }
}

// ============================================================
// fp32 -> (hi, lo) bf16 split (weights only now).
// ============================================================
__global__ __launch_bounds__(256) void split_kernel(
    const float* __restrict__ in,
    __nv_bfloat16* __restrict__ hi, __nv_bfloat16* __restrict__ lo, int n4)
{
    int i = blockIdx.x * 256 + threadIdx.x;
    int stride = gridDim.x * 256;
    for (; i < n4; i += stride) {
        float4 v = ((const float4*)in)[i];
        split_store2((__nv_bfloat162*)hi, (__nv_bfloat162*)lo, 2*i,     make_float2(v.x, v.y));
        split_store2((__nv_bfloat162*)hi, (__nv_bfloat162*)lo, 2*i + 1, make_float2(v.z, v.w));
    }
}

// ============================================================
// Split-bf16 tensor-core GEMM (R9, unchanged).
// ============================================================
#define BKt 16
#define APAD 24
#define BPAD 136

template<int MODE>
__global__ __launch_bounds__(256) void mma_gemm(
    const __nv_bfloat16* __restrict__ Ah, const __nv_bfloat16* __restrict__ Al,
    const __nv_bfloat16* __restrict__ Bh, const __nv_bfloat16* __restrict__ Bl,
    const float* __restrict__ bias,
    float* __restrict__ C,
    int M, int Ntot, int K)
{
    __shared__ __align__(16) __nv_bfloat16 sAh[2][128][APAD];
    __shared__ __align__(16) __nv_bfloat16 sAl[2][128][APAD];
    __shared__ __align__(16) __nv_bfloat16 sBh[2][BKt][BPAD];
    __shared__ __align__(16) __nv_bfloat16 sBl[2][BKt][BPAD];

    const int bx = blockIdx.x, by = blockIdx.y, bz = blockIdx.z;
    const int n0 = bx * 128, m0 = by * 128;
    const __nv_bfloat16* Bhp = Bh + (size_t)bz * K * Ntot;
    const __nv_bfloat16* Blp = Bl + (size_t)bz * K * Ntot;
    float* Cp = C + (size_t)bz * M * Ntot;

    const int tid  = threadIdx.x;
    const int lane = tid & 31;
    const int wid  = tid >> 5;
    const int wm   = wid >> 2;
    const int wn   = wid & 3;

    const unsigned uAh = (unsigned)__cvta_generic_to_shared(&sAh[0][0][0]);
    const unsigned uAl = (unsigned)__cvta_generic_to_shared(&sAl[0][0][0]);
    const unsigned uBh = (unsigned)__cvta_generic_to_shared(&sBh[0][0][0]);
    const unsigned uBl = (unsigned)__cvta_generic_to_shared(&sBl[0][0][0]);

    const int arow = tid >> 1;
    const int achk = (tid & 1) * 8;
    const int brow = tid >> 4;
    const int bchk = (tid & 15) * 8;

    auto loadTiles = [&](int k0, int bufI) {
        cp_async16(uAh + (unsigned)(((bufI*128 + arow)*APAD + achk)*2),
                   Ah + (size_t)(m0 + arow) * K + k0 + achk);
        cp_async16(uAl + (unsigned)(((bufI*128 + arow)*APAD + achk)*2),
                   Al + (size_t)(m0 + arow) * K + k0 + achk);
        cp_async16(uBh + (unsigned)(((bufI*BKt + brow)*BPAD + bchk)*2),
                   Bhp + (size_t)(k0 + brow) * Ntot + n0 + bchk);
        cp_async16(uBl + (unsigned)(((bufI*BKt + brow)*BPAD + bchk)*2),
                   Blp + (size_t)(k0 + brow) * Ntot + n0 + bchk);
        cp_commit();
    };

    float acc[4][4][4];
    #pragma unroll
    for (int i = 0; i < 4; i++)
        #pragma unroll
        for (int j = 0; j < 4; j++)
            #pragma unroll
            for (int q = 0; q < 4; q++) acc[i][j][q] = 0.f;

    const unsigned aOff = (unsigned)(((lane & 15) * APAD + (lane >> 4) * 8) * 2);
    const unsigned bOff = (unsigned)(((lane & 15) * BPAD + 32*wn + (lane >> 4) * 8) * 2);

    const int nStages = K / BKt;
    loadTiles(0, 0);
    cp_wait0();
    __syncthreads();

    for (int s = 0; s < nStages; s++) {
        const int buf = s & 1, nxt = buf ^ 1;
        const bool more = (s + 1 < nStages);
        if (more) loadTiles((s + 1) * BKt, nxt);

        unsigned aH[4][4], aL[4][4], bH[2][4], bL[2][4];
        #pragma unroll
        for (int mf = 0; mf < 4; mf++) {
            unsigned rowbase = (unsigned)((buf*128 + 64*wm + 16*mf) * APAD * 2);
            ldsm4(aH[mf], uAh + rowbase + aOff);
            ldsm4(aL[mf], uAl + rowbase + aOff);
        }
        #pragma unroll
        for (int np = 0; np < 2; np++) {
            unsigned cb = (unsigned)((buf*BKt*BPAD + 16*np) * 2);
            ldsm4t(bH[np], uBh + cb + bOff);
            ldsm4t(bL[np], uBl + cb + bOff);
        }
        #pragma unroll
        for (int mf = 0; mf < 4; mf++)
            #pragma unroll
            for (int nf = 0; nf < 4; nf++) {
                const unsigned* bh = &bH[nf >> 1][2*(nf & 1)];
                const unsigned* bl = &bL[nf >> 1][2*(nf & 1)];
                mma16816(acc[mf][nf], aH[mf], bh);
                mma16816(acc[mf][nf], aH[mf], bl);
                mma16816(acc[mf][nf], aL[mf], bh);
            }
        if (more) cp_wait0();
        __syncthreads();
    }

    const int rbase = m0 + 64*wm + (lane >> 2);
    const int cbase = n0 + 32*wn + 2*(lane & 3);
    #pragma unroll
    for (int mf = 0; mf < 4; mf++) {
        #pragma unroll
        for (int half = 0; half < 2; half++) {
            int m = rbase + 16*mf + 8*half;
            float bv = (MODE >= 1) ? bias[m] : 0.f;
            #pragma unroll
            for (int nf = 0; nf < 4; nf++) {
                int c = cbase + 8*nf;
                float vx = acc[mf][nf][2*half + 0] + bv;
                float vy = acc[mf][nf][2*half + 1] + bv;
                if (MODE == 1) {
                    vx = vx / (1.f + __expf(-vx));
                    vy = vy / (1.f + __expf(-vy));
                }
                *(float2*)&Cp[(size_t)m * Ntot + c] = make_float2(vx, vy);
            }
        }
    }
}

// ============================================================
// Forward rfft2 + x-split: reads plane with float4, emits
//   - x hi/lo bf16 split (for gate GEMM)
//   - spectrum hi/lo bf16 split (for QKV GEMM), coalesced.
// ============================================================
__global__ __launch_bounds__(256) void fft2_fwd_split_kernel(
    const float* __restrict__ in,
    __nv_bfloat162* __restrict__ xh, __nv_bfloat162* __restrict__ xl,
    __nv_bfloat162* __restrict__ outh, __nv_bfloat162* __restrict__ outl,
    float scale)
{
    __shared__ float  sp[HH * 65];
    __shared__ float2 u2[FREQ];
    __shared__ float2 pc[64];
    __shared__ float2 Tf[64];
    const int tid = threadIdx.x;
    const int plane = blockIdx.x;
    const float* p = in + (size_t)plane * NPIX;
    __nv_bfloat162* xhp = xh + (size_t)plane * (NPIX/2);
    __nv_bfloat162* xlp = xl + (size_t)plane * (NPIX/2);

    if (tid < 64) {
        float s, c; sincosf(TWO_PI_OVER_64 * (float)tid, &s, &c);
        Tf[tid] = make_float2(c, -s);
    }
    #pragma unroll
    for (int q = 0; q < 4; q++) {
        int base = tid + 256*q;            // float4 index, 0..1023
        float4 v = ((const float4*)p)[base];
        int row = base >> 4, col = (base & 15) * 4;
        sp[row*65 + col + 0] = v.x;
        sp[row*65 + col + 1] = v.y;
        sp[row*65 + col + 2] = v.z;
        sp[row*65 + col + 3] = v.w;
        split_store2(xhp, xlp, 2*base,     make_float2(v.x, v.y));
        split_store2(xhp, xlp, 2*base + 1, make_float2(v.z, v.w));
    }
    __syncthreads();

    fft_rows(sp, 65, u2, Tf, tid);
    __syncthreads();
    fft_cols_finish(u2, pc, Tf, tid, scale);
    __syncthreads();

    __nv_bfloat162* oh = outh + (size_t)plane * FREQ;
    __nv_bfloat162* ol = outl + (size_t)plane * FREQ;
    for (int i = tid; i < FREQ; i += 256) split_store2(oh, ol, i, u2[i]);
}

// ============================================================
// Fused middle: conj(q)*k -> irfft2 -> softmax -> rfft2 -> Xc (fp32).
// ============================================================
__global__ __launch_bounds__(256) void mid_fused_kernel(
    const float2* __restrict__ qc, float2* __restrict__ outc)
{
    __shared__ float2 y2[FREQ];
    __shared__ float2 u2[FREQ];
    __shared__ float2 pc[64];
    __shared__ float2 Tf[64];
    __shared__ float2 Ti[64];
    __shared__ float  red[256];
    float* pl = (float*)y2;

    const int tid = threadIdx.x;
    const int plane = blockIdx.x;
    const int b  = plane >> 9;
    const int ch = plane & 511;
    const float2* qp = qc + ((size_t)b * CH3 + ch) * FREQ;
    const float2* kp = qc + ((size_t)b * CH3 + 512 + ch) * FREQ;

    if (tid < 64) {
        float s, c; sincosf(TWO_PI_OVER_64 * (float)tid, &s, &c);
        Tf[tid] = make_float2(c, -s);
        Ti[tid] = make_float2(c,  s);
    }
    for (int i = tid; i < FREQ; i += 256) {
        float2 q = qp[i], k = kp[i];
        y2[i] = make_float2(q.x*k.x + q.y*k.y, q.x*k.y - q.y*k.x);
    }
    __syncthreads();

    ifft_cols(y2, u2, Ti, tid);
    __syncthreads();

    {
        float2 zres[8];
        ifft_rows(u2, Ti, tid, zres);
        const int r = tid >> 3, sub = tid & 7;
        const float s = 1.0f / 64.0f;
        __syncthreads();
        #pragma unroll
        for (int k2 = 0; k2 < 8; k2++) {
            int w = sub + 8*k2;
            pl[(2*r)*65 + w]     = zres[k2].x * s;
            pl[(2*r + 1)*65 + w] = zres[k2].y * s;
        }
    }
    __syncthreads();

    {
        float m = -3.4e38f;
        for (int i = tid; i < NPIX; i += 256) {
            float v = pl[(i >> 6)*65 + (i & 63)];
            m = fmaxf(m, v);
        }
        red[tid] = m; __syncthreads();
        for (int s = 128; s > 0; s >>= 1) { if (tid < s) red[tid] = fmaxf(red[tid], red[tid + s]); __syncthreads(); }
        const float M = red[0];
        __syncthreads();
        float sum = 0.f;
        for (int i = tid; i < NPIX; i += 256) {
            int a = (i >> 6)*65 + (i & 63);
            float e = __expf(pl[a] - M);
            pl[a] = e; sum += e;
        }
        red[tid] = sum; __syncthreads();
        for (int s = 128; s > 0; s >>= 1) { if (tid < s) red[tid] += red[tid + s]; __syncthreads(); }
        const float inv = 1.f / red[0];
        __syncthreads();
        for (int i = tid; i < NPIX; i += 256) {
            int a = (i >> 6)*65 + (i & 63);
            pl[a] *= inv;
        }
    }
    __syncthreads();

    fft_rows(pl, 65, u2, Tf, tid);
    __syncthreads();
    fft_cols_finish(u2, pc, Tf, tid, 1.0f);
    __syncthreads();

    float2* ob = outc + (size_t)plane * FREQ;
    for (int i = tid; i < FREQ; i += 256) ob[i] = u2[i];
}

// ============================================================
// Fused: Y = conj(a)*b, irfft2(Y), gate-multiply, bf16 hi/lo out.
// ============================================================
__global__ __launch_bounds__(256) void prod_ifft2_gate_bf16_kernel(
    const float2* __restrict__ ac, int aCPB, int aOff,
    const float2* __restrict__ bc, int bCPB, int bOff,
    const float* __restrict__ gate,
    __nv_bfloat162* __restrict__ outh, __nv_bfloat162* __restrict__ outl,
    float scale)
{
    __shared__ float2 y2[FREQ];
    __shared__ float2 u2[FREQ];
    __shared__ float2 Ti[64];
    float* pl = (float*)y2;
    const int tid = threadIdx.x;
    const int plane = blockIdx.x;
    const int b  = plane >> 9;
    const int ch = plane & 511;
    const float2* ap = ac + ((size_t)b * aCPB + aOff + ch) * FREQ;
    const float2* bp = bc + ((size_t)b * bCPB + bOff + ch) * FREQ;

    if (tid < 64) {
        float s, c; sincosf(TWO_PI_OVER_64 * (float)tid, &s, &c);
        Ti[tid] = make_float2(c, s);
    }
    for (int i = tid; i < FREQ; i += 256) {
        float2 a = ap[i], bb = bp[i];
        y2[i] = make_float2(a.x*bb.x + a.y*bb.y, a.x*bb.y - a.y*bb.x);
    }
    __syncthreads();

    ifft_cols(y2, u2, Ti, tid);
    __syncthreads();

    {
        float2 zres[8];
        ifft_rows(u2, Ti, tid, zres);
        __syncthreads();
        const int r = tid >> 3, sub = tid & 7;
        #pragma unroll
        for (int k2 = 0; k2 < 8; k2++) {
            int w = sub + 8*k2;
            pl[(2*r)*65 + w]     = zres[k2].x * scale;
            pl[(2*r + 1)*65 + w] = zres[k2].y * scale;
        }
    }
    __syncthreads();

    {
        const float2* gp2 = (const float2*)(gate + (size_t)plane * NPIX);
        __nv_bfloat162* oh = outh + (size_t)plane * (NPIX/2);
        __nv_bfloat162* ol = outl + (size_t)plane * (NPIX/2);
        for (int i = tid; i < NPIX/2; i += 256) {
            int row = (2*i) >> 6, col = (2*i) & 63;
            float2 g = gp2[i];
            float2 v = make_float2(pl[row*65 + col] * g.x, pl[row*65 + col + 1] * g.y);
            split_store2(oh, ol, i, v);
        }
    }
}

// ============================================================
extern "C" void kernel_launch(void* const* d_in, const int* in_sizes, int n_in,
                              void* d_out, int out_size)
{
    const float* x      = (const float*)d_in[0];
    const float* w_qkv  = (const float*)d_in[1];
    const float* w_gate = (const float*)d_in[2];
    const float* b_gate = (const float*)d_in[3];
    const float* w_proj = (const float*)d_in[4];
    const float* b_proj = (const float*)d_in[5];
    float* out = (float*)d_out;

    float2 *Xc, *Qc;
    float  *t;
    __nv_bfloat16 *wh, *wl, *bh, *bl, *b2h, *b2l;
    cudaGetSymbolAddress((void**)&Xc,   g_Xc);
    cudaGetSymbolAddress((void**)&Qc,   g_Qc);
    cudaGetSymbolAddress((void**)&t,    g_t);
    cudaGetSymbolAddress((void**)&wh,   g_wh);
    cudaGetSymbolAddress((void**)&wl,   g_wl);
    cudaGetSymbolAddress((void**)&bh,   g_bh);
    cudaGetSymbolAddress((void**)&bl,   g_bl);
    cudaGetSymbolAddress((void**)&b2h,  g_b2h);
    cudaGetSymbolAddress((void**)&b2l,  g_b2l);

    const float inv64 = 1.0f / 64.0f;
    const int SPLIT_BLKS = 1184;

    // 1. fft2+split: x -> x-split (bh/bl) AND spectrum-split (b2h/b2l)
    fft2_fwd_split_kernel<<<PLANES, 256>>>(x,
        (__nv_bfloat162*)bh, (__nv_bfloat162*)bl,
        (__nv_bfloat162*)b2h, (__nv_bfloat162*)b2l, inv64);
    // 2. gate: t = SiLU(Wg*x + bg)
    split_kernel<<<SPLIT_BLKS, 256>>>(w_gate, wh, wl, (CH*CH)/4);
    {
        dim3 g(NPIX / 128, CH / 128, BATCH);
        mma_gemm<1><<<g, 256>>>(wh, wl, bh, bl, b_gate, t, CH, NPIX, CH);
    }
    // 3. QKV GEMM (complex interleaved, Ntot=4224)
    split_kernel<<<SPLIT_BLKS, 256>>>(w_qkv, wh, wl, (CH3*CH)/4);
    {
        dim3 g(NQKV / 128, CH3 / 128, BATCH);
        mma_gemm<0><<<g, 256>>>(wh, wl, b2h, b2l, nullptr, (float*)Qc, CH3, NQKV, CH);
    }
    // 4-6. fused middle: conj(q)*k -> irfft2 -> softmax -> rfft2 -> Xc
    mid_fused_kernel<<<PLANES, 256>>>(Qc, Xc);
    // 7. y = irfft2(conj(A)*v) * t -> bf16 hi/lo (bh/bl)
    prod_ifft2_gate_bf16_kernel<<<PLANES, 256>>>(Xc, CH, 0,
                                                 Qc, CH3, 1024,
                                                 t, (__nv_bfloat162*)bh, (__nv_bfloat162*)bl,
                                                 inv64);
    // 8. proj: out = Wp*y + bp
    split_kernel<<<SPLIT_BLKS, 256>>>(w_proj, wh, wl, (CH*CH)/4);
    {
        dim3 g(NPIX / 128, CH / 128, BATCH);
        mma_gemm<3><<<g, 256>>>(wh, wl, bh, bl, b_proj, out, CH, NPIX, CH);
    }
}

// round 12
// speedup vs baseline: 2.6395x; 1.0006x over previous
#include <cuda_runtime.h>
#include <cuda_bf16.h>
#include <cstdint>
#include <math.h>

#define BATCH 8
#define CH    512
#define CH3   1536
#define HH    64
#define NPIX  4096          // 64*64
#define WR    33            // rfft width 64/2+1
#define FREQ  2112          // 64*33
#define PLANES (BATCH*CH)   // 4096
#define NQKV  4224          // 2*FREQ floats per plane-row (interleaved complex)

// ---- static scratch (no allocations allowed) ----
__device__ float2 g_Xc[BATCH*CH*FREQ];    // interleaved {re,im} (mid output)
__device__ float2 g_Qc[BATCH*CH3*FREQ];   // interleaved {re,im}
__device__ float  g_t[BATCH*CH*NPIX];
// bf16 split buffers
__device__ __nv_bfloat16 g_wh[CH3*CH];
__device__ __nv_bfloat16 g_wl[CH3*CH];
__device__ __nv_bfloat16 g_bh[BATCH*CH*NQKV];    // x-split / y-split
__device__ __nv_bfloat16 g_bl[BATCH*CH*NQKV];
__device__ __nv_bfloat16 g_b2h[BATCH*CH*NQKV];   // spectrum split
__device__ __nv_bfloat16 g_b2l[BATCH*CH*NQKV];

#define TWO_PI_OVER_64 0.09817477042468103f

// ---- cp.async helpers ----
__device__ __forceinline__ void cp_async16(unsigned int saddr, const void* g) {
    asm volatile("cp.async.cg.shared.global [%0], [%1], 16;\n" :: "r"(saddr), "l"(g));
}
__device__ __forceinline__ void cp_commit() { asm volatile("cp.async.commit_group;\n"); }
__device__ __forceinline__ void cp_wait0()  { asm volatile("cp.async.wait_group 0;\n" ::: "memory"); }

// ---- tensor-core helpers ----
__device__ __forceinline__ void mma16816(float* d, const unsigned* a, const unsigned* b) {
    asm volatile("mma.sync.aligned.m16n8k16.row.col.f32.bf16.bf16.f32 "
        "{%0,%1,%2,%3}, {%4,%5,%6,%7}, {%8,%9}, {%0,%1,%2,%3};"
        : "+f"(d[0]), "+f"(d[1]), "+f"(d[2]), "+f"(d[3])
        : "r"(a[0]), "r"(a[1]), "r"(a[2]), "r"(a[3]), "r"(b[0]), "r"(b[1]));
}
__device__ __forceinline__ void ldsm4(unsigned* r, unsigned addr) {
    asm volatile("ldmatrix.sync.aligned.m8n8.x4.shared.b16 {%0,%1,%2,%3}, [%4];"
        : "=r"(r[0]), "=r"(r[1]), "=r"(r[2]), "=r"(r[3]) : "r"(addr));
}
__device__ __forceinline__ void ldsm4t(unsigned* r, unsigned addr) {
    asm volatile("ldmatrix.sync.aligned.m8n8.x4.trans.shared.b16 {%0,%1,%2,%3}, [%4];"
        : "=r"(r[0]), "=r"(r[1]), "=r"(r[2]), "=r"(r[3]) : "r"(addr));
}

// ---- bf16 hi/lo split store of a float2 ----
__device__ __forceinline__ void split_store2(__nv_bfloat162* __restrict__ h,
                                             __nv_bfloat162* __restrict__ l,
                                             size_t idx, float2 v) {
    __nv_bfloat16 hx = __float2bfloat16(v.x);
    __nv_bfloat16 hy = __float2bfloat16(v.y);
    __nv_bfloat162 H, L;
    H.x = hx; H.y = hy;
    L.x = __float2bfloat16(v.x - __bfloat162float(hx));
    L.y = __float2bfloat16(v.y - __bfloat162float(hy));
    h[idx] = H; l[idx] = L;
}

// ---- complex helpers ----
__device__ __forceinline__ float2 cadd(float2 a, float2 b){ return make_float2(a.x+b.x, a.y+b.y); }
__device__ __forceinline__ float2 csub(float2 a, float2 b){ return make_float2(a.x-b.x, a.y-b.y); }
__device__ __forceinline__ float2 cmul(float2 a, float2 t){ return make_float2(a.x*t.x - a.y*t.y, a.x*t.y + a.y*t.x); }

template<int S>
__device__ __forceinline__ float2 muliS(float2 a) {
    return (S > 0) ? make_float2(-a.y, a.x) : make_float2(a.y, -a.x);
}

template<int S>
__device__ __forceinline__ void dft8(float2 z[8]) {
    const float C = 0.70710678118654752f;
    const float sf = (S > 0) ? 1.f : -1.f;
    float2 t0 = cadd(z[0], z[4]), t1 = csub(z[0], z[4]);
    float2 t2 = cadd(z[2], z[6]), t3 = csub(z[2], z[6]);
    float2 E0 = cadd(t0, t2), E2 = csub(t0, t2);
    float2 t3r = muliS<S>(t3);
    float2 E1 = cadd(t1, t3r), E3 = csub(t1, t3r);
    float2 s0 = cadd(z[1], z[5]), s1 = csub(z[1], z[5]);
    float2 s2 = cadd(z[3], z[7]), s3 = csub(z[3], z[7]);
    float2 O0 = cadd(s0, s2), O2 = csub(s0, s2);
    float2 s3r = muliS<S>(s3);
    float2 O1 = cadd(s1, s3r), O3 = csub(s1, s3r);
    float2 W1O1 = make_float2(C*(O1.x - sf*O1.y), C*(O1.y + sf*O1.x));
    float2 W2O2 = muliS<S>(O2);
    float2 W3O3 = make_float2(C*(-O3.x - sf*O3.y), C*(-O3.y + sf*O3.x));
    z[0] = cadd(E0, O0);  z[4] = csub(E0, O0);
    z[1] = cadd(E1, W1O1); z[5] = csub(E1, W1O1);
    z[2] = cadd(E2, W2O2); z[6] = csub(E2, W2O2);
    z[3] = cadd(E3, W3O3); z[7] = csub(E3, W3O3);
}

// ============================================================
// Warp-cooperative 64-pt FFT phases.
// ============================================================
__device__ __forceinline__ void ifft_cols(const float2* __restrict__ y2, float2* __restrict__ u2,
                                          const float2* Ti, int tid)
{
    const int g = tid >> 3, sub = tid & 7;
    float2 z[8];
    if (g == 0) {
        #pragma unroll
        for (int n1 = 0; n1 < 8; n1++) {
            int m = 8*n1 + sub;
            float2 A = y2[33*m], B = y2[33*m + 32];
            z[n1] = make_float2(A.x - B.y, A.y + B.x);
        }
    } else {
        #pragma unroll
        for (int n1 = 0; n1 < 8; n1++) z[n1] = y2[33*(8*n1 + sub) + g];
    }
    dft8<1>(z);
    #pragma unroll
    for (int k1 = 1; k1 < 8; k1++) z[k1] = cmul(z[k1], Ti[k1*sub]);
    #pragma unroll
    for (int k1 = 0; k1 < 8; k1++) u2[33*(8*k1 + sub) + g] = z[k1];
    __syncwarp();
    #pragma unroll
    for (int j = 0; j < 8; j++) z[j] = u2[33*(8*sub + j) + g];
    dft8<1>(z);
    __syncwarp();
    #pragma unroll
    for (int k2 = 0; k2 < 8; k2++) u2[33*(sub + 8*k2) + g] = z[k2];
}

__device__ __forceinline__ void ifft_rows(float2* __restrict__ u2, const float2* Ti, int tid,
                                          float2 zres[8])
{
    const int r = tid >> 3, sub = tid & 7;
    float2* R = u2 + 66*r;
    float2 z[8];
    #pragma unroll
    for (int n1 = 0; n1 < 8; n1++) {
        int m = 8*n1 + sub;
        float2 A, B;
        if (m == 0)       { A = make_float2(R[0].x, 0.f);  B = make_float2(R[33].x, 0.f); }
        else if (m == 32) { A = make_float2(R[0].y, 0.f);  B = make_float2(R[33].y, 0.f); }
        else if (m < 32)  { A = R[m];                      B = R[33 + m]; }
        else {
            float2 Am = R[64 - m];      A = make_float2(Am.x, -Am.y);
            float2 Bm = R[33 + 64 - m]; B = make_float2(Bm.x, -Bm.y);
        }
        z[n1] = make_float2(A.x - B.y, A.y + B.x);
    }
    __syncwarp();
    dft8<1>(z);
    #pragma unroll
    for (int k1 = 1; k1 < 8; k1++) z[k1] = cmul(z[k1], Ti[k1*sub]);
    #pragma unroll
    for (int k1 = 0; k1 < 8; k1++) R[8*k1 + sub] = z[k1];
    __syncwarp();
    #pragma unroll
    for (int j = 0; j < 8; j++) z[j] = R[8*sub + j];
    dft8<1>(z);
    #pragma unroll
    for (int k2 = 0; k2 < 8; k2++) zres[k2] = z[k2];
}

__device__ __forceinline__ void fft_rows(const float* __restrict__ pl, int plstride,
                                         float2* __restrict__ u2, const float2* Tf, int tid)
{
    const int r = tid >> 3, sub = tid & 7;
    const float* p0 = pl + (2*r) * plstride;
    const float* p1 = pl + (2*r + 1) * plstride;
    float2* R = u2 + 66*r;
    float2 z[8];
    #pragma unroll
    for (int n1 = 0; n1 < 8; n1++) {
        int m = 8*n1 + sub;
        z[n1] = make_float2(p0[m], p1[m]);
    }
    dft8<-1>(z);
    #pragma unroll
    for (int k1 = 1; k1 < 8; k1++) z[k1] = cmul(z[k1], Tf[k1*sub]);
    #pragma unroll
    for (int k1 = 0; k1 < 8; k1++) R[8*k1 + sub] = z[k1];
    __syncwarp();
    #pragma unroll
    for (int j = 0; j < 8; j++) z[j] = R[8*sub + j];
    dft8<-1>(z);
    __syncwarp();
    #pragma unroll
    for (int k2 = 0; k2 < 8; k2++) R[sub + 8*k2] = z[k2];
    __syncwarp();
    float2 Zk[5], Zm[5];
    #pragma unroll
    for (int q = 0; q < 4; q++) { int k = sub + 8*q; Zk[q] = R[k]; Zm[q] = R[(64 - k) & 63]; }
    if (sub == 0) { Zk[4] = R[32]; Zm[4] = R[32]; }
    __syncwarp();
    #pragma unroll
    for (int q = 0; q < 4; q++) {
        int k = sub + 8*q;
        R[k]      = make_float2(0.5f*(Zk[q].x + Zm[q].x), 0.5f*(Zk[q].y - Zm[q].y));
        R[33 + k] = make_float2(0.5f*(Zk[q].y + Zm[q].y), 0.5f*(Zm[q].x - Zk[q].x));
    }
    if (sub == 0) {
        R[32] = make_float2(Zk[4].x, 0.f);
        R[65] = make_float2(Zk[4].y, 0.f);
    }
}

// Forward FFT along h; finishes IN SMEM: u2[kh*33 + k] holds the scaled
// final spectrum (row-major). pc = 64-entry float2 side buffer.
__device__ __forceinline__ void fft_cols_finish(float2* __restrict__ u2, float2* __restrict__ pc,
                                                const float2* Tf, int tid, float scale)
{
    const int g = tid >> 3, sub = tid & 7;
    float2 z[8];
    if (g == 0) {
        #pragma unroll
        for (int n1 = 0; n1 < 8; n1++) {
            int h = 8*n1 + sub;
            z[n1] = make_float2(u2[33*h].x, u2[33*h + 32].x);
        }
    } else {
        #pragma unroll
        for (int n1 = 0; n1 < 8; n1++) z[n1] = u2[33*(8*n1 + sub) + g];
    }
    dft8<-1>(z);
    #pragma unroll
    for (int k1 = 1; k1 < 8; k1++) z[k1] = cmul(z[k1], Tf[k1*sub]);
    #pragma unroll
    for (int k1 = 0; k1 < 8; k1++) u2[33*(8*k1 + sub) + g] = z[k1];
    __syncwarp();
    #pragma unroll
    for (int j = 0; j < 8; j++) z[j] = u2[33*(8*sub + j) + g];
    dft8<-1>(z);
    __syncwarp();
    if (g != 0) {
        #pragma unroll
        for (int k2 = 0; k2 < 8; k2++) {
            int kh = sub + 8*k2;
            u2[kh*33 + g] = make_float2(z[k2].x * scale, z[k2].y * scale);
        }
    } else {
        #pragma unroll
        for (int k2 = 0; k2 < 8; k2++) pc[sub + 8*k2] = z[k2];   // packed col to side buf
    }
    __syncwarp();
    if (g == 0) {
        #pragma unroll
        for (int j = 0; j < 8; j++) {
            int k = 8*sub + j;
            float2 Zk = pc[k];
            float2 Zm = pc[(64 - k) & 63];
            u2[k*33 + 0]  = make_float2(0.5f*(Zk.x + Zm.x)*scale, 0.5f*(Zk.y - Zm.y)*scale);
            u2[k*33 + 32] = make_float2(0.5f*(Zk.y + Zm.y)*scale, 0.5f*(Zm.x - Zk.x)*scale);
        }
    }
}

// ============================================================
// fp32 -> (hi, lo) bf16 split (weights only now).
// ============================================================
__global__ __launch_bounds__(256) void split_kernel(
    const float* __restrict__ in,
    __nv_bfloat16* __restrict__ hi, __nv_bfloat16* __restrict__ lo, int n4)
{
    int i = blockIdx.x * 256 + threadIdx.x;
    int stride = gridDim.x * 256;
    for (; i < n4; i += stride) {
        float4 v = ((const float4*)in)[i];
        split_store2((__nv_bfloat162*)hi, (__nv_bfloat162*)lo, 2*i,     make_float2(v.x, v.y));
        split_store2((__nv_bfloat162*)hi, (__nv_bfloat162*)lo, 2*i + 1, make_float2(v.z, v.w));
    }
}

// ============================================================
// Split-bf16 tensor-core GEMM (R9, unchanged).
// ============================================================
#define BKt 16
#define APAD 24
#define BPAD 136

template<int MODE>
__global__ __launch_bounds__(256) void mma_gemm(
    const __nv_bfloat16* __restrict__ Ah, const __nv_bfloat16* __restrict__ Al,
    const __nv_bfloat16* __restrict__ Bh, const __nv_bfloat16* __restrict__ Bl,
    const float* __restrict__ bias,
    float* __restrict__ C,
    int M, int Ntot, int K)
{
    __shared__ __align__(16) __nv_bfloat16 sAh[2][128][APAD];
    __shared__ __align__(16) __nv_bfloat16 sAl[2][128][APAD];
    __shared__ __align__(16) __nv_bfloat16 sBh[2][BKt][BPAD];
    __shared__ __align__(16) __nv_bfloat16 sBl[2][BKt][BPAD];

    const int bx = blockIdx.x, by = blockIdx.y, bz = blockIdx.z;
    const int n0 = bx * 128, m0 = by * 128;
    const __nv_bfloat16* Bhp = Bh + (size_t)bz * K * Ntot;
    const __nv_bfloat16* Blp = Bl + (size_t)bz * K * Ntot;
    float* Cp = C + (size_t)bz * M * Ntot;

    const int tid  = threadIdx.x;
    const int lane = tid & 31;
    const int wid  = tid >> 5;
    const int wm   = wid >> 2;
    const int wn   = wid & 3;

    const unsigned uAh = (unsigned)__cvta_generic_to_shared(&sAh[0][0][0]);
    const unsigned uAl = (unsigned)__cvta_generic_to_shared(&sAl[0][0][0]);
    const unsigned uBh = (unsigned)__cvta_generic_to_shared(&sBh[0][0][0]);
    const unsigned uBl = (unsigned)__cvta_generic_to_shared(&sBl[0][0][0]);

    const int arow = tid >> 1;
    const int achk = (tid & 1) * 8;
    const int brow = tid >> 4;
    const int bchk = (tid & 15) * 8;

    auto loadTiles = [&](int k0, int bufI) {
        cp_async16(uAh + (unsigned)(((bufI*128 + arow)*APAD + achk)*2),
                   Ah + (size_t)(m0 + arow) * K + k0 + achk);
        cp_async16(uAl + (unsigned)(((bufI*128 + arow)*APAD + achk)*2),
                   Al + (size_t)(m0 + arow) * K + k0 + achk);
        cp_async16(uBh + (unsigned)(((bufI*BKt + brow)*BPAD + bchk)*2),
                   Bhp + (size_t)(k0 + brow) * Ntot + n0 + bchk);
        cp_async16(uBl + (unsigned)(((bufI*BKt + brow)*BPAD + bchk)*2),
                   Blp + (size_t)(k0 + brow) * Ntot + n0 + bchk);
        cp_commit();
    };

    float acc[4][4][4];
    #pragma unroll
    for (int i = 0; i < 4; i++)
        #pragma unroll
        for (int j = 0; j < 4; j++)
            #pragma unroll
            for (int q = 0; q < 4; q++) acc[i][j][q] = 0.f;

    const unsigned aOff = (unsigned)(((lane & 15) * APAD + (lane >> 4) * 8) * 2);
    const unsigned bOff = (unsigned)(((lane & 15) * BPAD + 32*wn + (lane >> 4) * 8) * 2);

    const int nStages = K / BKt;
    loadTiles(0, 0);
    cp_wait0();
    __syncthreads();

    for (int s = 0; s < nStages; s++) {
        const int buf = s & 1, nxt = buf ^ 1;
        const bool more = (s + 1 < nStages);
        if (more) loadTiles((s + 1) * BKt, nxt);

        unsigned aH[4][4], aL[4][4], bH[2][4], bL[2][4];
        #pragma unroll
        for (int mf = 0; mf < 4; mf++) {
            unsigned rowbase = (unsigned)((buf*128 + 64*wm + 16*mf) * APAD * 2);
            ldsm4(aH[mf], uAh + rowbase + aOff);
            ldsm4(aL[mf], uAl + rowbase + aOff);
        }
        #pragma unroll
        for (int np = 0; np < 2; np++) {
            unsigned cb = (unsigned)((buf*BKt*BPAD + 16*np) * 2);
            ldsm4t(bH[np], uBh + cb + bOff);
            ldsm4t(bL[np], uBl + cb + bOff);
        }
        #pragma unroll
        for (int mf = 0; mf < 4; mf++)
            #pragma unroll
            for (int nf = 0; nf < 4; nf++) {
                const unsigned* bh = &bH[nf >> 1][2*(nf & 1)];
                const unsigned* bl = &bL[nf >> 1][2*(nf & 1)];
                mma16816(acc[mf][nf], aH[mf], bh);
                mma16816(acc[mf][nf], aH[mf], bl);
                mma16816(acc[mf][nf], aL[mf], bh);
            }
        if (more) cp_wait0();
        __syncthreads();
    }

    const int rbase = m0 + 64*wm + (lane >> 2);
    const int cbase = n0 + 32*wn + 2*(lane & 3);
    #pragma unroll
    for (int mf = 0; mf < 4; mf++) {
        #pragma unroll
        for (int half = 0; half < 2; half++) {
            int m = rbase + 16*mf + 8*half;
            float bv = (MODE >= 1) ? bias[m] : 0.f;
            #pragma unroll
            for (int nf = 0; nf < 4; nf++) {
                int c = cbase + 8*nf;
                float vx = acc[mf][nf][2*half + 0] + bv;
                float vy = acc[mf][nf][2*half + 1] + bv;
                if (MODE == 1) {
                    vx = vx / (1.f + __expf(-vx));
                    vy = vy / (1.f + __expf(-vy));
                }
                *(float2*)&Cp[(size_t)m * Ntot + c] = make_float2(vx, vy);
            }
        }
    }
}

// ============================================================
// Forward rfft2 + x-split: reads plane with float4, emits
//   - x hi/lo bf16 split (for gate GEMM)
//   - spectrum hi/lo bf16 split (for QKV GEMM), coalesced.
// ============================================================
__global__ __launch_bounds__(256) void fft2_fwd_split_kernel(
    const float* __restrict__ in,
    __nv_bfloat162* __restrict__ xh, __nv_bfloat162* __restrict__ xl,
    __nv_bfloat162* __restrict__ outh, __nv_bfloat162* __restrict__ outl,
    float scale)
{
    __shared__ float  sp[HH * 65];
    __shared__ float2 u2[FREQ];
    __shared__ float2 pc[64];
    __shared__ float2 Tf[64];
    const int tid = threadIdx.x;
    const int plane = blockIdx.x;
    const float* p = in + (size_t)plane * NPIX;
    __nv_bfloat162* xhp = xh + (size_t)plane * (NPIX/2);
    __nv_bfloat162* xlp = xl + (size_t)plane * (NPIX/2);

    if (tid < 64) {
        float s, c; sincosf(TWO_PI_OVER_64 * (float)tid, &s, &c);
        Tf[tid] = make_float2(c, -s);
    }
    #pragma unroll
    for (int q = 0; q < 4; q++) {
        int base = tid + 256*q;            // float4 index, 0..1023
        float4 v = ((const float4*)p)[base];
        int row = base >> 4, col = (base & 15) * 4;
        sp[row*65 + col + 0] = v.x;
        sp[row*65 + col + 1] = v.y;
        sp[row*65 + col + 2] = v.z;
        sp[row*65 + col + 3] = v.w;
        split_store2(xhp, xlp, 2*base,     make_float2(v.x, v.y));
        split_store2(xhp, xlp, 2*base + 1, make_float2(v.z, v.w));
    }
    __syncthreads();

    fft_rows(sp, 65, u2, Tf, tid);
    __syncthreads();
    fft_cols_finish(u2, pc, Tf, tid, scale);
    __syncthreads();

    __nv_bfloat162* oh = outh + (size_t)plane * FREQ;
    __nv_bfloat162* ol = outl + (size_t)plane * FREQ;
    for (int i = tid; i < FREQ; i += 256) split_store2(oh, ol, i, u2[i]);
}

// ============================================================
// Fused middle: conj(q)*k -> irfft2 -> softmax -> rfft2 -> Xc (fp32).
// ============================================================
__global__ __launch_bounds__(256) void mid_fused_kernel(
    const float2* __restrict__ qc, float2* __restrict__ outc)
{
    __shared__ float2 y2[FREQ];
    __shared__ float2 u2[FREQ];
    __shared__ float2 pc[64];
    __shared__ float2 Tf[64];
    __shared__ float2 Ti[64];
    __shared__ float  red[256];
    float* pl = (float*)y2;

    const int tid = threadIdx.x;
    const int plane = blockIdx.x;
    const int b  = plane >> 9;
    const int ch = plane & 511;
    const float2* qp = qc + ((size_t)b * CH3 + ch) * FREQ;
    const float2* kp = qc + ((size_t)b * CH3 + 512 + ch) * FREQ;

    if (tid < 64) {
        float s, c; sincosf(TWO_PI_OVER_64 * (float)tid, &s, &c);
        Tf[tid] = make_float2(c, -s);
        Ti[tid] = make_float2(c,  s);
    }
    for (int i = tid; i < FREQ; i += 256) {
        float2 q = qp[i], k = kp[i];
        y2[i] = make_float2(q.x*k.x + q.y*k.y, q.x*k.y - q.y*k.x);
    }
    __syncthreads();

    ifft_cols(y2, u2, Ti, tid);
    __syncthreads();

    {
        float2 zres[8];
        ifft_rows(u2, Ti, tid, zres);
        const int r = tid >> 3, sub = tid & 7;
        const float s = 1.0f / 64.0f;
        __syncthreads();
        #pragma unroll
        for (int k2 = 0; k2 < 8; k2++) {
            int w = sub + 8*k2;
            pl[(2*r)*65 + w]     = zres[k2].x * s;
            pl[(2*r + 1)*65 + w] = zres[k2].y * s;
        }
    }
    __syncthreads();

    {
        float m = -3.4e38f;
        for (int i = tid; i < NPIX; i += 256) {
            float v = pl[(i >> 6)*65 + (i & 63)];
            m = fmaxf(m, v);
        }
        red[tid] = m; __syncthreads();
        for (int s = 128; s > 0; s >>= 1) { if (tid < s) red[tid] = fmaxf(red[tid], red[tid + s]); __syncthreads(); }
        const float M = red[0];
        __syncthreads();
        float sum = 0.f;
        for (int i = tid; i < NPIX; i += 256) {
            int a = (i >> 6)*65 + (i & 63);
            float e = __expf(pl[a] - M);
            pl[a] = e; sum += e;
        }
        red[tid] = sum; __syncthreads();
        for (int s = 128; s > 0; s >>= 1) { if (tid < s) red[tid] += red[tid + s]; __syncthreads(); }
        const float inv = 1.f / red[0];
        __syncthreads();
        for (int i = tid; i < NPIX; i += 256) {
            int a = (i >> 6)*65 + (i & 63);
            pl[a] *= inv;
        }
    }
    __syncthreads();

    fft_rows(pl, 65, u2, Tf, tid);
    __syncthreads();
    fft_cols_finish(u2, pc, Tf, tid, 1.0f);
    __syncthreads();

    float2* ob = outc + (size_t)plane * FREQ;
    for (int i = tid; i < FREQ; i += 256) ob[i] = u2[i];
}

// ============================================================
// Fused: Y = conj(a)*b, irfft2(Y), gate-multiply, bf16 hi/lo out.
// ============================================================
__global__ __launch_bounds__(256) void prod_ifft2_gate_bf16_kernel(
    const float2* __restrict__ ac, int aCPB, int aOff,
    const float2* __restrict__ bc, int bCPB, int bOff,
    const float* __restrict__ gate,
    __nv_bfloat162* __restrict__ outh, __nv_bfloat162* __restrict__ outl,
    float scale)
{
    __shared__ float2 y2[FREQ];
    __shared__ float2 u2[FREQ];
    __shared__ float2 Ti[64];
    float* pl = (float*)y2;
    const int tid = threadIdx.x;
    const int plane = blockIdx.x;
    const int b  = plane >> 9;
    const int ch = plane & 511;
    const float2* ap = ac + ((size_t)b * aCPB + aOff + ch) * FREQ;
    const float2* bp = bc + ((size_t)b * bCPB + bOff + ch) * FREQ;

    if (tid < 64) {
        float s, c; sincosf(TWO_PI_OVER_64 * (float)tid, &s, &c);
        Ti[tid] = make_float2(c, s);
    }
    for (int i = tid; i < FREQ; i += 256) {
        float2 a = ap[i], bb = bp[i];
        y2[i] = make_float2(a.x*bb.x + a.y*bb.y, a.x*bb.y - a.y*bb.x);
    }
    __syncthreads();

    ifft_cols(y2, u2, Ti, tid);
    __syncthreads();

    {
        float2 zres[8];
        ifft_rows(u2, Ti, tid, zres);
        __syncthreads();
        const int r = tid >> 3, sub = tid & 7;
        #pragma unroll
        for (int k2 = 0; k2 < 8; k2++) {
            int w = sub + 8*k2;
            pl[(2*r)*65 + w]     = zres[k2].x * scale;
            pl[(2*r + 1)*65 + w] = zres[k2].y * scale;
        }
    }
    __syncthreads();

    {
        const float2* gp2 = (const float2*)(gate + (size_t)plane * NPIX);
        __nv_bfloat162* oh = outh + (size_t)plane * (NPIX/2);
        __nv_bfloat162* ol = outl + (size_t)plane * (NPIX/2);
        for (int i = tid; i < NPIX/2; i += 256) {
            int row = (2*i) >> 6, col = (2*i) & 63;
            float2 g = gp2[i];
            float2 v = make_float2(pl[row*65 + col] * g.x, pl[row*65 + col + 1] * g.y);
            split_store2(oh, ol, i, v);
        }
    }
}

// ============================================================
extern "C" void kernel_launch(void* const* d_in, const int* in_sizes, int n_in,
                              void* d_out, int out_size)
{
    const float* x      = (const float*)d_in[0];
    const float* w_qkv  = (const float*)d_in[1];
    const float* w_gate = (const float*)d_in[2];
    const float* b_gate = (const float*)d_in[3];
    const float* w_proj = (const float*)d_in[4];
    const float* b_proj = (const float*)d_in[5];
    float* out = (float*)d_out;

    float2 *Xc, *Qc;
    float  *t;
    __nv_bfloat16 *wh, *wl, *bh, *bl, *b2h, *b2l;
    cudaGetSymbolAddress((void**)&Xc,   g_Xc);
    cudaGetSymbolAddress((void**)&Qc,   g_Qc);
    cudaGetSymbolAddress((void**)&t,    g_t);
    cudaGetSymbolAddress((void**)&wh,   g_wh);
    cudaGetSymbolAddress((void**)&wl,   g_wl);
    cudaGetSymbolAddress((void**)&bh,   g_bh);
    cudaGetSymbolAddress((void**)&bl,   g_bl);
    cudaGetSymbolAddress((void**)&b2h,  g_b2h);
    cudaGetSymbolAddress((void**)&b2l,  g_b2l);

    const float inv64 = 1.0f / 64.0f;
    const int SPLIT_BLKS = 1184;

    // 1. fft2+split: x -> x-split (bh/bl) AND spectrum-split (b2h/b2l)
    fft2_fwd_split_kernel<<<PLANES, 256>>>(x,
        (__nv_bfloat162*)bh, (__nv_bfloat162*)bl,
        (__nv_bfloat162*)b2h, (__nv_bfloat162*)b2l, inv64);
    // 2. gate: t = SiLU(Wg*x + bg)
    split_kernel<<<SPLIT_BLKS, 256>>>(w_gate, wh, wl, (CH*CH)/4);
    {
        dim3 g(NPIX / 128, CH / 128, BATCH);
        mma_gemm<1><<<g, 256>>>(wh, wl, bh, bl, b_gate, t, CH, NPIX, CH);
    }
    // 3. QKV GEMM (complex interleaved, Ntot=4224)
    split_kernel<<<SPLIT_BLKS, 256>>>(w_qkv, wh, wl, (CH3*CH)/4);
    {
        dim3 g(NQKV / 128, CH3 / 128, BATCH);
        mma_gemm<0><<<g, 256>>>(wh, wl, b2h, b2l, nullptr, (float*)Qc, CH3, NQKV, CH);
    }
    // 4-6. fused middle: conj(q)*k -> irfft2 -> softmax -> rfft2 -> Xc
    mid_fused_kernel<<<PLANES, 256>>>(Qc, Xc);
    // 7. y = irfft2(conj(A)*v) * t -> bf16 hi/lo (bh/bl)
    prod_ifft2_gate_bf16_kernel<<<PLANES, 256>>>(Xc, CH, 0,
                                                 Qc, CH3, 1024,
                                                 t, (__nv_bfloat162*)bh, (__nv_bfloat162*)bl,
                                                 inv64);
    // 8. proj: out = Wp*y + bp
    split_kernel<<<SPLIT_BLKS, 256>>>(w_proj, wh, wl, (CH*CH)/4);
    {
        dim3 g(NPIX / 128, CH / 128, BATCH);
        mma_gemm<3><<<g, 256>>>(wh, wl, bh, bl, b_proj, out, CH, NPIX, CH);
    }
}